// round 4
// baseline (speedup 1.0000x reference)
#include <cuda_runtime.h>
#include <math.h>

#define BT   8
#define TT   1024
#define DD   128
#define HH   8
#define DHH  16
#define FF   256
#define NTOK (BT*TT)   /* 8192 rows */

// ---------------- packed fp32x2 helpers (Blackwell FFMA2) -------------------
__device__ __forceinline__ unsigned long long pk2(float lo, float hi) {
    unsigned long long r;
    asm("mov.b64 %0, {%1, %2};" : "=l"(r) : "f"(lo), "f"(hi));
    return r;
}
__device__ __forceinline__ void upk2(unsigned long long p, float& lo, float& hi) {
    asm("mov.b64 {%0, %1}, %2;" : "=f"(lo), "=f"(hi) : "l"(p));
}
__device__ __forceinline__ void ffma2(unsigned long long& d,
                                      unsigned long long a, unsigned long long b) {
    asm("fma.rn.f32x2 %0, %1, %2, %3;" : "=l"(d) : "l"(a), "l"(b), "l"(d));
}

// ---------------- scratch (device globals; no allocation allowed) ----------
__device__ float g_xn[NTOK*DD];
__device__ float g_yn[NTOK*DD];
__device__ float g_qx[NTOK*DD];
__device__ float g_kx[NTOK*DD];
__device__ float g_vx[NTOK*DD];
__device__ float g_qy[NTOK*DD];
__device__ float g_ky[NTOK*DD];
__device__ float g_vy[NTOK*DD];
__device__ float g_o1[NTOK*DD];
__device__ float g_o2[NTOK*DD];
__device__ float g_hx[NTOK*FF];
__device__ float g_hy[NTOK*FF];

// ---------------- fused layernorm (both streams) ---------------------------
__global__ void ln_kernel(const float* __restrict__ xs, const float* __restrict__ ys,
                          float* __restrict__ xd, float* __restrict__ yd,
                          const float* __restrict__ gx, const float* __restrict__ bx,
                          const float* __restrict__ gy, const float* __restrict__ by)
{
    int row = blockIdx.x;
    bool second = row >= NTOK;
    int r = second ? row - NTOK : row;
    const float* src = second ? ys : xs;
    float*       dst = second ? yd : xd;
    const float* g   = second ? gy : gx;
    const float* b   = second ? by : bx;

    int t = threadIdx.x;
    float v = src[(size_t)r*DD + t];
    float s = v, s2 = v*v;
    #pragma unroll
    for (int o = 16; o; o >>= 1) {
        s  += __shfl_xor_sync(0xffffffffu, s , o);
        s2 += __shfl_xor_sync(0xffffffffu, s2, o);
    }
    __shared__ float ss[4], ss2[4];
    int w = t >> 5;
    if ((t & 31) == 0) { ss[w] = s; ss2[w] = s2; }
    __syncthreads();
    s  = ss[0]+ss[1]+ss[2]+ss[3];
    s2 = ss2[0]+ss2[1]+ss2[2]+ss2[3];
    float mean = s * (1.0f/DD);
    float var  = s2 * (1.0f/DD) - mean*mean;
    float inv  = rsqrtf(var + 1e-5f);
    dst[(size_t)r*DD + t] = (v - mean) * inv * g[t] + b[t];
}

// ---------------- batched SGEMM, FFMA2, 128x64 tile, 128 threads -----------
// mode 0: C = acc ; mode 1: C = res + acc + bias[n] ; mode 2: C = gelu(acc+bias)
#define GBM 128
#define GBN 64
#define GBK 16

struct GemmBatch {
    const float* A[6];
    const float* B[6];
    const float* bias[6];
    const float* res[6];
    float*       C[6];
};

__global__ void __launch_bounds__(128, 4)
gemm_kernel(GemmBatch g, int M, int N, int K, int mode)
{
    const int z = blockIdx.z;
    const float* __restrict__ A    = g.A[z];
    const float* __restrict__ B    = g.B[z];
    const float* __restrict__ bias = g.bias[z];
    const float* __restrict__ res  = g.res[z];
    float*       __restrict__ C    = g.C[z];

    __shared__ float As [GBK][GBM + 4];   // row stride 132 floats (528B, 16B-mult)
    __shared__ float Bsd[GBK][GBN * 2];   // duplicated pairs: [2j],[2j+1] = b[j]

    int bn = blockIdx.x * GBN;
    int bm = blockIdx.y * GBM;
    int tid = threadIdx.x;
    int tx = tid & 7;              // col group: n = tx + 8*j
    int ty = tid >> 3;             // row group: m = ty*8 + {0..7}

    unsigned long long acc[4][8];  // [row-pair][col j]
    #pragma unroll
    for (int ip = 0; ip < 4; ip++)
        #pragma unroll
        for (int j = 0; j < 8; j++) acc[ip][j] = 0ULL;

    for (int k0 = 0; k0 < K; k0 += GBK) {
        // A tile: 128 rows x 16 k, transposed store (4 float4/thread)
        #pragma unroll
        for (int e = tid; e < 512; e += 128) {
            int m  = e >> 2;
            int kk = (e & 3) * 4;
            float4 a = *(const float4*)&A[(size_t)(bm + m)*K + k0 + kk];
            As[kk+0][m] = a.x;
            As[kk+1][m] = a.y;
            As[kk+2][m] = a.z;
            As[kk+3][m] = a.w;
        }
        // B tile duplicated: 16 k x 64 n (2 float4/thread source)
        #pragma unroll
        for (int e = tid; e < 256; e += 128) {
            int kk = e >> 4;
            int j4 = (e & 15) * 4;
            float4 b = *(const float4*)&B[(size_t)(k0 + kk)*N + bn + j4];
            *(float4*)&Bsd[kk][j4*2    ] = make_float4(b.x, b.x, b.y, b.y);
            *(float4*)&Bsd[kk][j4*2 + 4] = make_float4(b.z, b.z, b.w, b.w);
        }
        __syncthreads();

        #pragma unroll
        for (int kk = 0; kk < GBK; kk++) {
            const unsigned long long* ap = (const unsigned long long*)&As[kk][ty*8];
            unsigned long long a_p[4];
            #pragma unroll
            for (int ip = 0; ip < 4; ip++) a_p[ip] = ap[ip];
            #pragma unroll
            for (int j = 0; j < 8; j++) {
                unsigned long long b_p =
                    *(const unsigned long long*)&Bsd[kk][(tx + 8*j)*2];
                #pragma unroll
                for (int ip = 0; ip < 4; ip++)
                    ffma2(acc[ip][j], a_p[ip], b_p);
            }
        }
        __syncthreads();
    }

    #pragma unroll
    for (int ip = 0; ip < 4; ip++) {
        int m0 = bm + ty*8 + ip*2;
        #pragma unroll
        for (int j = 0; j < 8; j++) {
            int n = bn + tx + 8*j;
            float v0, v1;
            upk2(acc[ip][j], v0, v1);
            if (mode == 1) {
                float bi = bias[n];
                v0 += bi + res[(size_t)m0*N + n];
                v1 += bi + res[(size_t)(m0+1)*N + n];
            } else if (mode == 2) {
                float bi = bias[n];
                v0 += bi; v1 += bi;
                v0 = 0.5f * v0 * (1.0f + erff(v0 * 0.70710678118654752f));
                v1 = 0.5f * v1 * (1.0f + erff(v1 * 0.70710678118654752f));
            }
            C[(size_t)m0*N + n]     = v0;
            C[(size_t)(m0+1)*N + n] = v1;
        }
    }
}

// ---------------- fused dual-branch flash attention (FFMA2, one-pass) ------
// Combined head: q=[qx,qy](32), k=[kx,ky](32), v=[vx,vy](32 -> o1|o2).
// 2 queries/thread (rows i, i+64) packed lane-wise into f32x2.
// K/V stored DUPLICATED in smem so LDS.64 yields broadcast pairs.
#define KVD 68   /* dup row stride in floats (272B, 16B multiple) */
__global__ void __launch_bounds__(64)
attn_kernel()
{
    __shared__ float Ksd[64][KVD];
    __shared__ float Vsd[64][KVD];

    int bh = blockIdx.x;
    int b  = bh >> 3;
    int h  = bh & 7;
    int i  = threadIdx.x;

    size_t qb0 = ((size_t)(b*TT) + blockIdx.y*128 + i)*DD + h*DHH;
    size_t qb1 = qb0 + (size_t)64*DD;

    unsigned long long q_p[32];
    {
        float q0[32], q1[32];
        const float4* p;
        p = (const float4*)(g_qx + qb0);
        #pragma unroll
        for (int d = 0; d < 4; d++) { float4 v = p[d]; q0[d*4+0]=v.x; q0[d*4+1]=v.y; q0[d*4+2]=v.z; q0[d*4+3]=v.w; }
        p = (const float4*)(g_qy + qb0);
        #pragma unroll
        for (int d = 0; d < 4; d++) { float4 v = p[d]; q0[16+d*4+0]=v.x; q0[16+d*4+1]=v.y; q0[16+d*4+2]=v.z; q0[16+d*4+3]=v.w; }
        p = (const float4*)(g_qx + qb1);
        #pragma unroll
        for (int d = 0; d < 4; d++) { float4 v = p[d]; q1[d*4+0]=v.x; q1[d*4+1]=v.y; q1[d*4+2]=v.z; q1[d*4+3]=v.w; }
        p = (const float4*)(g_qy + qb1);
        #pragma unroll
        for (int d = 0; d < 4; d++) { float4 v = p[d]; q1[16+d*4+0]=v.x; q1[16+d*4+1]=v.y; q1[16+d*4+2]=v.z; q1[16+d*4+3]=v.w; }
        #pragma unroll
        for (int d = 0; d < 32; d++) q_p[d] = pk2(q0[d], q1[d]);
    }

    float l0 = 0.f, l1 = 0.f;
    unsigned long long o_p[32];
    #pragma unroll
    for (int d = 0; d < 32; d++) o_p[d] = 0ULL;

    for (int kt = 0; kt < TT/64; kt++) {
        size_t kb = ((size_t)(b*TT) + kt*64 + i)*DD + h*DHH;
        {
            float4* dk = (float4*)&Ksd[i][0];
            float4* dv = (float4*)&Vsd[i][0];
            const float4* kx4 = (const float4*)(g_kx + kb);
            const float4* ky4 = (const float4*)(g_ky + kb);
            const float4* vx4 = (const float4*)(g_vx + kb);
            const float4* vy4 = (const float4*)(g_vy + kb);
            #pragma unroll
            for (int d = 0; d < 4; d++) {
                float4 v = kx4[d];
                dk[2*d]   = make_float4(v.x, v.x, v.y, v.y);
                dk[2*d+1] = make_float4(v.z, v.z, v.w, v.w);
                v = ky4[d];
                dk[8+2*d]   = make_float4(v.x, v.x, v.y, v.y);
                dk[8+2*d+1] = make_float4(v.z, v.z, v.w, v.w);
                v = vx4[d];
                dv[2*d]   = make_float4(v.x, v.x, v.y, v.y);
                dv[2*d+1] = make_float4(v.z, v.z, v.w, v.w);
                v = vy4[d];
                dv[8+2*d]   = make_float4(v.x, v.x, v.y, v.y);
                dv[8+2*d+1] = make_float4(v.z, v.z, v.w, v.w);
            }
        }
        __syncthreads();

        #pragma unroll 2
        for (int j = 0; j < 64; j++) {
            const unsigned long long* kr = (const unsigned long long*)&Ksd[j][0];
            unsigned long long s_p = 0ULL;
            #pragma unroll
            for (int d = 0; d < 32; d++) ffma2(s_p, q_p[d], kr[d]);
            float s0, s1;
            upk2(s_p, s0, s1);
            float p0 = __expf(s0 * 0.125f);
            float p1 = __expf(s1 * 0.125f);
            l0 += p0; l1 += p1;
            unsigned long long pp = pk2(p0, p1);
            const unsigned long long* vr = (const unsigned long long*)&Vsd[j][0];
            #pragma unroll
            for (int d = 0; d < 32; d++) ffma2(o_p[d], pp, vr[d]);
        }
        __syncthreads();
    }

    float inv0 = 1.f / l0;
    float inv1 = 1.f / l1;
    float o0[32], o1v[32];
    #pragma unroll
    for (int d = 0; d < 32; d++) {
        upk2(o_p[d], o0[d], o1v[d]);
        o0[d] *= inv0; o1v[d] *= inv1;
    }
    float4* p1x = (float4*)(g_o1 + qb0);
    float4* p2x = (float4*)(g_o2 + qb0);
    float4* p1y = (float4*)(g_o1 + qb1);
    float4* p2y = (float4*)(g_o2 + qb1);
    #pragma unroll
    for (int d = 0; d < 4; d++) {
        p1x[d] = make_float4(o0[d*4+0], o0[d*4+1], o0[d*4+2], o0[d*4+3]);
        p2x[d] = make_float4(o0[16+d*4+0], o0[16+d*4+1], o0[16+d*4+2], o0[16+d*4+3]);
        p1y[d] = make_float4(o1v[d*4+0], o1v[d*4+1], o1v[d*4+2], o1v[d*4+3]);
        p2y[d] = make_float4(o1v[16+d*4+0], o1v[16+d*4+1], o1v[16+d*4+2], o1v[16+d*4+3]);
    }
}

// ---------------- host launcher --------------------------------------------
template <typename Sym>
static float* symaddr(const Sym& s) {
    void* p = nullptr;
    cudaGetSymbolAddress(&p, s);
    return (float*)p;
}

extern "C" void kernel_launch(void* const* d_in, const int* in_sizes, int n_in,
                              void* d_out, int out_size)
{
    const float* x_in  = (const float*)d_in[0];
    const float* y_in  = (const float*)d_in[1];
    const float* Wq    = (const float*)d_in[2];
    const float* Wk    = (const float*)d_in[3];
    const float* Wv    = (const float*)d_in[4];
    const float* Wox   = (const float*)d_in[5];
    const float* box   = (const float*)d_in[6];
    const float* Woy   = (const float*)d_in[7];
    const float* boy   = (const float*)d_in[8];
    const float* l1xg  = (const float*)d_in[9];
    const float* l1xb  = (const float*)d_in[10];
    const float* l1yg  = (const float*)d_in[11];
    const float* l1yb  = (const float*)d_in[12];
    const float* l2xg  = (const float*)d_in[13];
    const float* l2xb  = (const float*)d_in[14];
    const float* l2yg  = (const float*)d_in[15];
    const float* l2yb  = (const float*)d_in[16];
    const float* fxw1  = (const float*)d_in[17];
    const float* fxb1  = (const float*)d_in[18];
    const float* fxw2  = (const float*)d_in[19];
    const float* fxb2  = (const float*)d_in[20];
    const float* fyw1  = (const float*)d_in[21];
    const float* fyb1  = (const float*)d_in[22];
    const float* fyw2  = (const float*)d_in[23];
    const float* fyb2  = (const float*)d_in[24];

    float* X = (float*)d_out;
    float* Y = X + (size_t)NTOK*DD;

    float* xn = symaddr(g_xn); float* yn = symaddr(g_yn);
    float* qx = symaddr(g_qx); float* kx = symaddr(g_kx); float* vx = symaddr(g_vx);
    float* qy = symaddr(g_qy); float* ky = symaddr(g_ky); float* vy = symaddr(g_vy);
    float* o1 = symaddr(g_o1); float* o2 = symaddr(g_o2);
    float* hx = symaddr(g_hx); float* hy = symaddr(g_hy);

    size_t bytes = (size_t)NTOK*DD*sizeof(float);
    cudaMemcpyAsync(X, x_in, bytes, cudaMemcpyDeviceToDevice);
    cudaMemcpyAsync(Y, y_in, bytes, cudaMemcpyDeviceToDevice);

    dim3 attnG(BT*HH, TT/128);

    for (int l = 0; l < 2; l++) {
        const float* Wq_l  = Wq  + (size_t)l*DD*DD;
        const float* Wk_l  = Wk  + (size_t)l*DD*DD;
        const float* Wv_l  = Wv  + (size_t)l*DD*DD;
        const float* Wox_l = Wox + (size_t)l*DD*DD;
        const float* Woy_l = Woy + (size_t)l*DD*DD;
        const float* box_l = box + (size_t)l*DD;
        const float* boy_l = boy + (size_t)l*DD;

        ln_kernel<<<2*NTOK, 128>>>(X, Y, xn, yn,
                                   l1xg + l*DD, l1xb + l*DD,
                                   l1yg + l*DD, l1yb + l*DD);

        {
            GemmBatch gb = {};
            gb.A[0]=xn; gb.B[0]=Wq_l; gb.C[0]=qy;
            gb.A[1]=xn; gb.B[1]=Wk_l; gb.C[1]=kx;
            gb.A[2]=xn; gb.B[2]=Wv_l; gb.C[2]=vx;
            gb.A[3]=yn; gb.B[3]=Wq_l; gb.C[3]=qx;
            gb.A[4]=yn; gb.B[4]=Wk_l; gb.C[4]=ky;
            gb.A[5]=yn; gb.B[5]=Wv_l; gb.C[5]=vy;
            dim3 grid(DD/GBN, NTOK/GBM, 6);
            gemm_kernel<<<grid, 128>>>(gb, NTOK, DD, DD, 0);
        }

        attn_kernel<<<attnG, 64>>>();

        {
            GemmBatch gb = {};
            gb.A[0]=o1; gb.B[0]=Wox_l; gb.bias[0]=box_l; gb.res[0]=X; gb.C[0]=X;
            gb.A[1]=o2; gb.B[1]=Woy_l; gb.bias[1]=boy_l; gb.res[1]=Y; gb.C[1]=Y;
            dim3 grid(DD/GBN, NTOK/GBM, 2);
            gemm_kernel<<<grid, 128>>>(gb, NTOK, DD, DD, 1);
        }

        ln_kernel<<<2*NTOK, 128>>>(X, Y, xn, yn,
                                   l2xg + l*DD, l2xb + l*DD,
                                   l2yg + l*DD, l2yb + l*DD);

        {
            GemmBatch gb = {};
            gb.A[0]=xn; gb.B[0]=fxw1 + (size_t)l*DD*FF; gb.bias[0]=fxb1 + l*FF; gb.C[0]=hx;
            gb.A[1]=yn; gb.B[1]=fyw1 + (size_t)l*DD*FF; gb.bias[1]=fyb1 + l*FF; gb.C[1]=hy;
            dim3 grid(FF/GBN, NTOK/GBM, 2);
            gemm_kernel<<<grid, 128>>>(gb, NTOK, FF, DD, 2);
        }
        {
            GemmBatch gb = {};
            gb.A[0]=hx; gb.B[0]=fxw2 + (size_t)l*FF*DD; gb.bias[0]=fxb2 + l*DD; gb.res[0]=X; gb.C[0]=X;
            gb.A[1]=hy; gb.B[1]=fyw2 + (size_t)l*FF*DD; gb.bias[1]=fyb2 + l*DD; gb.res[1]=Y; gb.C[1]=Y;
            dim3 grid(DD/GBN, NTOK/GBM, 2);
            gemm_kernel<<<grid, 128>>>(gb, NTOK, DD, FF, 1);
        }
    }
}

// round 5
// speedup vs baseline: 1.0204x; 1.0204x over previous
#include <cuda_runtime.h>
#include <math.h>

#define BT   8
#define TT   1024
#define DD   128
#define HH   8
#define DHH  16
#define FF   256
#define NTOK (BT*TT)   /* 8192 rows */

typedef unsigned long long u64;

// ---------------- packed fp32x2 helpers (Blackwell FFMA2) -------------------
__device__ __forceinline__ u64 pk2(float lo, float hi) {
    u64 r;
    asm("mov.b64 %0, {%1, %2};" : "=l"(r) : "f"(lo), "f"(hi));
    return r;
}
__device__ __forceinline__ void upk2(u64 p, float& lo, float& hi) {
    asm("mov.b64 {%0, %1}, %2;" : "=f"(lo), "=f"(hi) : "l"(p));
}
__device__ __forceinline__ void ffma2(u64& d, u64 a, u64 b) {
    asm("fma.rn.f32x2 %0, %1, %2, %3;" : "=l"(d) : "l"(a), "l"(b), "l"(d));
}

// ---------------- scratch (device globals; no allocation allowed) ----------
__device__ float g_xn[NTOK*DD];
__device__ float g_yn[NTOK*DD];
__device__ float g_qx[NTOK*DD];
__device__ float g_kx[NTOK*DD];
__device__ float g_vx[NTOK*DD];
__device__ float g_qy[NTOK*DD];
__device__ float g_ky[NTOK*DD];
__device__ float g_vy[NTOK*DD];
__device__ float g_o1[NTOK*DD];
__device__ float g_o2[NTOK*DD];
__device__ float g_hx[NTOK*FF];
__device__ float g_hy[NTOK*FF];

// ---------------- fused layernorm (both streams) ---------------------------
__global__ void ln_kernel(const float* __restrict__ xs, const float* __restrict__ ys,
                          float* __restrict__ xd, float* __restrict__ yd,
                          const float* __restrict__ gx, const float* __restrict__ bx,
                          const float* __restrict__ gy, const float* __restrict__ by)
{
    int row = blockIdx.x;
    bool second = row >= NTOK;
    int r = second ? row - NTOK : row;
    const float* src = second ? ys : xs;
    float*       dst = second ? yd : xd;
    const float* g   = second ? gy : gx;
    const float* b   = second ? by : bx;

    int t = threadIdx.x;
    float v = src[(size_t)r*DD + t];
    float s = v, s2 = v*v;
    #pragma unroll
    for (int o = 16; o; o >>= 1) {
        s  += __shfl_xor_sync(0xffffffffu, s , o);
        s2 += __shfl_xor_sync(0xffffffffu, s2, o);
    }
    __shared__ float ss[4], ss2[4];
    int w = t >> 5;
    if ((t & 31) == 0) { ss[w] = s; ss2[w] = s2; }
    __syncthreads();
    s  = ss[0]+ss[1]+ss[2]+ss[3];
    s2 = ss2[0]+ss2[1]+ss2[2]+ss2[3];
    float mean = s * (1.0f/DD);
    float var  = s2 * (1.0f/DD) - mean*mean;
    float inv  = rsqrtf(var + 1e-5f);
    dst[(size_t)r*DD + t] = (v - mean) * inv * g[t] + b[t];
}

// ---------------- batched SGEMM (FFMA2, 64x128 tile, 256 threads) ----------
// thread tile: 4 m-rows x 8 n-cols (4 n-pairs, pairs strided by 32 cols)
// B tile stored DUPLICATED in smem: one LDS.128 -> two broadcast pairs.
// mode 0: C = acc ; mode 1: C = res + acc + bias[n] ; mode 2: C = gelu(acc+bias)
#define GBM 64
#define GBN 128
#define GBK 16
#define BSD (2*GBN + 8)   /* dup'd row stride in floats */

struct GemmBatch {
    const float* A[6];
    const float* B[6];
    const float* bias[6];
    const float* res[6];
    float*       C[6];
};

__global__ void __launch_bounds__(256)
gemm_kernel(GemmBatch g, int M, int N, int K, int mode)
{
    const int z = blockIdx.z;
    const float* __restrict__ A    = g.A[z];
    const float* __restrict__ B    = g.B[z];
    const float* __restrict__ bias = g.bias[z];
    const float* __restrict__ res  = g.res[z];
    float*       __restrict__ C    = g.C[z];

    __shared__ float As [GBK][GBM + 4];
    __shared__ float Bsd[GBK][BSD];

    int bn = blockIdx.x * GBN;
    int bm = blockIdx.y * GBM;
    int tid = threadIdx.x;
    int tx = tid & 15;             // n-pair lane: pairs {tx, tx+16, tx+32, tx+48}
    int ty = tid >> 4;             // m-group: rows ty*4 .. ty*4+3

    u64 acc[4][4];                 // [m-row][n-pair c]
    #pragma unroll
    for (int i = 0; i < 4; i++)
        #pragma unroll
        for (int c = 0; c < 4; c++) acc[i][c] = 0ULL;

    for (int k0 = 0; k0 < K; k0 += GBK) {
        // A tile: 64 rows x 16 k -> transposed (1 float4 per thread)
        {
            int m  = tid >> 2;
            int kk = (tid & 3) * 4;
            float4 a = *(const float4*)&A[(size_t)(bm + m)*K + k0 + kk];
            As[kk+0][m] = a.x;
            As[kk+1][m] = a.y;
            As[kk+2][m] = a.z;
            As[kk+3][m] = a.w;
        }
        // B tile duplicated: 16 k x 128 n (2 src float4 per thread)
        #pragma unroll
        for (int e = tid; e < 512; e += 256) {
            int kk = e >> 5;
            int n4 = (e & 31) * 4;
            float4 b = *(const float4*)&B[(size_t)(k0 + kk)*N + bn + n4];
            *(float4*)&Bsd[kk][n4*2    ] = make_float4(b.x, b.x, b.y, b.y);
            *(float4*)&Bsd[kk][n4*2 + 4] = make_float4(b.z, b.z, b.w, b.w);
        }
        __syncthreads();

        #pragma unroll
        for (int kk = 0; kk < GBK; kk++) {
            // A: one LDS.128 broadcast (all lanes in half-warp same ty)
            float4 a4 = *(const float4*)&As[kk][ty*4];
            float av[4] = {a4.x, a4.y, a4.z, a4.w};
            #pragma unroll
            for (int c = 0; c < 4; c++) {
                // dup'd pair (tx+16c): floats [4*(tx+16c) .. +3] -> LDS.128
                float4 b4 = *(const float4*)&Bsd[kk][(tx + 16*c)*4];
                u64 bp = pk2(b4.x, b4.z);   // (b_n, b_n+1) from dup'd layout
                #pragma unroll
                for (int i = 0; i < 4; i++) {
                    u64 ap = pk2(av[i], av[i]);
                    ffma2(acc[i][c], ap, bp);
                }
            }
        }
        __syncthreads();
    }

    #pragma unroll
    for (int i = 0; i < 4; i++) {
        int m = bm + ty*4 + i;
        #pragma unroll
        for (int c = 0; c < 4; c++) {
            int n0 = bn + (tx + 16*c)*2;
            float v0, v1;
            upk2(acc[i][c], v0, v1);
            if (mode == 1) {
                v0 += bias[n0]   + res[(size_t)m*N + n0];
                v1 += bias[n0+1] + res[(size_t)m*N + n0+1];
            } else if (mode == 2) {
                v0 += bias[n0];
                v1 += bias[n0+1];
                v0 = 0.5f * v0 * (1.0f + erff(v0 * 0.70710678118654752f));
                v1 = 0.5f * v1 * (1.0f + erff(v1 * 0.70710678118654752f));
            }
            *(float2*)&C[(size_t)m*N + n0] = make_float2(v0, v1);
        }
    }
}

// ---------------- fused dual-branch flash attention (FFMA2, one-pass) ------
// K/V in NATURAL float4 layout (same smem traffic as scalar version).
// Scores: packed over the 32-dim reduction axis (horizontal add at end).
// AV:     packed over the v-dim output axis (p duplicated per key).
// 2 queries/thread (rows i, i+64). grid = (B*H, T/128), block = 64 threads.
#define KVPAD 36
__global__ void __launch_bounds__(64)
attn_kernel()
{
    __shared__ float Ks[64][KVPAD];
    __shared__ float Vs[64][KVPAD];

    int bh = blockIdx.x;
    int b  = bh >> 3;
    int h  = bh & 7;
    int i  = threadIdx.x;

    size_t qb0 = ((size_t)(b*TT) + blockIdx.y*128 + i)*DD + h*DHH;
    size_t qb1 = qb0 + (size_t)64*DD;

    u64 qp0[16], qp1[16];
    {
        const float4* p;
        p = (const float4*)(g_qx + qb0);
        #pragma unroll
        for (int d = 0; d < 4; d++) { float4 v = p[d]; qp0[2*d] = pk2(v.x,v.y); qp0[2*d+1] = pk2(v.z,v.w); }
        p = (const float4*)(g_qy + qb0);
        #pragma unroll
        for (int d = 0; d < 4; d++) { float4 v = p[d]; qp0[8+2*d] = pk2(v.x,v.y); qp0[8+2*d+1] = pk2(v.z,v.w); }
        p = (const float4*)(g_qx + qb1);
        #pragma unroll
        for (int d = 0; d < 4; d++) { float4 v = p[d]; qp1[2*d] = pk2(v.x,v.y); qp1[2*d+1] = pk2(v.z,v.w); }
        p = (const float4*)(g_qy + qb1);
        #pragma unroll
        for (int d = 0; d < 4; d++) { float4 v = p[d]; qp1[8+2*d] = pk2(v.x,v.y); qp1[8+2*d+1] = pk2(v.z,v.w); }
    }

    float l0 = 0.f, l1 = 0.f;
    u64 op0[16], op1[16];
    #pragma unroll
    for (int d = 0; d < 16; d++) { op0[d] = 0ULL; op1[d] = 0ULL; }

    for (int kt = 0; kt < TT/64; kt++) {
        size_t kb = ((size_t)(b*TT) + kt*64 + i)*DD + h*DHH;
        {
            float4* dk = (float4*)&Ks[i][0];
            float4* dv = (float4*)&Vs[i][0];
            const float4* kx4 = (const float4*)(g_kx + kb);
            const float4* ky4 = (const float4*)(g_ky + kb);
            const float4* vx4 = (const float4*)(g_vx + kb);
            const float4* vy4 = (const float4*)(g_vy + kb);
            #pragma unroll
            for (int d = 0; d < 4; d++) { dk[d] = kx4[d]; dk[4+d] = ky4[d]; }
            #pragma unroll
            for (int d = 0; d < 4; d++) { dv[d] = vx4[d]; dv[4+d] = vy4[d]; }
        }
        __syncthreads();

        #pragma unroll 2
        for (int j = 0; j < 64; j++) {
            const float4* kr = (const float4*)&Ks[j][0];
            // packed score partials: (even dims, odd dims); 2 split chains/query
            u64 s0a = 0ULL, s0b = 0ULL, s1a = 0ULL, s1b = 0ULL;
            #pragma unroll
            for (int d4 = 0; d4 < 8; d4++) {
                float4 kk = kr[d4];
                u64 kpa = pk2(kk.x, kk.y);
                u64 kpb = pk2(kk.z, kk.w);
                ffma2(s0a, qp0[2*d4],   kpa);
                ffma2(s0b, qp0[2*d4+1], kpb);
                ffma2(s1a, qp1[2*d4],   kpa);
                ffma2(s1b, qp1[2*d4+1], kpb);
            }
            float alo, ahi, blo, bhi;
            upk2(s0a, alo, ahi); upk2(s0b, blo, bhi);
            float s0 = (alo + ahi) + (blo + bhi);
            upk2(s1a, alo, ahi); upk2(s1b, blo, bhi);
            float s1 = (alo + ahi) + (blo + bhi);

            float p0 = __expf(s0 * 0.125f);
            float p1 = __expf(s1 * 0.125f);
            l0 += p0; l1 += p1;
            u64 pp0 = pk2(p0, p0);
            u64 pp1 = pk2(p1, p1);

            const float4* vr = (const float4*)&Vs[j][0];
            #pragma unroll
            for (int d4 = 0; d4 < 8; d4++) {
                float4 vv = vr[d4];
                u64 vpa = pk2(vv.x, vv.y);
                u64 vpb = pk2(vv.z, vv.w);
                ffma2(op0[2*d4],   pp0, vpa);
                ffma2(op0[2*d4+1], pp0, vpb);
                ffma2(op1[2*d4],   pp1, vpa);
                ffma2(op1[2*d4+1], pp1, vpb);
            }
        }
        __syncthreads();
    }

    float inv0 = 1.f / l0;
    float inv1 = 1.f / l1;
    float o0[32], o1v[32];
    #pragma unroll
    for (int d = 0; d < 16; d++) {
        upk2(op0[d], o0[2*d], o0[2*d+1]);
        upk2(op1[d], o1v[2*d], o1v[2*d+1]);
        o0[2*d] *= inv0; o0[2*d+1] *= inv0;
        o1v[2*d] *= inv1; o1v[2*d+1] *= inv1;
    }
    float4* p1x = (float4*)(g_o1 + qb0);
    float4* p2x = (float4*)(g_o2 + qb0);
    float4* p1y = (float4*)(g_o1 + qb1);
    float4* p2y = (float4*)(g_o2 + qb1);
    #pragma unroll
    for (int d = 0; d < 4; d++) {
        p1x[d] = make_float4(o0[d*4+0], o0[d*4+1], o0[d*4+2], o0[d*4+3]);
        p2x[d] = make_float4(o0[16+d*4+0], o0[16+d*4+1], o0[16+d*4+2], o0[16+d*4+3]);
        p1y[d] = make_float4(o1v[d*4+0], o1v[d*4+1], o1v[d*4+2], o1v[d*4+3]);
        p2y[d] = make_float4(o1v[16+d*4+0], o1v[16+d*4+1], o1v[16+d*4+2], o1v[16+d*4+3]);
    }
}

// ---------------- host launcher --------------------------------------------
template <typename Sym>
static float* symaddr(const Sym& s) {
    void* p = nullptr;
    cudaGetSymbolAddress(&p, s);
    return (float*)p;
}

extern "C" void kernel_launch(void* const* d_in, const int* in_sizes, int n_in,
                              void* d_out, int out_size)
{
    const float* x_in  = (const float*)d_in[0];
    const float* y_in  = (const float*)d_in[1];
    const float* Wq    = (const float*)d_in[2];
    const float* Wk    = (const float*)d_in[3];
    const float* Wv    = (const float*)d_in[4];
    const float* Wox   = (const float*)d_in[5];
    const float* box   = (const float*)d_in[6];
    const float* Woy   = (const float*)d_in[7];
    const float* boy   = (const float*)d_in[8];
    const float* l1xg  = (const float*)d_in[9];
    const float* l1xb  = (const float*)d_in[10];
    const float* l1yg  = (const float*)d_in[11];
    const float* l1yb  = (const float*)d_in[12];
    const float* l2xg  = (const float*)d_in[13];
    const float* l2xb  = (const float*)d_in[14];
    const float* l2yg  = (const float*)d_in[15];
    const float* l2yb  = (const float*)d_in[16];
    const float* fxw1  = (const float*)d_in[17];
    const float* fxb1  = (const float*)d_in[18];
    const float* fxw2  = (const float*)d_in[19];
    const float* fxb2  = (const float*)d_in[20];
    const float* fyw1  = (const float*)d_in[21];
    const float* fyb1  = (const float*)d_in[22];
    const float* fyw2  = (const float*)d_in[23];
    const float* fyb2  = (const float*)d_in[24];

    float* X = (float*)d_out;
    float* Y = X + (size_t)NTOK*DD;

    float* xn = symaddr(g_xn); float* yn = symaddr(g_yn);
    float* qx = symaddr(g_qx); float* kx = symaddr(g_kx); float* vx = symaddr(g_vx);
    float* qy = symaddr(g_qy); float* ky = symaddr(g_ky); float* vy = symaddr(g_vy);
    float* o1 = symaddr(g_o1); float* o2 = symaddr(g_o2);
    float* hx = symaddr(g_hx); float* hy = symaddr(g_hy);

    size_t bytes = (size_t)NTOK*DD*sizeof(float);
    cudaMemcpyAsync(X, x_in, bytes, cudaMemcpyDeviceToDevice);
    cudaMemcpyAsync(Y, y_in, bytes, cudaMemcpyDeviceToDevice);

    dim3 attnG(BT*HH, TT/128);

    for (int l = 0; l < 2; l++) {
        const float* Wq_l  = Wq  + (size_t)l*DD*DD;
        const float* Wk_l  = Wk  + (size_t)l*DD*DD;
        const float* Wv_l  = Wv  + (size_t)l*DD*DD;
        const float* Wox_l = Wox + (size_t)l*DD*DD;
        const float* Woy_l = Woy + (size_t)l*DD*DD;
        const float* box_l = box + (size_t)l*DD;
        const float* boy_l = boy + (size_t)l*DD;

        ln_kernel<<<2*NTOK, 128>>>(X, Y, xn, yn,
                                   l1xg + l*DD, l1xb + l*DD,
                                   l1yg + l*DD, l1yb + l*DD);

        {
            GemmBatch gb = {};
            gb.A[0]=xn; gb.B[0]=Wq_l; gb.C[0]=qy;
            gb.A[1]=xn; gb.B[1]=Wk_l; gb.C[1]=kx;
            gb.A[2]=xn; gb.B[2]=Wv_l; gb.C[2]=vx;
            gb.A[3]=yn; gb.B[3]=Wq_l; gb.C[3]=qx;
            gb.A[4]=yn; gb.B[4]=Wk_l; gb.C[4]=ky;
            gb.A[5]=yn; gb.B[5]=Wv_l; gb.C[5]=vy;
            dim3 grid(DD/GBN, NTOK/GBM, 6);   // (1, 128, 6) = 768 blocks
            gemm_kernel<<<grid, 256>>>(gb, NTOK, DD, DD, 0);
        }

        attn_kernel<<<attnG, 64>>>();

        {
            GemmBatch gb = {};
            gb.A[0]=o1; gb.B[0]=Wox_l; gb.bias[0]=box_l; gb.res[0]=X; gb.C[0]=X;
            gb.A[1]=o2; gb.B[1]=Woy_l; gb.bias[1]=boy_l; gb.res[1]=Y; gb.C[1]=Y;
            dim3 grid(DD/GBN, NTOK/GBM, 2);   // 256 blocks
            gemm_kernel<<<grid, 256>>>(gb, NTOK, DD, DD, 1);
        }

        ln_kernel<<<2*NTOK, 128>>>(X, Y, xn, yn,
                                   l2xg + l*DD, l2xb + l*DD,
                                   l2yg + l*DD, l2yb + l*DD);

        {
            GemmBatch gb = {};
            gb.A[0]=xn; gb.B[0]=fxw1 + (size_t)l*DD*FF; gb.bias[0]=fxb1 + l*FF; gb.C[0]=hx;
            gb.A[1]=yn; gb.B[1]=fyw1 + (size_t)l*DD*FF; gb.bias[1]=fyb1 + l*FF; gb.C[1]=hy;
            dim3 grid(FF/GBN, NTOK/GBM, 2);   // (2, 128, 2) = 512 blocks
            gemm_kernel<<<grid, 256>>>(gb, NTOK, FF, DD, 2);
        }
        {
            GemmBatch gb = {};
            gb.A[0]=hx; gb.B[0]=fxw2 + (size_t)l*FF*DD; gb.bias[0]=fxb2 + l*DD; gb.res[0]=X; gb.C[0]=X;
            gb.A[1]=hy; gb.B[1]=fyw2 + (size_t)l*FF*DD; gb.bias[1]=fyb2 + l*DD; gb.res[1]=Y; gb.C[1]=Y;
            dim3 grid(DD/GBN, NTOK/GBM, 2);   // 256 blocks
            gemm_kernel<<<grid, 256>>>(gb, NTOK, DD, FF, 1);
        }
    }
}

// round 6
// speedup vs baseline: 1.6033x; 1.5712x over previous
#include <cuda_runtime.h>
#include <math.h>

#define BT   8
#define TT   1024
#define DD   128
#define HH   8
#define DHH  16
#define FF   256
#define NTOK (BT*TT)   /* 8192 rows */

// ---------------- scratch (device globals; no allocation allowed) ----------
__device__ float g_xn[NTOK*DD];
__device__ float g_yn[NTOK*DD];
__device__ float g_qx[NTOK*DD];
__device__ float g_kx[NTOK*DD];
__device__ float g_vx[NTOK*DD];
__device__ float g_qy[NTOK*DD];
__device__ float g_ky[NTOK*DD];
__device__ float g_vy[NTOK*DD];
__device__ float g_o1[NTOK*DD];
__device__ float g_o2[NTOK*DD];
__device__ float g_hx[NTOK*FF];
__device__ float g_hy[NTOK*FF];

// ---------------- tf32 mma helpers -----------------------------------------
__device__ __forceinline__ unsigned cvt_tf32(float f) {
    unsigned u;
    asm("cvt.rna.tf32.f32 %0, %1;" : "=r"(u) : "f"(f));
    return u;
}
__device__ __forceinline__ void mma_tf32(float* c,
    unsigned a0, unsigned a1, unsigned a2, unsigned a3,
    unsigned b0, unsigned b1)
{
    asm("mma.sync.aligned.m16n8k8.row.col.f32.tf32.tf32.f32 "
        "{%0,%1,%2,%3}, {%4,%5,%6,%7}, {%8,%9}, {%0,%1,%2,%3};"
        : "+f"(c[0]), "+f"(c[1]), "+f"(c[2]), "+f"(c[3])
        : "r"(a0), "r"(a1), "r"(a2), "r"(a3), "r"(b0), "r"(b1));
}

// ---------------- fused layernorm (both streams) ---------------------------
__global__ void ln_kernel(const float* __restrict__ xs, const float* __restrict__ ys,
                          float* __restrict__ xd, float* __restrict__ yd,
                          const float* __restrict__ gx, const float* __restrict__ bx,
                          const float* __restrict__ gy, const float* __restrict__ by)
{
    int row = blockIdx.x;
    bool second = row >= NTOK;
    int r = second ? row - NTOK : row;
    const float* src = second ? ys : xs;
    float*       dst = second ? yd : xd;
    const float* g   = second ? gy : gx;
    const float* b   = second ? by : bx;

    int t = threadIdx.x;
    float v = src[(size_t)r*DD + t];
    float s = v, s2 = v*v;
    #pragma unroll
    for (int o = 16; o; o >>= 1) {
        s  += __shfl_xor_sync(0xffffffffu, s , o);
        s2 += __shfl_xor_sync(0xffffffffu, s2, o);
    }
    __shared__ float ss[4], ss2[4];
    int w = t >> 5;
    if ((t & 31) == 0) { ss[w] = s; ss2[w] = s2; }
    __syncthreads();
    s  = ss[0]+ss[1]+ss[2]+ss[3];
    s2 = ss2[0]+ss2[1]+ss2[2]+ss2[3];
    float mean = s * (1.0f/DD);
    float var  = s2 * (1.0f/DD) - mean*mean;
    float inv  = rsqrtf(var + 1e-5f);
    dst[(size_t)r*DD + t] = (v - mean) * inv * g[t] + b[t];
}

// ---------------- batched tiled SGEMM (R3-proven: 128x128, 8x8/thread) -----
#define GBM 128
#define GBN 128
#define GBK 16

struct GemmBatch {
    const float* A[6];
    const float* B[6];
    const float* bias[6];
    const float* res[6];
    float*       C[6];
};

__global__ void __launch_bounds__(256, 2)
gemm_kernel(GemmBatch g, int M, int N, int K, int mode)
{
    const int z = blockIdx.z;
    const float* __restrict__ A    = g.A[z];
    const float* __restrict__ B    = g.B[z];
    const float* __restrict__ bias = g.bias[z];
    const float* __restrict__ res  = g.res[z];
    float*       __restrict__ C    = g.C[z];

    __shared__ float As[GBK][GBM + 4];
    __shared__ float Bs[GBK][GBN];

    int bn = blockIdx.x * GBN;
    int bm = blockIdx.y * GBM;
    int tid = threadIdx.x;
    int tx = tid & 15;
    int ty = tid >> 4;

    float acc[8][8];
    #pragma unroll
    for (int i = 0; i < 8; i++)
        #pragma unroll
        for (int j = 0; j < 8; j++) acc[i][j] = 0.f;

    for (int k0 = 0; k0 < K; k0 += GBK) {
        #pragma unroll
        for (int e = tid; e < 512; e += 256) {
            int m  = e >> 2;
            int kk = (e & 3) * 4;
            float4 a = *(const float4*)&A[(size_t)(bm + m)*K + k0 + kk];
            As[kk+0][m] = a.x;
            As[kk+1][m] = a.y;
            As[kk+2][m] = a.z;
            As[kk+3][m] = a.w;
        }
        #pragma unroll
        for (int e = tid; e < 512; e += 256) {
            int kk = e >> 5;
            int n  = (e & 31) * 4;
            *(float4*)&Bs[kk][n] = *(const float4*)&B[(size_t)(k0 + kk)*N + bn + n];
        }
        __syncthreads();

        #pragma unroll
        for (int kk = 0; kk < GBK; kk++) {
            float4 a0 = *(const float4*)&As[kk][ty*8];
            float4 a1 = *(const float4*)&As[kk][ty*8 + 4];
            float4 b0 = *(const float4*)&Bs[kk][tx*8];
            float4 b1 = *(const float4*)&Bs[kk][tx*8 + 4];
            float av[8] = {a0.x,a0.y,a0.z,a0.w,a1.x,a1.y,a1.z,a1.w};
            float bv[8] = {b0.x,b0.y,b0.z,b0.w,b1.x,b1.y,b1.z,b1.w};
            #pragma unroll
            for (int i = 0; i < 8; i++)
                #pragma unroll
                for (int j = 0; j < 8; j++)
                    acc[i][j] = fmaf(av[i], bv[j], acc[i][j]);
        }
        __syncthreads();
    }

    #pragma unroll
    for (int i = 0; i < 8; i++) {
        int m = bm + ty*8 + i;
        #pragma unroll
        for (int j = 0; j < 8; j++) {
            int n = bn + tx*8 + j;
            float v = acc[i][j];
            if (mode == 1) {
                v += bias[n];
                v += res[(size_t)m*N + n];
            } else if (mode == 2) {
                v += bias[n];
                v = 0.5f * v * (1.0f + erff(v * 0.70710678118654752f));
            }
            C[(size_t)m*N + n] = v;
        }
    }
}

// ---------------- tensor-core dual-branch flash attention (tf32) -----------
// Combined head: q=[qx,qy](32 dims), k=[kx,ky](32), v=[vx,vy](32 -> o1|o2).
// One-pass softmax (0.125 scale folded into Q). 4 warps/block, 16 q/warp,
// key tiles of 64. S and O via mma.m16n8k8 tf32, fp32 accumulate.
#define KPAD 36   /* K/V row stride (floats); b-frag reads conflict-free */
#define PPAD 67   /* P staging row stride */
__global__ void __launch_bounds__(128)
attn_kernel()
{
    __shared__ unsigned Ks[64][KPAD];   // tf32 bit patterns
    __shared__ unsigned Vs[64][KPAD];
    __shared__ unsigned Ps[4][16][PPAD];

    int bh = blockIdx.x;
    int b  = bh >> 3;
    int h  = bh & 7;
    int tid  = threadIdx.x;
    int w    = tid >> 5;
    int lane = tid & 31;
    int gq   = lane >> 2;   // group id 0..7
    int qq   = lane & 3;    // thread-in-group

    int tok0 = b*TT + blockIdx.y*64 + w*16;
    int r0 = tok0 + gq;
    int r1 = r0 + 8;

    // ---- Q fragments (x0.125, tf32), combined dim = [qx(16) | qy(16)] ----
    unsigned qa[4][4];
    #pragma unroll
    for (int kc = 0; kc < 4; kc++) {
        const float* src = (kc < 2) ? g_qx : g_qy;
        int d0 = (kc & 1)*8 + qq;
        qa[kc][0] = cvt_tf32(0.125f * src[(size_t)r0*DD + h*DHH + d0]);
        qa[kc][1] = cvt_tf32(0.125f * src[(size_t)r1*DD + h*DHH + d0]);
        qa[kc][2] = cvt_tf32(0.125f * src[(size_t)r0*DD + h*DHH + d0 + 4]);
        qa[kc][3] = cvt_tf32(0.125f * src[(size_t)r1*DD + h*DHH + d0 + 4]);
    }

    float o[4][4];
    #pragma unroll
    for (int j = 0; j < 4; j++)
        #pragma unroll
        for (int c = 0; c < 4; c++) o[j][c] = 0.f;
    float l0 = 0.f, l1 = 0.f;

    for (int kt = 0; kt < TT/64; kt++) {
        // ---- cooperative K/V tile load (tf32-converted at store) ----
        #pragma unroll
        for (int it = 0; it < 4; it++) {
            int e   = tid + it*128;
            int row = e >> 3;
            int c4  = (e & 7) * 4;
            int tokk = b*TT + kt*64 + row;
            int dd = c4 & 15;
            const float* ksrc = (c4 < 16) ? g_kx : g_ky;
            const float* vsrc = (c4 < 16) ? g_vx : g_vy;
            float4 kv = *(const float4*)&ksrc[(size_t)tokk*DD + h*DHH + dd];
            float4 vv = *(const float4*)&vsrc[(size_t)tokk*DD + h*DHH + dd];
            Ks[row][c4+0] = cvt_tf32(kv.x);
            Ks[row][c4+1] = cvt_tf32(kv.y);
            Ks[row][c4+2] = cvt_tf32(kv.z);
            Ks[row][c4+3] = cvt_tf32(kv.w);
            Vs[row][c4+0] = cvt_tf32(vv.x);
            Vs[row][c4+1] = cvt_tf32(vv.y);
            Vs[row][c4+2] = cvt_tf32(vv.z);
            Vs[row][c4+3] = cvt_tf32(vv.w);
        }
        __syncthreads();

        // ---- S = (Q*0.125) @ K^T : 8 n-chunks of 8 keys ----
        float sc[8][4];
        #pragma unroll
        for (int j = 0; j < 8; j++) {
            sc[j][0] = sc[j][1] = sc[j][2] = sc[j][3] = 0.f;
            #pragma unroll
            for (int kc = 0; kc < 4; kc++) {
                unsigned b0 = Ks[j*8 + gq][kc*8 + qq];
                unsigned b1 = Ks[j*8 + gq][kc*8 + qq + 4];
                mma_tf32(sc[j], qa[kc][0], qa[kc][1], qa[kc][2], qa[kc][3], b0, b1);
            }
        }

        // ---- exp + row sums + stage P (tf32) ----
        float rs0 = 0.f, rs1 = 0.f;
        #pragma unroll
        for (int j = 0; j < 8; j++) {
            float p0 = __expf(sc[j][0]);
            float p1 = __expf(sc[j][1]);
            float p2 = __expf(sc[j][2]);
            float p3 = __expf(sc[j][3]);
            rs0 += p0 + p1;
            rs1 += p2 + p3;
            Ps[w][gq  ][8*j + 2*qq    ] = cvt_tf32(p0);
            Ps[w][gq  ][8*j + 2*qq + 1] = cvt_tf32(p1);
            Ps[w][gq+8][8*j + 2*qq    ] = cvt_tf32(p2);
            Ps[w][gq+8][8*j + 2*qq + 1] = cvt_tf32(p3);
        }
        rs0 += __shfl_xor_sync(0xffffffffu, rs0, 1);
        rs0 += __shfl_xor_sync(0xffffffffu, rs0, 2);
        rs1 += __shfl_xor_sync(0xffffffffu, rs1, 1);
        rs1 += __shfl_xor_sync(0xffffffffu, rs1, 2);
        l0 += rs0;
        l1 += rs1;
        __syncwarp();

        // ---- O += P @ V : 8 k-chunks (keys) x 4 n-chunks (v dims) ----
        #pragma unroll
        for (int kc2 = 0; kc2 < 8; kc2++) {
            unsigned a0 = Ps[w][gq  ][8*kc2 + qq];
            unsigned a1 = Ps[w][gq+8][8*kc2 + qq];
            unsigned a2 = Ps[w][gq  ][8*kc2 + qq + 4];
            unsigned a3 = Ps[w][gq+8][8*kc2 + qq + 4];
            #pragma unroll
            for (int j = 0; j < 4; j++) {
                unsigned b0 = Vs[8*kc2 + qq    ][8*j + gq];
                unsigned b1 = Vs[8*kc2 + qq + 4][8*j + gq];
                mma_tf32(o[j], a0, a1, a2, a3, b0, b1);
            }
        }
        __syncthreads();
    }

    // ---- normalize + write (j<2 -> o1 dims, j>=2 -> o2 dims) ----
    float inv0 = 1.f / l0;
    float inv1 = 1.f / l1;
    #pragma unroll
    for (int j = 0; j < 4; j++) {
        float* dst = (j < 2) ? g_o1 : g_o2;
        int dbase = h*DHH + (j & 1)*8 + 2*qq;
        *(float2*)&dst[(size_t)r0*DD + dbase] = make_float2(o[j][0]*inv0, o[j][1]*inv0);
        *(float2*)&dst[(size_t)r1*DD + dbase] = make_float2(o[j][2]*inv1, o[j][3]*inv1);
    }
}

// ---------------- host launcher --------------------------------------------
template <typename Sym>
static float* symaddr(const Sym& s) {
    void* p = nullptr;
    cudaGetSymbolAddress(&p, s);
    return (float*)p;
}

extern "C" void kernel_launch(void* const* d_in, const int* in_sizes, int n_in,
                              void* d_out, int out_size)
{
    const float* x_in  = (const float*)d_in[0];
    const float* y_in  = (const float*)d_in[1];
    const float* Wq    = (const float*)d_in[2];
    const float* Wk    = (const float*)d_in[3];
    const float* Wv    = (const float*)d_in[4];
    const float* Wox   = (const float*)d_in[5];
    const float* box   = (const float*)d_in[6];
    const float* Woy   = (const float*)d_in[7];
    const float* boy   = (const float*)d_in[8];
    const float* l1xg  = (const float*)d_in[9];
    const float* l1xb  = (const float*)d_in[10];
    const float* l1yg  = (const float*)d_in[11];
    const float* l1yb  = (const float*)d_in[12];
    const float* l2xg  = (const float*)d_in[13];
    const float* l2xb  = (const float*)d_in[14];
    const float* l2yg  = (const float*)d_in[15];
    const float* l2yb  = (const float*)d_in[16];
    const float* fxw1  = (const float*)d_in[17];
    const float* fxb1  = (const float*)d_in[18];
    const float* fxw2  = (const float*)d_in[19];
    const float* fxb2  = (const float*)d_in[20];
    const float* fyw1  = (const float*)d_in[21];
    const float* fyb1  = (const float*)d_in[22];
    const float* fyw2  = (const float*)d_in[23];
    const float* fyb2  = (const float*)d_in[24];

    float* X = (float*)d_out;
    float* Y = X + (size_t)NTOK*DD;

    float* xn = symaddr(g_xn); float* yn = symaddr(g_yn);
    float* qx = symaddr(g_qx); float* kx = symaddr(g_kx); float* vx = symaddr(g_vx);
    float* qy = symaddr(g_qy); float* ky = symaddr(g_ky); float* vy = symaddr(g_vy);
    float* o1 = symaddr(g_o1); float* o2 = symaddr(g_o2);
    float* hx = symaddr(g_hx); float* hy = symaddr(g_hy);

    size_t bytes = (size_t)NTOK*DD*sizeof(float);
    cudaMemcpyAsync(X, x_in, bytes, cudaMemcpyDeviceToDevice);
    cudaMemcpyAsync(Y, y_in, bytes, cudaMemcpyDeviceToDevice);

    dim3 attnG(BT*HH, TT/64);

    for (int l = 0; l < 2; l++) {
        const float* Wq_l  = Wq  + (size_t)l*DD*DD;
        const float* Wk_l  = Wk  + (size_t)l*DD*DD;
        const float* Wv_l  = Wv  + (size_t)l*DD*DD;
        const float* Wox_l = Wox + (size_t)l*DD*DD;
        const float* Woy_l = Woy + (size_t)l*DD*DD;
        const float* box_l = box + (size_t)l*DD;
        const float* boy_l = boy + (size_t)l*DD;

        ln_kernel<<<2*NTOK, 128>>>(X, Y, xn, yn,
                                   l1xg + l*DD, l1xb + l*DD,
                                   l1yg + l*DD, l1yb + l*DD);

        {
            GemmBatch gb = {};
            gb.A[0]=xn; gb.B[0]=Wq_l; gb.C[0]=qy;
            gb.A[1]=xn; gb.B[1]=Wk_l; gb.C[1]=kx;
            gb.A[2]=xn; gb.B[2]=Wv_l; gb.C[2]=vx;
            gb.A[3]=yn; gb.B[3]=Wq_l; gb.C[3]=qx;
            gb.A[4]=yn; gb.B[4]=Wk_l; gb.C[4]=ky;
            gb.A[5]=yn; gb.B[5]=Wv_l; gb.C[5]=vy;
            dim3 grid(DD/GBN, NTOK/GBM, 6);
            gemm_kernel<<<grid, 256>>>(gb, NTOK, DD, DD, 0);
        }

        attn_kernel<<<attnG, 128>>>();

        {
            GemmBatch gb = {};
            gb.A[0]=o1; gb.B[0]=Wox_l; gb.bias[0]=box_l; gb.res[0]=X; gb.C[0]=X;
            gb.A[1]=o2; gb.B[1]=Woy_l; gb.bias[1]=boy_l; gb.res[1]=Y; gb.C[1]=Y;
            dim3 grid(DD/GBN, NTOK/GBM, 2);
            gemm_kernel<<<grid, 256>>>(gb, NTOK, DD, DD, 1);
        }

        ln_kernel<<<2*NTOK, 128>>>(X, Y, xn, yn,
                                   l2xg + l*DD, l2xb + l*DD,
                                   l2yg + l*DD, l2yb + l*DD);

        {
            GemmBatch gb = {};
            gb.A[0]=xn; gb.B[0]=fxw1 + (size_t)l*DD*FF; gb.bias[0]=fxb1 + l*FF; gb.C[0]=hx;
            gb.A[1]=yn; gb.B[1]=fyw1 + (size_t)l*DD*FF; gb.bias[1]=fyb1 + l*FF; gb.C[1]=hy;
            dim3 grid(FF/GBN, NTOK/GBM, 2);
            gemm_kernel<<<grid, 256>>>(gb, NTOK, FF, DD, 2);
        }
        {
            GemmBatch gb = {};
            gb.A[0]=hx; gb.B[0]=fxw2 + (size_t)l*FF*DD; gb.bias[0]=fxb2 + l*DD; gb.res[0]=X; gb.C[0]=X;
            gb.A[1]=hy; gb.B[1]=fyw2 + (size_t)l*FF*DD; gb.bias[1]=fyb2 + l*DD; gb.res[1]=Y; gb.C[1]=Y;
            dim3 grid(DD/GBN, NTOK/GBM, 2);
            gemm_kernel<<<grid, 256>>>(gb, NTOK, DD, FF, 1);
        }
    }
}

// round 7
// speedup vs baseline: 2.4891x; 1.5525x over previous
#include <cuda_runtime.h>
#include <math.h>

#define BT   8
#define TT   1024
#define DD   128
#define HH   8
#define DHH  16
#define FF   256
#define NTOK (BT*TT)   /* 8192 rows */

// ---------------- scratch (device globals; no allocation allowed) ----------
__device__ float g_xn[NTOK*DD];
__device__ float g_yn[NTOK*DD];
__device__ float g_qx[NTOK*DD];
__device__ float g_kx[NTOK*DD];
__device__ float g_vx[NTOK*DD];
__device__ float g_qy[NTOK*DD];
__device__ float g_ky[NTOK*DD];
__device__ float g_vy[NTOK*DD];
__device__ float g_o1[NTOK*DD];
__device__ float g_o2[NTOK*DD];
__device__ float g_hx[NTOK*FF];
__device__ float g_hy[NTOK*FF];

// ---------------- tf32 mma helpers -----------------------------------------
__device__ __forceinline__ unsigned cvt_tf32(float f) {
    unsigned u;
    asm("cvt.rna.tf32.f32 %0, %1;" : "=r"(u) : "f"(f));
    return u;
}
__device__ __forceinline__ void mma_tf32(float* c,
    unsigned a0, unsigned a1, unsigned a2, unsigned a3,
    unsigned b0, unsigned b1)
{
    asm("mma.sync.aligned.m16n8k8.row.col.f32.tf32.tf32.f32 "
        "{%0,%1,%2,%3}, {%4,%5,%6,%7}, {%8,%9}, {%0,%1,%2,%3};"
        : "+f"(c[0]), "+f"(c[1]), "+f"(c[2]), "+f"(c[3])
        : "r"(a0), "r"(a1), "r"(a2), "r"(a3), "r"(b0), "r"(b1));
}

// ---------------- fused layernorm (both streams) ---------------------------
__global__ void ln_kernel(const float* __restrict__ xs, const float* __restrict__ ys,
                          float* __restrict__ xd, float* __restrict__ yd,
                          const float* __restrict__ gx, const float* __restrict__ bx,
                          const float* __restrict__ gy, const float* __restrict__ by)
{
    int row = blockIdx.x;
    bool second = row >= NTOK;
    int r = second ? row - NTOK : row;
    const float* src = second ? ys : xs;
    float*       dst = second ? yd : xd;
    const float* g   = second ? gy : gx;
    const float* b   = second ? by : bx;

    int t = threadIdx.x;
    float v = src[(size_t)r*DD + t];
    float s = v, s2 = v*v;
    #pragma unroll
    for (int o = 16; o; o >>= 1) {
        s  += __shfl_xor_sync(0xffffffffu, s , o);
        s2 += __shfl_xor_sync(0xffffffffu, s2, o);
    }
    __shared__ float ss[4], ss2[4];
    int w = t >> 5;
    if ((t & 31) == 0) { ss[w] = s; ss2[w] = s2; }
    __syncthreads();
    s  = ss[0]+ss[1]+ss[2]+ss[3];
    s2 = ss2[0]+ss2[1]+ss2[2]+ss2[3];
    float mean = s * (1.0f/DD);
    float var  = s2 * (1.0f/DD) - mean*mean;
    float inv  = rsqrtf(var + 1e-5f);
    dst[(size_t)r*DD + t] = (v - mean) * inv * g[t] + b[t];
}

// ---------------- batched tf32 tensor-core GEMM ----------------------------
// 64x64 block tile, BK=32, 128 threads = 4 warps (2x2), 32x32 per warp.
// mode 0: C = acc ; mode 1: C = res + acc + bias[n] ; mode 2: C = gelu(acc+bias)
#define TBM 64
#define TBN 64
#define TBK 32
#define APAD 36   /* As row stride: a-frag bank = (4*gq+qq)&31 -> conflict-free */
#define BPAD 72   /* Bs row stride: b-frag bank = (8*qq+gq+..)&31 -> conflict-free */

struct GemmBatch {
    const float* A[6];
    const float* B[6];
    const float* bias[6];
    const float* res[6];
    float*       C[6];
};

__global__ void __launch_bounds__(128)
gemm_tc_kernel(GemmBatch g, int M, int N, int K, int mode)
{
    const int z = blockIdx.z;
    const float* __restrict__ A    = g.A[z];
    const float* __restrict__ B    = g.B[z];
    const float* __restrict__ bias = g.bias[z];
    const float* __restrict__ res  = g.res[z];
    float*       __restrict__ C    = g.C[z];

    __shared__ unsigned As[TBM][APAD];   // [m][k] tf32 bits
    __shared__ unsigned Bs[TBK][BPAD];   // [k][n] tf32 bits

    int bn = blockIdx.x * TBN;
    int bm = blockIdx.y * TBM;
    int tid  = threadIdx.x;
    int w    = tid >> 5;
    int lane = tid & 31;
    int gq   = lane >> 2;
    int qq   = lane & 3;
    int wm   = (w & 1) * 32;
    int wn   = (w >> 1) * 32;

    float c[2][4][4];
    #pragma unroll
    for (int mi = 0; mi < 2; mi++)
        #pragma unroll
        for (int ni = 0; ni < 4; ni++)
            #pragma unroll
            for (int r = 0; r < 4; r++) c[mi][ni][r] = 0.f;

    for (int k0 = 0; k0 < K; k0 += TBK) {
        // A tile: 64 m x 32 k  (4 float4 per thread)
        #pragma unroll
        for (int e = tid; e < 512; e += 128) {
            int row  = e >> 3;
            int col4 = (e & 7) * 4;
            float4 a = *(const float4*)&A[(size_t)(bm + row)*K + k0 + col4];
            As[row][col4+0] = cvt_tf32(a.x);
            As[row][col4+1] = cvt_tf32(a.y);
            As[row][col4+2] = cvt_tf32(a.z);
            As[row][col4+3] = cvt_tf32(a.w);
        }
        // B tile: 32 k x 64 n  (4 float4 per thread)
        #pragma unroll
        for (int e = tid; e < 512; e += 128) {
            int row  = e >> 4;
            int col4 = (e & 15) * 4;
            float4 b = *(const float4*)&B[(size_t)(k0 + row)*N + bn + col4];
            Bs[row][col4+0] = cvt_tf32(b.x);
            Bs[row][col4+1] = cvt_tf32(b.y);
            Bs[row][col4+2] = cvt_tf32(b.z);
            Bs[row][col4+3] = cvt_tf32(b.w);
        }
        __syncthreads();

        #pragma unroll
        for (int kc = 0; kc < TBK/8; kc++) {
            unsigned a[2][4], bf[4][2];
            #pragma unroll
            for (int mi = 0; mi < 2; mi++) {
                int m0 = wm + mi*16;
                a[mi][0] = As[m0 + gq    ][kc*8 + qq];
                a[mi][1] = As[m0 + gq + 8][kc*8 + qq];
                a[mi][2] = As[m0 + gq    ][kc*8 + qq + 4];
                a[mi][3] = As[m0 + gq + 8][kc*8 + qq + 4];
            }
            #pragma unroll
            for (int ni = 0; ni < 4; ni++) {
                bf[ni][0] = Bs[kc*8 + qq    ][wn + ni*8 + gq];
                bf[ni][1] = Bs[kc*8 + qq + 4][wn + ni*8 + gq];
            }
            #pragma unroll
            for (int mi = 0; mi < 2; mi++)
                #pragma unroll
                for (int ni = 0; ni < 4; ni++)
                    mma_tf32(c[mi][ni], a[mi][0], a[mi][1], a[mi][2], a[mi][3],
                             bf[ni][0], bf[ni][1]);
        }
        __syncthreads();
    }

    // ---- epilogue (fp32) ----
    #pragma unroll
    for (int mi = 0; mi < 2; mi++) {
        int r0 = bm + wm + mi*16 + gq;
        int r1 = r0 + 8;
        #pragma unroll
        for (int ni = 0; ni < 4; ni++) {
            int n0 = bn + wn + ni*8 + 2*qq;
            float v0 = c[mi][ni][0], v1 = c[mi][ni][1];
            float v2 = c[mi][ni][2], v3 = c[mi][ni][3];
            if (mode == 1) {
                float b0 = bias[n0], b1 = bias[n0+1];
                v0 += b0 + res[(size_t)r0*N + n0];
                v1 += b1 + res[(size_t)r0*N + n0+1];
                v2 += b0 + res[(size_t)r1*N + n0];
                v3 += b1 + res[(size_t)r1*N + n0+1];
            } else if (mode == 2) {
                float b0 = bias[n0], b1 = bias[n0+1];
                v0 += b0; v1 += b1; v2 += b0; v3 += b1;
                v0 = 0.5f * v0 * (1.0f + erff(v0 * 0.70710678118654752f));
                v1 = 0.5f * v1 * (1.0f + erff(v1 * 0.70710678118654752f));
                v2 = 0.5f * v2 * (1.0f + erff(v2 * 0.70710678118654752f));
                v3 = 0.5f * v3 * (1.0f + erff(v3 * 0.70710678118654752f));
            }
            *(float2*)&C[(size_t)r0*N + n0] = make_float2(v0, v1);
            *(float2*)&C[(size_t)r1*N + n0] = make_float2(v2, v3);
        }
    }
}

// ---------------- tensor-core dual-branch flash attention (tf32) -----------
#define KPAD 36
#define PPAD 67
__global__ void __launch_bounds__(128)
attn_kernel()
{
    __shared__ unsigned Ks[64][KPAD];
    __shared__ unsigned Vs[64][KPAD];
    __shared__ unsigned Ps[4][16][PPAD];

    int bh = blockIdx.x;
    int b  = bh >> 3;
    int h  = bh & 7;
    int tid  = threadIdx.x;
    int w    = tid >> 5;
    int lane = tid & 31;
    int gq   = lane >> 2;
    int qq   = lane & 3;

    int tok0 = b*TT + blockIdx.y*64 + w*16;
    int r0 = tok0 + gq;
    int r1 = r0 + 8;

    unsigned qa[4][4];
    #pragma unroll
    for (int kc = 0; kc < 4; kc++) {
        const float* src = (kc < 2) ? g_qx : g_qy;
        int d0 = (kc & 1)*8 + qq;
        qa[kc][0] = cvt_tf32(0.125f * src[(size_t)r0*DD + h*DHH + d0]);
        qa[kc][1] = cvt_tf32(0.125f * src[(size_t)r1*DD + h*DHH + d0]);
        qa[kc][2] = cvt_tf32(0.125f * src[(size_t)r0*DD + h*DHH + d0 + 4]);
        qa[kc][3] = cvt_tf32(0.125f * src[(size_t)r1*DD + h*DHH + d0 + 4]);
    }

    float o[4][4];
    #pragma unroll
    for (int j = 0; j < 4; j++)
        #pragma unroll
        for (int cc = 0; cc < 4; cc++) o[j][cc] = 0.f;
    float l0 = 0.f, l1 = 0.f;

    for (int kt = 0; kt < TT/64; kt++) {
        #pragma unroll
        for (int it = 0; it < 4; it++) {
            int e   = tid + it*128;
            int row = e >> 3;
            int c4  = (e & 7) * 4;
            int tokk = b*TT + kt*64 + row;
            int dd = c4 & 15;
            const float* ksrc = (c4 < 16) ? g_kx : g_ky;
            const float* vsrc = (c4 < 16) ? g_vx : g_vy;
            float4 kv = *(const float4*)&ksrc[(size_t)tokk*DD + h*DHH + dd];
            float4 vv = *(const float4*)&vsrc[(size_t)tokk*DD + h*DHH + dd];
            Ks[row][c4+0] = cvt_tf32(kv.x);
            Ks[row][c4+1] = cvt_tf32(kv.y);
            Ks[row][c4+2] = cvt_tf32(kv.z);
            Ks[row][c4+3] = cvt_tf32(kv.w);
            Vs[row][c4+0] = cvt_tf32(vv.x);
            Vs[row][c4+1] = cvt_tf32(vv.y);
            Vs[row][c4+2] = cvt_tf32(vv.z);
            Vs[row][c4+3] = cvt_tf32(vv.w);
        }
        __syncthreads();

        float sc[8][4];
        #pragma unroll
        for (int j = 0; j < 8; j++) {
            sc[j][0] = sc[j][1] = sc[j][2] = sc[j][3] = 0.f;
            #pragma unroll
            for (int kc = 0; kc < 4; kc++) {
                unsigned b0 = Ks[j*8 + gq][kc*8 + qq];
                unsigned b1 = Ks[j*8 + gq][kc*8 + qq + 4];
                mma_tf32(sc[j], qa[kc][0], qa[kc][1], qa[kc][2], qa[kc][3], b0, b1);
            }
        }

        float rs0 = 0.f, rs1 = 0.f;
        #pragma unroll
        for (int j = 0; j < 8; j++) {
            float p0 = __expf(sc[j][0]);
            float p1 = __expf(sc[j][1]);
            float p2 = __expf(sc[j][2]);
            float p3 = __expf(sc[j][3]);
            rs0 += p0 + p1;
            rs1 += p2 + p3;
            Ps[w][gq  ][8*j + 2*qq    ] = cvt_tf32(p0);
            Ps[w][gq  ][8*j + 2*qq + 1] = cvt_tf32(p1);
            Ps[w][gq+8][8*j + 2*qq    ] = cvt_tf32(p2);
            Ps[w][gq+8][8*j + 2*qq + 1] = cvt_tf32(p3);
        }
        rs0 += __shfl_xor_sync(0xffffffffu, rs0, 1);
        rs0 += __shfl_xor_sync(0xffffffffu, rs0, 2);
        rs1 += __shfl_xor_sync(0xffffffffu, rs1, 1);
        rs1 += __shfl_xor_sync(0xffffffffu, rs1, 2);
        l0 += rs0;
        l1 += rs1;
        __syncwarp();

        #pragma unroll
        for (int kc2 = 0; kc2 < 8; kc2++) {
            unsigned a0 = Ps[w][gq  ][8*kc2 + qq];
            unsigned a1 = Ps[w][gq+8][8*kc2 + qq];
            unsigned a2 = Ps[w][gq  ][8*kc2 + qq + 4];
            unsigned a3 = Ps[w][gq+8][8*kc2 + qq + 4];
            #pragma unroll
            for (int j = 0; j < 4; j++) {
                unsigned b0 = Vs[8*kc2 + qq    ][8*j + gq];
                unsigned b1 = Vs[8*kc2 + qq + 4][8*j + gq];
                mma_tf32(o[j], a0, a1, a2, a3, b0, b1);
            }
        }
        __syncthreads();
    }

    float inv0 = 1.f / l0;
    float inv1 = 1.f / l1;
    #pragma unroll
    for (int j = 0; j < 4; j++) {
        float* dst = (j < 2) ? g_o1 : g_o2;
        int dbase = h*DHH + (j & 1)*8 + 2*qq;
        *(float2*)&dst[(size_t)r0*DD + dbase] = make_float2(o[j][0]*inv0, o[j][1]*inv0);
        *(float2*)&dst[(size_t)r1*DD + dbase] = make_float2(o[j][2]*inv1, o[j][3]*inv1);
    }
}

// ---------------- host launcher --------------------------------------------
template <typename Sym>
static float* symaddr(const Sym& s) {
    void* p = nullptr;
    cudaGetSymbolAddress(&p, s);
    return (float*)p;
}

extern "C" void kernel_launch(void* const* d_in, const int* in_sizes, int n_in,
                              void* d_out, int out_size)
{
    const float* x_in  = (const float*)d_in[0];
    const float* y_in  = (const float*)d_in[1];
    const float* Wq    = (const float*)d_in[2];
    const float* Wk    = (const float*)d_in[3];
    const float* Wv    = (const float*)d_in[4];
    const float* Wox   = (const float*)d_in[5];
    const float* box   = (const float*)d_in[6];
    const float* Woy   = (const float*)d_in[7];
    const float* boy   = (const float*)d_in[8];
    const float* l1xg  = (const float*)d_in[9];
    const float* l1xb  = (const float*)d_in[10];
    const float* l1yg  = (const float*)d_in[11];
    const float* l1yb  = (const float*)d_in[12];
    const float* l2xg  = (const float*)d_in[13];
    const float* l2xb  = (const float*)d_in[14];
    const float* l2yg  = (const float*)d_in[15];
    const float* l2yb  = (const float*)d_in[16];
    const float* fxw1  = (const float*)d_in[17];
    const float* fxb1  = (const float*)d_in[18];
    const float* fxw2  = (const float*)d_in[19];
    const float* fxb2  = (const float*)d_in[20];
    const float* fyw1  = (const float*)d_in[21];
    const float* fyb1  = (const float*)d_in[22];
    const float* fyw2  = (const float*)d_in[23];
    const float* fyb2  = (const float*)d_in[24];

    float* X = (float*)d_out;
    float* Y = X + (size_t)NTOK*DD;

    float* xn = symaddr(g_xn); float* yn = symaddr(g_yn);
    float* qx = symaddr(g_qx); float* kx = symaddr(g_kx); float* vx = symaddr(g_vx);
    float* qy = symaddr(g_qy); float* ky = symaddr(g_ky); float* vy = symaddr(g_vy);
    float* o1 = symaddr(g_o1); float* o2 = symaddr(g_o2);
    float* hx = symaddr(g_hx); float* hy = symaddr(g_hy);

    size_t bytes = (size_t)NTOK*DD*sizeof(float);
    cudaMemcpyAsync(X, x_in, bytes, cudaMemcpyDeviceToDevice);
    cudaMemcpyAsync(Y, y_in, bytes, cudaMemcpyDeviceToDevice);

    dim3 attnG(BT*HH, TT/64);

    for (int l = 0; l < 2; l++) {
        const float* Wq_l  = Wq  + (size_t)l*DD*DD;
        const float* Wk_l  = Wk  + (size_t)l*DD*DD;
        const float* Wv_l  = Wv  + (size_t)l*DD*DD;
        const float* Wox_l = Wox + (size_t)l*DD*DD;
        const float* Woy_l = Woy + (size_t)l*DD*DD;
        const float* box_l = box + (size_t)l*DD;
        const float* boy_l = boy + (size_t)l*DD;

        ln_kernel<<<2*NTOK, 128>>>(X, Y, xn, yn,
                                   l1xg + l*DD, l1xb + l*DD,
                                   l1yg + l*DD, l1yb + l*DD);

        {
            GemmBatch gb = {};
            gb.A[0]=xn; gb.B[0]=Wq_l; gb.C[0]=qy;
            gb.A[1]=xn; gb.B[1]=Wk_l; gb.C[1]=kx;
            gb.A[2]=xn; gb.B[2]=Wv_l; gb.C[2]=vx;
            gb.A[3]=yn; gb.B[3]=Wq_l; gb.C[3]=qx;
            gb.A[4]=yn; gb.B[4]=Wk_l; gb.C[4]=ky;
            gb.A[5]=yn; gb.B[5]=Wv_l; gb.C[5]=vy;
            dim3 grid(DD/TBN, NTOK/TBM, 6);   // (2,128,6) = 1536 blocks
            gemm_tc_kernel<<<grid, 128>>>(gb, NTOK, DD, DD, 0);
        }

        attn_kernel<<<attnG, 128>>>();

        {
            GemmBatch gb = {};
            gb.A[0]=o1; gb.B[0]=Wox_l; gb.bias[0]=box_l; gb.res[0]=X; gb.C[0]=X;
            gb.A[1]=o2; gb.B[1]=Woy_l; gb.bias[1]=boy_l; gb.res[1]=Y; gb.C[1]=Y;
            dim3 grid(DD/TBN, NTOK/TBM, 2);   // (2,128,2) = 512 blocks
            gemm_tc_kernel<<<grid, 128>>>(gb, NTOK, DD, DD, 1);
        }

        ln_kernel<<<2*NTOK, 128>>>(X, Y, xn, yn,
                                   l2xg + l*DD, l2xb + l*DD,
                                   l2yg + l*DD, l2yb + l*DD);

        {
            GemmBatch gb = {};
            gb.A[0]=xn; gb.B[0]=fxw1 + (size_t)l*DD*FF; gb.bias[0]=fxb1 + l*FF; gb.C[0]=hx;
            gb.A[1]=yn; gb.B[1]=fyw1 + (size_t)l*DD*FF; gb.bias[1]=fyb1 + l*FF; gb.C[1]=hy;
            dim3 grid(FF/TBN, NTOK/TBM, 2);   // (4,128,2) = 1024 blocks
            gemm_tc_kernel<<<grid, 128>>>(gb, NTOK, FF, DD, 2);
        }
        {
            GemmBatch gb = {};
            gb.A[0]=hx; gb.B[0]=fxw2 + (size_t)l*FF*DD; gb.bias[0]=fxb2 + l*DD; gb.res[0]=X; gb.C[0]=X;
            gb.A[1]=hy; gb.B[1]=fyw2 + (size_t)l*FF*DD; gb.bias[1]=fyb2 + l*DD; gb.res[1]=Y; gb.C[1]=Y;
            dim3 grid(DD/TBN, NTOK/TBM, 2);   // (2,128,2) = 512 blocks
            gemm_tc_kernel<<<grid, 128>>>(gb, NTOK, DD, FF, 1);
        }
    }
}

// round 8
// speedup vs baseline: 2.6536x; 1.0661x over previous
#include <cuda_runtime.h>
#include <math.h>

#define BT   8
#define TT   1024
#define DD   128
#define HH   8
#define DHH  16
#define FF   256
#define NTOK (BT*TT)   /* 8192 rows */

// ---------------- scratch (device globals; no allocation allowed) ----------
__device__ float g_xn[NTOK*DD];
__device__ float g_yn[NTOK*DD];
__device__ float g_qx[NTOK*DD];   // tf32 bits (pre-scaled by 0.125)
__device__ float g_kx[NTOK*DD];   // tf32 bits
__device__ float g_vx[NTOK*DD];   // tf32 bits
__device__ float g_qy[NTOK*DD];   // tf32 bits (pre-scaled by 0.125)
__device__ float g_ky[NTOK*DD];   // tf32 bits
__device__ float g_vy[NTOK*DD];   // tf32 bits
__device__ float g_o1[NTOK*DD];
__device__ float g_o2[NTOK*DD];
__device__ float g_hx[NTOK*FF];
__device__ float g_hy[NTOK*FF];

// ---------------- tf32 mma helpers -----------------------------------------
__device__ __forceinline__ unsigned cvt_tf32(float f) {
    unsigned u;
    asm("cvt.rna.tf32.f32 %0, %1;" : "=r"(u) : "f"(f));
    return u;
}
__device__ __forceinline__ void mma_tf32(float* c,
    unsigned a0, unsigned a1, unsigned a2, unsigned a3,
    unsigned b0, unsigned b1)
{
    asm("mma.sync.aligned.m16n8k8.row.col.f32.tf32.tf32.f32 "
        "{%0,%1,%2,%3}, {%4,%5,%6,%7}, {%8,%9}, {%0,%1,%2,%3};"
        : "+f"(c[0]), "+f"(c[1]), "+f"(c[2]), "+f"(c[3])
        : "r"(a0), "r"(a1), "r"(a2), "r"(a3), "r"(b0), "r"(b1));
}

// ---------------- fused layernorm (both streams) ---------------------------
__global__ void ln_kernel(const float* __restrict__ xs, const float* __restrict__ ys,
                          float* __restrict__ xd, float* __restrict__ yd,
                          const float* __restrict__ gx, const float* __restrict__ bx,
                          const float* __restrict__ gy, const float* __restrict__ by)
{
    int row = blockIdx.x;
    bool second = row >= NTOK;
    int r = second ? row - NTOK : row;
    const float* src = second ? ys : xs;
    float*       dst = second ? yd : xd;
    const float* g   = second ? gy : gx;
    const float* b   = second ? by : bx;

    int t = threadIdx.x;
    float v = src[(size_t)r*DD + t];
    float s = v, s2 = v*v;
    #pragma unroll
    for (int o = 16; o; o >>= 1) {
        s  += __shfl_xor_sync(0xffffffffu, s , o);
        s2 += __shfl_xor_sync(0xffffffffu, s2, o);
    }
    __shared__ float ss[4], ss2[4];
    int w = t >> 5;
    if ((t & 31) == 0) { ss[w] = s; ss2[w] = s2; }
    __syncthreads();
    s  = ss[0]+ss[1]+ss[2]+ss[3];
    s2 = ss2[0]+ss2[1]+ss2[2]+ss2[3];
    float mean = s * (1.0f/DD);
    float var  = s2 * (1.0f/DD) - mean*mean;
    float inv  = rsqrtf(var + 1e-5f);
    dst[(size_t)r*DD + t] = (v - mean) * inv * g[t] + b[t];
}

// ---------------- batched tf32 tensor-core GEMM ----------------------------
// 64x64 block tile, BK=32, 128 threads = 4 warps (2x2), 32x32 per warp.
// per-z epilogue mode em[z]:
//  0: C = acc (fp32)
//  1: C = res + acc + bias[n]
//  2: C = gelu(acc + bias[n])      (exact erf gelu)
//  3: C = tf32_bits(acc)
//  4: C = tf32_bits(0.125 * acc)
#define TBM 64
#define TBN 64
#define TBK 32
#define APAD 36
#define BPAD 72

struct GemmBatch {
    const float* A[6];
    const float* B[6];
    const float* bias[6];
    const float* res[6];
    float*       C[6];
    int          em[6];
};

__global__ void __launch_bounds__(128)
gemm_tc_kernel(GemmBatch g, int M, int N, int K)
{
    const int z = blockIdx.z;
    const float* __restrict__ A    = g.A[z];
    const float* __restrict__ B    = g.B[z];
    const float* __restrict__ bias = g.bias[z];
    const float* __restrict__ res  = g.res[z];
    float*       __restrict__ C    = g.C[z];
    const int mode = g.em[z];

    __shared__ unsigned As[TBM][APAD];
    __shared__ unsigned Bs[TBK][BPAD];

    int bn = blockIdx.x * TBN;
    int bm = blockIdx.y * TBM;
    int tid  = threadIdx.x;
    int w    = tid >> 5;
    int lane = tid & 31;
    int gq   = lane >> 2;
    int qq   = lane & 3;
    int wm   = (w & 1) * 32;
    int wn   = (w >> 1) * 32;

    float c[2][4][4];
    #pragma unroll
    for (int mi = 0; mi < 2; mi++)
        #pragma unroll
        for (int ni = 0; ni < 4; ni++)
            #pragma unroll
            for (int r = 0; r < 4; r++) c[mi][ni][r] = 0.f;

    for (int k0 = 0; k0 < K; k0 += TBK) {
        #pragma unroll
        for (int e = tid; e < 512; e += 128) {
            int row  = e >> 3;
            int col4 = (e & 7) * 4;
            float4 a = *(const float4*)&A[(size_t)(bm + row)*K + k0 + col4];
            As[row][col4+0] = cvt_tf32(a.x);
            As[row][col4+1] = cvt_tf32(a.y);
            As[row][col4+2] = cvt_tf32(a.z);
            As[row][col4+3] = cvt_tf32(a.w);
        }
        #pragma unroll
        for (int e = tid; e < 512; e += 128) {
            int row  = e >> 4;
            int col4 = (e & 15) * 4;
            float4 b = *(const float4*)&B[(size_t)(k0 + row)*N + bn + col4];
            Bs[row][col4+0] = cvt_tf32(b.x);
            Bs[row][col4+1] = cvt_tf32(b.y);
            Bs[row][col4+2] = cvt_tf32(b.z);
            Bs[row][col4+3] = cvt_tf32(b.w);
        }
        __syncthreads();

        #pragma unroll
        for (int kc = 0; kc < TBK/8; kc++) {
            unsigned a[2][4], bf[4][2];
            #pragma unroll
            for (int mi = 0; mi < 2; mi++) {
                int m0 = wm + mi*16;
                a[mi][0] = As[m0 + gq    ][kc*8 + qq];
                a[mi][1] = As[m0 + gq + 8][kc*8 + qq];
                a[mi][2] = As[m0 + gq    ][kc*8 + qq + 4];
                a[mi][3] = As[m0 + gq + 8][kc*8 + qq + 4];
            }
            #pragma unroll
            for (int ni = 0; ni < 4; ni++) {
                bf[ni][0] = Bs[kc*8 + qq    ][wn + ni*8 + gq];
                bf[ni][1] = Bs[kc*8 + qq + 4][wn + ni*8 + gq];
            }
            #pragma unroll
            for (int mi = 0; mi < 2; mi++)
                #pragma unroll
                for (int ni = 0; ni < 4; ni++)
                    mma_tf32(c[mi][ni], a[mi][0], a[mi][1], a[mi][2], a[mi][3],
                             bf[ni][0], bf[ni][1]);
        }
        __syncthreads();
    }

    #pragma unroll
    for (int mi = 0; mi < 2; mi++) {
        int r0 = bm + wm + mi*16 + gq;
        int r1 = r0 + 8;
        #pragma unroll
        for (int ni = 0; ni < 4; ni++) {
            int n0 = bn + wn + ni*8 + 2*qq;
            float v0 = c[mi][ni][0], v1 = c[mi][ni][1];
            float v2 = c[mi][ni][2], v3 = c[mi][ni][3];
            if (mode == 1) {
                float b0 = bias[n0], b1 = bias[n0+1];
                v0 += b0 + res[(size_t)r0*N + n0];
                v1 += b1 + res[(size_t)r0*N + n0+1];
                v2 += b0 + res[(size_t)r1*N + n0];
                v3 += b1 + res[(size_t)r1*N + n0+1];
            } else if (mode == 2) {
                float b0 = bias[n0], b1 = bias[n0+1];
                v0 += b0; v1 += b1; v2 += b0; v3 += b1;
                v0 = 0.5f * v0 * (1.0f + erff(v0 * 0.70710678118654752f));
                v1 = 0.5f * v1 * (1.0f + erff(v1 * 0.70710678118654752f));
                v2 = 0.5f * v2 * (1.0f + erff(v2 * 0.70710678118654752f));
                v3 = 0.5f * v3 * (1.0f + erff(v3 * 0.70710678118654752f));
            }
            if (mode <= 2) {
                *(float2*)&C[(size_t)r0*N + n0] = make_float2(v0, v1);
                *(float2*)&C[(size_t)r1*N + n0] = make_float2(v2, v3);
            } else {
                float sc = (mode == 4) ? 0.125f : 1.0f;
                unsigned* Cu = (unsigned*)C;
                *(uint2*)&Cu[(size_t)r0*N + n0] =
                    make_uint2(cvt_tf32(v0*sc), cvt_tf32(v1*sc));
                *(uint2*)&Cu[(size_t)r1*N + n0] =
                    make_uint2(cvt_tf32(v2*sc), cvt_tf32(v3*sc));
            }
        }
    }
}

// ---------------- tensor-core dual-branch flash attention (tf32) -----------
// Q/K/V arrive as tf32 bits (Q pre-scaled by 0.125). 8 warps, 128 q/block.
// P re-layout C-frag -> A-frag via intra-quad shuffles (no smem staging).
#define KPAD 36
__global__ void __launch_bounds__(256)
attn_kernel()
{
    __shared__ unsigned Ks[64][KPAD];
    __shared__ unsigned Vs[64][KPAD];

    int bh = blockIdx.x;
    int b  = bh >> 3;
    int h  = bh & 7;
    int tid  = threadIdx.x;
    int w    = tid >> 5;
    int lane = tid & 31;
    int gq   = lane >> 2;
    int qq   = lane & 3;

    const unsigned* QX = (const unsigned*)g_qx;
    const unsigned* QY = (const unsigned*)g_qy;
    const unsigned* KX = (const unsigned*)g_kx;
    const unsigned* KY = (const unsigned*)g_ky;
    const unsigned* VX = (const unsigned*)g_vx;
    const unsigned* VY = (const unsigned*)g_vy;

    int tok0 = b*TT + blockIdx.y*128 + w*16;
    int r0 = tok0 + gq;
    int r1 = r0 + 8;

    unsigned qa[4][4];
    #pragma unroll
    for (int kc = 0; kc < 4; kc++) {
        const unsigned* src = (kc < 2) ? QX : QY;
        int d0 = (kc & 1)*8 + qq;
        qa[kc][0] = src[(size_t)r0*DD + h*DHH + d0];
        qa[kc][1] = src[(size_t)r1*DD + h*DHH + d0];
        qa[kc][2] = src[(size_t)r0*DD + h*DHH + d0 + 4];
        qa[kc][3] = src[(size_t)r1*DD + h*DHH + d0 + 4];
    }

    float o[4][4];
    #pragma unroll
    for (int j = 0; j < 4; j++)
        #pragma unroll
        for (int cc = 0; cc < 4; cc++) o[j][cc] = 0.f;
    float l0 = 0.f, l1 = 0.f;

    int srcA = 4*gq + (qq >> 1);
    int srcB = srcA + 2;
    bool odd = qq & 1;

    for (int kt = 0; kt < TT/64; kt++) {
        // ---- K/V tile load: raw uint4, no conversion ----
        #pragma unroll
        for (int it = 0; it < 2; it++) {
            int e   = tid + it*256;           // 0..511
            int row = e >> 3;
            int c4  = (e & 7) * 4;
            int tokk = b*TT + kt*64 + row;
            int dd = c4 & 15;
            const unsigned* ksrc = (c4 < 16) ? KX : KY;
            const unsigned* vsrc = (c4 < 16) ? VX : VY;
            *(uint4*)&Ks[row][c4] = *(const uint4*)&ksrc[(size_t)tokk*DD + h*DHH + dd];
            *(uint4*)&Vs[row][c4] = *(const uint4*)&vsrc[(size_t)tokk*DD + h*DHH + dd];
        }
        __syncthreads();

        float rs0 = 0.f, rs1 = 0.f;
        #pragma unroll
        for (int j = 0; j < 8; j++) {
            // ---- S chunk j: 16 q x 8 keys ----
            float sc[4] = {0.f, 0.f, 0.f, 0.f};
            #pragma unroll
            for (int kc = 0; kc < 4; kc++) {
                unsigned b0 = Ks[j*8 + gq][kc*8 + qq];
                unsigned b1 = Ks[j*8 + gq][kc*8 + qq + 4];
                mma_tf32(sc, qa[kc][0], qa[kc][1], qa[kc][2], qa[kc][3], b0, b1);
            }
            // ---- exp + row-sum partials ----
            float p0 = __expf(sc[0]);
            float p1 = __expf(sc[1]);
            float p2 = __expf(sc[2]);
            float p3 = __expf(sc[3]);
            rs0 += p0 + p1;
            rs1 += p2 + p3;
            unsigned pb0 = cvt_tf32(p0);
            unsigned pb1 = cvt_tf32(p1);
            unsigned pb2 = cvt_tf32(p2);
            unsigned pb3 = cvt_tf32(p3);
            // ---- C-frag -> A-frag re-layout via intra-quad shuffles ----
            unsigned e0 = __shfl_sync(0xffffffffu, pb0, srcA);
            unsigned e1 = __shfl_sync(0xffffffffu, pb1, srcA);
            unsigned f2 = __shfl_sync(0xffffffffu, pb2, srcA);
            unsigned f3 = __shfl_sync(0xffffffffu, pb3, srcA);
            unsigned g0 = __shfl_sync(0xffffffffu, pb0, srcB);
            unsigned g1 = __shfl_sync(0xffffffffu, pb1, srcB);
            unsigned h2 = __shfl_sync(0xffffffffu, pb2, srcB);
            unsigned h3 = __shfl_sync(0xffffffffu, pb3, srcB);
            unsigned a0 = odd ? e1 : e0;
            unsigned a1 = odd ? f3 : f2;
            unsigned a2 = odd ? g1 : g0;
            unsigned a3 = odd ? h3 : h2;
            // ---- O += P_j @ V_j ----
            #pragma unroll
            for (int jv = 0; jv < 4; jv++) {
                unsigned b0 = Vs[8*j + qq    ][8*jv + gq];
                unsigned b1 = Vs[8*j + qq + 4][8*jv + gq];
                mma_tf32(o[jv], a0, a1, a2, a3, b0, b1);
            }
        }
        rs0 += __shfl_xor_sync(0xffffffffu, rs0, 1);
        rs0 += __shfl_xor_sync(0xffffffffu, rs0, 2);
        rs1 += __shfl_xor_sync(0xffffffffu, rs1, 1);
        rs1 += __shfl_xor_sync(0xffffffffu, rs1, 2);
        l0 += rs0;
        l1 += rs1;
        __syncthreads();
    }

    float inv0 = 1.f / l0;
    float inv1 = 1.f / l1;
    #pragma unroll
    for (int j = 0; j < 4; j++) {
        float* dst = (j < 2) ? g_o1 : g_o2;
        int dbase = h*DHH + (j & 1)*8 + 2*qq;
        *(float2*)&dst[(size_t)r0*DD + dbase] = make_float2(o[j][0]*inv0, o[j][1]*inv0);
        *(float2*)&dst[(size_t)r1*DD + dbase] = make_float2(o[j][2]*inv1, o[j][3]*inv1);
    }
}

// ---------------- host launcher --------------------------------------------
template <typename Sym>
static float* symaddr(const Sym& s) {
    void* p = nullptr;
    cudaGetSymbolAddress(&p, s);
    return (float*)p;
}

extern "C" void kernel_launch(void* const* d_in, const int* in_sizes, int n_in,
                              void* d_out, int out_size)
{
    const float* x_in  = (const float*)d_in[0];
    const float* y_in  = (const float*)d_in[1];
    const float* Wq    = (const float*)d_in[2];
    const float* Wk    = (const float*)d_in[3];
    const float* Wv    = (const float*)d_in[4];
    const float* Wox   = (const float*)d_in[5];
    const float* box   = (const float*)d_in[6];
    const float* Woy   = (const float*)d_in[7];
    const float* boy   = (const float*)d_in[8];
    const float* l1xg  = (const float*)d_in[9];
    const float* l1xb  = (const float*)d_in[10];
    const float* l1yg  = (const float*)d_in[11];
    const float* l1yb  = (const float*)d_in[12];
    const float* l2xg  = (const float*)d_in[13];
    const float* l2xb  = (const float*)d_in[14];
    const float* l2yg  = (const float*)d_in[15];
    const float* l2yb  = (const float*)d_in[16];
    const float* fxw1  = (const float*)d_in[17];
    const float* fxb1  = (const float*)d_in[18];
    const float* fxw2  = (const float*)d_in[19];
    const float* fxb2  = (const float*)d_in[20];
    const float* fyw1  = (const float*)d_in[21];
    const float* fyb1  = (const float*)d_in[22];
    const float* fyw2  = (const float*)d_in[23];
    const float* fyb2  = (const float*)d_in[24];

    float* X = (float*)d_out;
    float* Y = X + (size_t)NTOK*DD;

    float* xn = symaddr(g_xn); float* yn = symaddr(g_yn);
    float* qx = symaddr(g_qx); float* kx = symaddr(g_kx); float* vx = symaddr(g_vx);
    float* qy = symaddr(g_qy); float* ky = symaddr(g_ky); float* vy = symaddr(g_vy);
    float* o1 = symaddr(g_o1); float* o2 = symaddr(g_o2);
    float* hx = symaddr(g_hx); float* hy = symaddr(g_hy);

    size_t bytes = (size_t)NTOK*DD*sizeof(float);
    cudaMemcpyAsync(X, x_in, bytes, cudaMemcpyDeviceToDevice);
    cudaMemcpyAsync(Y, y_in, bytes, cudaMemcpyDeviceToDevice);

    dim3 attnG(BT*HH, TT/128);

    for (int l = 0; l < 2; l++) {
        const float* Wq_l  = Wq  + (size_t)l*DD*DD;
        const float* Wk_l  = Wk  + (size_t)l*DD*DD;
        const float* Wv_l  = Wv  + (size_t)l*DD*DD;
        const float* Wox_l = Wox + (size_t)l*DD*DD;
        const float* Woy_l = Woy + (size_t)l*DD*DD;
        const float* box_l = box + (size_t)l*DD;
        const float* boy_l = boy + (size_t)l*DD;

        ln_kernel<<<2*NTOK, 128>>>(X, Y, xn, yn,
                                   l1xg + l*DD, l1xb + l*DD,
                                   l1yg + l*DD, l1yb + l*DD);

        {
            GemmBatch gb = {};
            gb.A[0]=xn; gb.B[0]=Wq_l; gb.C[0]=qy; gb.em[0]=4;
            gb.A[1]=xn; gb.B[1]=Wk_l; gb.C[1]=kx; gb.em[1]=3;
            gb.A[2]=xn; gb.B[2]=Wv_l; gb.C[2]=vx; gb.em[2]=3;
            gb.A[3]=yn; gb.B[3]=Wq_l; gb.C[3]=qx; gb.em[3]=4;
            gb.A[4]=yn; gb.B[4]=Wk_l; gb.C[4]=ky; gb.em[4]=3;
            gb.A[5]=yn; gb.B[5]=Wv_l; gb.C[5]=vy; gb.em[5]=3;
            dim3 grid(DD/TBN, NTOK/TBM, 6);
            gemm_tc_kernel<<<grid, 128>>>(gb, NTOK, DD, DD);
        }

        attn_kernel<<<attnG, 256>>>();

        {
            GemmBatch gb = {};
            gb.A[0]=o1; gb.B[0]=Wox_l; gb.bias[0]=box_l; gb.res[0]=X; gb.C[0]=X; gb.em[0]=1;
            gb.A[1]=o2; gb.B[1]=Woy_l; gb.bias[1]=boy_l; gb.res[1]=Y; gb.C[1]=Y; gb.em[1]=1;
            dim3 grid(DD/TBN, NTOK/TBM, 2);
            gemm_tc_kernel<<<grid, 128>>>(gb, NTOK, DD, DD);
        }

        ln_kernel<<<2*NTOK, 128>>>(X, Y, xn, yn,
                                   l2xg + l*DD, l2xb + l*DD,
                                   l2yg + l*DD, l2yb + l*DD);

        {
            GemmBatch gb = {};
            gb.A[0]=xn; gb.B[0]=fxw1 + (size_t)l*DD*FF; gb.bias[0]=fxb1 + l*FF; gb.C[0]=hx; gb.em[0]=2;
            gb.A[1]=yn; gb.B[1]=fyw1 + (size_t)l*DD*FF; gb.bias[1]=fyb1 + l*FF; gb.C[1]=hy; gb.em[1]=2;
            dim3 grid(FF/TBN, NTOK/TBM, 2);
            gemm_tc_kernel<<<grid, 128>>>(gb, NTOK, FF, DD);
        }
        {
            GemmBatch gb = {};
            gb.A[0]=hx; gb.B[0]=fxw2 + (size_t)l*FF*DD; gb.bias[0]=fxb2 + l*DD; gb.res[0]=X; gb.C[0]=X; gb.em[0]=1;
            gb.A[1]=hy; gb.B[1]=fyw2 + (size_t)l*FF*DD; gb.bias[1]=fyb2 + l*DD; gb.res[1]=Y; gb.C[1]=Y; gb.em[1]=1;
            dim3 grid(DD/TBN, NTOK/TBM, 2);
            gemm_tc_kernel<<<grid, 128>>>(gb, NTOK, DD, FF);
        }
    }
}

// round 9
// speedup vs baseline: 2.9573x; 1.1144x over previous
#include <cuda_runtime.h>
#include <math.h>

#define BT   8
#define TT   1024
#define DD   128
#define HH   8
#define DHH  16
#define FF   256
#define NTOK (BT*TT)   /* 8192 rows */

// ---------------- scratch (device globals; no allocation allowed) ----------
__device__ unsigned g_xn[NTOK*DD];     // LN out, tf32 bits
__device__ unsigned g_yn[NTOK*DD];
__device__ unsigned g_qx[NTOK*DD];     // tf32 bits (pre-scaled 0.125)
__device__ unsigned g_kx[NTOK*DD];
__device__ unsigned g_vx[NTOK*DD];
__device__ unsigned g_qy[NTOK*DD];
__device__ unsigned g_ky[NTOK*DD];
__device__ unsigned g_vy[NTOK*DD];
__device__ unsigned g_o1[NTOK*DD];     // attention out, tf32 bits
__device__ unsigned g_o2[NTOK*DD];
__device__ unsigned g_hx[NTOK*FF];     // FFN hidden, tf32 bits
__device__ unsigned g_hy[NTOK*FF];
// converted weights (tf32 bits), both layers
__device__ unsigned g_cwq [2*DD*DD];
__device__ unsigned g_cwk [2*DD*DD];
__device__ unsigned g_cwv [2*DD*DD];
__device__ unsigned g_cwox[2*DD*DD];
__device__ unsigned g_cwoy[2*DD*DD];
__device__ unsigned g_cfx1[2*DD*FF];
__device__ unsigned g_cfy1[2*DD*FF];
__device__ unsigned g_cfx2[2*FF*DD];
__device__ unsigned g_cfy2[2*FF*DD];

// ---------------- helpers ---------------------------------------------------
__device__ __forceinline__ unsigned cvt_tf32(float f) {
    unsigned u;
    asm("cvt.rna.tf32.f32 %0, %1;" : "=r"(u) : "f"(f));
    return u;
}
__device__ __forceinline__ void mma_tf32(float* c,
    unsigned a0, unsigned a1, unsigned a2, unsigned a3,
    unsigned b0, unsigned b1)
{
    asm("mma.sync.aligned.m16n8k8.row.col.f32.tf32.tf32.f32 "
        "{%0,%1,%2,%3}, {%4,%5,%6,%7}, {%8,%9}, {%0,%1,%2,%3};"
        : "+f"(c[0]), "+f"(c[1]), "+f"(c[2]), "+f"(c[3])
        : "r"(a0), "r"(a1), "r"(a2), "r"(a3), "r"(b0), "r"(b1));
}
__device__ __forceinline__ void cp16(unsigned saddr, const void* g) {
    asm volatile("cp.async.cg.shared.global [%0], [%1], 16;" :: "r"(saddr), "l"(g));
}
#define CP_COMMIT() asm volatile("cp.async.commit_group;")
#define CP_WAIT(N)  asm volatile("cp.async.wait_group %0;" :: "n"(N))

// ---------------- weight pre-conversion ------------------------------------
struct CvtBatch {
    const float* src[9];
    unsigned*    dst[9];
    int          n[9];
};
__global__ void cvt_kernel(CvtBatch cb)
{
    int z = blockIdx.y;
    int n = cb.n[z];
    const float4* s = (const float4*)cb.src[z];
    uint4* d = (uint4*)cb.dst[z];
    int i = blockIdx.x * blockDim.x + threadIdx.x;
    if (i*4 < n) {
        float4 v = s[i];
        d[i] = make_uint4(cvt_tf32(v.x), cvt_tf32(v.y), cvt_tf32(v.z), cvt_tf32(v.w));
    }
}

// ---------------- fused layernorm (both streams, tf32-bit output) ----------
__global__ void ln_kernel(const float* __restrict__ xs, const float* __restrict__ ys,
                          unsigned* __restrict__ xd, unsigned* __restrict__ yd,
                          const float* __restrict__ gx, const float* __restrict__ bx,
                          const float* __restrict__ gy, const float* __restrict__ by)
{
    int row = blockIdx.x;
    bool second = row >= NTOK;
    int r = second ? row - NTOK : row;
    const float* src = second ? ys : xs;
    unsigned*    dst = second ? yd : xd;
    const float* g   = second ? gy : gx;
    const float* b   = second ? by : bx;

    int t = threadIdx.x;
    float v = src[(size_t)r*DD + t];
    float s = v, s2 = v*v;
    #pragma unroll
    for (int o = 16; o; o >>= 1) {
        s  += __shfl_xor_sync(0xffffffffu, s , o);
        s2 += __shfl_xor_sync(0xffffffffu, s2, o);
    }
    __shared__ float ss[4], ss2[4];
    int w = t >> 5;
    if ((t & 31) == 0) { ss[w] = s; ss2[w] = s2; }
    __syncthreads();
    s  = ss[0]+ss[1]+ss[2]+ss[3];
    s2 = ss2[0]+ss2[1]+ss2[2]+ss2[3];
    float mean = s * (1.0f/DD);
    float var  = s2 * (1.0f/DD) - mean*mean;
    float inv  = rsqrtf(var + 1e-5f);
    dst[(size_t)r*DD + t] = cvt_tf32((v - mean) * inv * g[t] + b[t]);
}

// ---------------- batched tf32 GEMM, cp.async double-buffered --------------
// A, B are tf32 BITS. 64x64 tile, BK=32, 128 threads (4 warps 2x2).
// em: 1 = fp32 res+bias out ; 2 = gelu(acc+bias) -> tf32 bits
//     3 = tf32 bits ; 4 = tf32 bits * 0.125
#define TBM 64
#define TBN 64
#define TBK 32
#define APAD 36
#define BPAD 72

struct GemmBatch {
    const unsigned* A[6];
    const unsigned* B[6];
    const float*    bias[6];
    const float*    res[6];
    void*           C[6];
    int             em[6];
};

__global__ void __launch_bounds__(128)
gemm_tc_kernel(GemmBatch g, int M, int N, int K)
{
    const int z = blockIdx.z;
    const unsigned* __restrict__ A    = g.A[z];
    const unsigned* __restrict__ B    = g.B[z];
    const float*    __restrict__ bias = g.bias[z];
    const float*    __restrict__ res  = g.res[z];
    const int mode = g.em[z];

    __shared__ unsigned As[2][TBM][APAD];
    __shared__ unsigned Bs[2][TBK][BPAD];

    int bn = blockIdx.x * TBN;
    int bm = blockIdx.y * TBM;
    int tid  = threadIdx.x;
    int w    = tid >> 5;
    int lane = tid & 31;
    int gq   = lane >> 2;
    int qq   = lane & 3;
    int wm   = (w & 1) * 32;
    int wn   = (w >> 1) * 32;

    // loader chunk coords (4 chunks each for A and B)
    unsigned sA[4], sB[4];
    int ar[4], ac[4], br_[4], bc[4];
    #pragma unroll
    for (int it = 0; it < 4; it++) {
        int e = tid + it*128;
        ar[it] = e >> 3;  ac[it] = (e & 7) * 4;
        br_[it] = e >> 4; bc[it] = (e & 15) * 4;
        sA[it] = (unsigned)__cvta_generic_to_shared(&As[0][ar[it]][ac[it]]);
        sB[it] = (unsigned)__cvta_generic_to_shared(&Bs[0][br_[it]][bc[it]]);
    }
    const unsigned bufA = sizeof(unsigned)*TBM*APAD;
    const unsigned bufB = sizeof(unsigned)*TBK*BPAD;

    float c[2][4][4];
    #pragma unroll
    for (int mi = 0; mi < 2; mi++)
        #pragma unroll
        for (int ni = 0; ni < 4; ni++)
            #pragma unroll
            for (int r = 0; r < 4; r++) c[mi][ni][r] = 0.f;

    int nk = K / TBK;
    // prefetch tile 0 into buf 0
    #pragma unroll
    for (int it = 0; it < 4; it++) {
        cp16(sA[it], &A[(size_t)(bm + ar[it])*K + ac[it]]);
        cp16(sB[it], &B[(size_t)br_[it]*N + bn + bc[it]]);
    }
    CP_COMMIT();

    for (int kt = 0; kt < nk; kt++) {
        int buf = kt & 1;
        if (kt + 1 < nk) {
            int k0 = (kt + 1) * TBK;
            unsigned off = (buf ^ 1) ? bufA : 0u;
            unsigned offB = (buf ^ 1) ? bufB : 0u;
            #pragma unroll
            for (int it = 0; it < 4; it++) {
                cp16(sA[it] + off,  &A[(size_t)(bm + ar[it])*K + k0 + ac[it]]);
                cp16(sB[it] + offB, &B[(size_t)(k0 + br_[it])*N + bn + bc[it]]);
            }
            CP_COMMIT();
            CP_WAIT(1);
        } else {
            CP_WAIT(0);
        }
        __syncthreads();

        #pragma unroll
        for (int kc = 0; kc < TBK/8; kc++) {
            unsigned a[2][4], bf[4][2];
            #pragma unroll
            for (int mi = 0; mi < 2; mi++) {
                int m0 = wm + mi*16;
                a[mi][0] = As[buf][m0 + gq    ][kc*8 + qq];
                a[mi][1] = As[buf][m0 + gq + 8][kc*8 + qq];
                a[mi][2] = As[buf][m0 + gq    ][kc*8 + qq + 4];
                a[mi][3] = As[buf][m0 + gq + 8][kc*8 + qq + 4];
            }
            #pragma unroll
            for (int ni = 0; ni < 4; ni++) {
                bf[ni][0] = Bs[buf][kc*8 + qq    ][wn + ni*8 + gq];
                bf[ni][1] = Bs[buf][kc*8 + qq + 4][wn + ni*8 + gq];
            }
            #pragma unroll
            for (int mi = 0; mi < 2; mi++)
                #pragma unroll
                for (int ni = 0; ni < 4; ni++)
                    mma_tf32(c[mi][ni], a[mi][0], a[mi][1], a[mi][2], a[mi][3],
                             bf[ni][0], bf[ni][1]);
        }
        __syncthreads();
    }

    #pragma unroll
    for (int mi = 0; mi < 2; mi++) {
        int r0 = bm + wm + mi*16 + gq;
        int r1 = r0 + 8;
        #pragma unroll
        for (int ni = 0; ni < 4; ni++) {
            int n0 = bn + wn + ni*8 + 2*qq;
            float v0 = c[mi][ni][0], v1 = c[mi][ni][1];
            float v2 = c[mi][ni][2], v3 = c[mi][ni][3];
            if (mode == 1) {
                float b0 = bias[n0], b1 = bias[n0+1];
                float* Cf = (float*)g.C[z];
                v0 += b0 + res[(size_t)r0*N + n0];
                v1 += b1 + res[(size_t)r0*N + n0+1];
                v2 += b0 + res[(size_t)r1*N + n0];
                v3 += b1 + res[(size_t)r1*N + n0+1];
                *(float2*)&Cf[(size_t)r0*N + n0] = make_float2(v0, v1);
                *(float2*)&Cf[(size_t)r1*N + n0] = make_float2(v2, v3);
            } else if (mode == 2) {
                float b0 = bias[n0], b1 = bias[n0+1];
                v0 += b0; v1 += b1; v2 += b0; v3 += b1;
                v0 = 0.5f * v0 * (1.0f + erff(v0 * 0.70710678118654752f));
                v1 = 0.5f * v1 * (1.0f + erff(v1 * 0.70710678118654752f));
                v2 = 0.5f * v2 * (1.0f + erff(v2 * 0.70710678118654752f));
                v3 = 0.5f * v3 * (1.0f + erff(v3 * 0.70710678118654752f));
                unsigned* Cu = (unsigned*)g.C[z];
                *(uint2*)&Cu[(size_t)r0*N + n0] = make_uint2(cvt_tf32(v0), cvt_tf32(v1));
                *(uint2*)&Cu[(size_t)r1*N + n0] = make_uint2(cvt_tf32(v2), cvt_tf32(v3));
            } else {
                float sc = (mode == 4) ? 0.125f : 1.0f;
                unsigned* Cu = (unsigned*)g.C[z];
                *(uint2*)&Cu[(size_t)r0*N + n0] = make_uint2(cvt_tf32(v0*sc), cvt_tf32(v1*sc));
                *(uint2*)&Cu[(size_t)r1*N + n0] = make_uint2(cvt_tf32(v2*sc), cvt_tf32(v3*sc));
            }
        }
    }
}

// ---------------- tensor-core dual-branch flash attention (tf32) -----------
// Q/K/V as tf32 bits (Q pre-scaled 0.125). 8 warps, 128 q/block.
// cp.async double-buffered K/V tiles; P re-layout via intra-quad shuffles.
#define KPAD 36
__global__ void __launch_bounds__(256)
attn_kernel()
{
    __shared__ unsigned Ks[2][64][KPAD];
    __shared__ unsigned Vs[2][64][KPAD];

    int bh = blockIdx.x;
    int b  = bh >> 3;
    int h  = bh & 7;
    int tid  = threadIdx.x;
    int w    = tid >> 5;
    int lane = tid & 31;
    int gq   = lane >> 2;
    int qq   = lane & 3;

    int tok0 = b*TT + blockIdx.y*128 + w*16;
    int r0 = tok0 + gq;
    int r1 = r0 + 8;

    unsigned qa[4][4];
    #pragma unroll
    for (int kc = 0; kc < 4; kc++) {
        const unsigned* src = (kc < 2) ? g_qx : g_qy;
        int d0 = (kc & 1)*8 + qq;
        qa[kc][0] = src[(size_t)r0*DD + h*DHH + d0];
        qa[kc][1] = src[(size_t)r1*DD + h*DHH + d0];
        qa[kc][2] = src[(size_t)r0*DD + h*DHH + d0 + 4];
        qa[kc][3] = src[(size_t)r1*DD + h*DHH + d0 + 4];
    }

    // loader coords: 2 chunks each for K and V
    int lrow[2], lc4[2], ldd[2];
    const unsigned* lks[2];
    const unsigned* lvs[2];
    unsigned sK[2], sV[2];
    #pragma unroll
    for (int it = 0; it < 2; it++) {
        int e = tid + it*256;
        lrow[it] = e >> 3;
        lc4[it]  = (e & 7) * 4;
        ldd[it]  = lc4[it] & 15;
        lks[it] = (lc4[it] < 16) ? g_kx : g_ky;
        lvs[it] = (lc4[it] < 16) ? g_vx : g_vy;
        sK[it] = (unsigned)__cvta_generic_to_shared(&Ks[0][lrow[it]][lc4[it]]);
        sV[it] = (unsigned)__cvta_generic_to_shared(&Vs[0][lrow[it]][lc4[it]]);
    }
    const unsigned bufO = sizeof(unsigned)*64*KPAD;

    float o[4][4];
    #pragma unroll
    for (int j = 0; j < 4; j++)
        #pragma unroll
        for (int cc = 0; cc < 4; cc++) o[j][cc] = 0.f;
    float l0 = 0.f, l1 = 0.f;

    int srcA = 4*gq + (qq >> 1);
    int srcB = srcA + 2;
    bool odd = qq & 1;

    // prefetch tile 0
    #pragma unroll
    for (int it = 0; it < 2; it++) {
        int tokk = b*TT + lrow[it];
        cp16(sK[it], &lks[it][(size_t)tokk*DD + h*DHH + ldd[it]]);
        cp16(sV[it], &lvs[it][(size_t)tokk*DD + h*DHH + ldd[it]]);
    }
    CP_COMMIT();

    for (int kt = 0; kt < TT/64; kt++) {
        int buf = kt & 1;
        if (kt + 1 < TT/64) {
            unsigned off = (buf ^ 1) ? bufO : 0u;
            #pragma unroll
            for (int it = 0; it < 2; it++) {
                int tokk = b*TT + (kt+1)*64 + lrow[it];
                cp16(sK[it] + off, &lks[it][(size_t)tokk*DD + h*DHH + ldd[it]]);
                cp16(sV[it] + off, &lvs[it][(size_t)tokk*DD + h*DHH + ldd[it]]);
            }
            CP_COMMIT();
            CP_WAIT(1);
        } else {
            CP_WAIT(0);
        }
        __syncthreads();

        float rs0 = 0.f, rs1 = 0.f;
        #pragma unroll
        for (int j = 0; j < 8; j++) {
            float sc[4] = {0.f, 0.f, 0.f, 0.f};
            #pragma unroll
            for (int kc = 0; kc < 4; kc++) {
                unsigned b0 = Ks[buf][j*8 + gq][kc*8 + qq];
                unsigned b1 = Ks[buf][j*8 + gq][kc*8 + qq + 4];
                mma_tf32(sc, qa[kc][0], qa[kc][1], qa[kc][2], qa[kc][3], b0, b1);
            }
            float p0 = __expf(sc[0]);
            float p1 = __expf(sc[1]);
            float p2 = __expf(sc[2]);
            float p3 = __expf(sc[3]);
            rs0 += p0 + p1;
            rs1 += p2 + p3;
            unsigned pb0 = cvt_tf32(p0);
            unsigned pb1 = cvt_tf32(p1);
            unsigned pb2 = cvt_tf32(p2);
            unsigned pb3 = cvt_tf32(p3);
            unsigned e0 = __shfl_sync(0xffffffffu, pb0, srcA);
            unsigned e1 = __shfl_sync(0xffffffffu, pb1, srcA);
            unsigned f2 = __shfl_sync(0xffffffffu, pb2, srcA);
            unsigned f3 = __shfl_sync(0xffffffffu, pb3, srcA);
            unsigned g0 = __shfl_sync(0xffffffffu, pb0, srcB);
            unsigned g1 = __shfl_sync(0xffffffffu, pb1, srcB);
            unsigned h2 = __shfl_sync(0xffffffffu, pb2, srcB);
            unsigned h3 = __shfl_sync(0xffffffffu, pb3, srcB);
            unsigned a0 = odd ? e1 : e0;
            unsigned a1 = odd ? f3 : f2;
            unsigned a2 = odd ? g1 : g0;
            unsigned a3 = odd ? h3 : h2;
            #pragma unroll
            for (int jv = 0; jv < 4; jv++) {
                unsigned b0 = Vs[buf][8*j + qq    ][8*jv + gq];
                unsigned b1 = Vs[buf][8*j + qq + 4][8*jv + gq];
                mma_tf32(o[jv], a0, a1, a2, a3, b0, b1);
            }
        }
        rs0 += __shfl_xor_sync(0xffffffffu, rs0, 1);
        rs0 += __shfl_xor_sync(0xffffffffu, rs0, 2);
        rs1 += __shfl_xor_sync(0xffffffffu, rs1, 1);
        rs1 += __shfl_xor_sync(0xffffffffu, rs1, 2);
        l0 += rs0;
        l1 += rs1;
        __syncthreads();
    }

    float inv0 = 1.f / l0;
    float inv1 = 1.f / l1;
    #pragma unroll
    for (int j = 0; j < 4; j++) {
        unsigned* dst = (j < 2) ? g_o1 : g_o2;
        int dbase = h*DHH + (j & 1)*8 + 2*qq;
        *(uint2*)&dst[(size_t)r0*DD + dbase] =
            make_uint2(cvt_tf32(o[j][0]*inv0), cvt_tf32(o[j][1]*inv0));
        *(uint2*)&dst[(size_t)r1*DD + dbase] =
            make_uint2(cvt_tf32(o[j][2]*inv1), cvt_tf32(o[j][3]*inv1));
    }
}

// ---------------- host launcher --------------------------------------------
template <typename T>
static T* symaddr(const T& s) {
    void* p = nullptr;
    cudaGetSymbolAddress(&p, s);
    return (T*)p;
}
template <typename T, size_t N>
static T* symaddr(const T (&s)[N]) {
    void* p = nullptr;
    cudaGetSymbolAddress(&p, s);
    return (T*)p;
}

extern "C" void kernel_launch(void* const* d_in, const int* in_sizes, int n_in,
                              void* d_out, int out_size)
{
    const float* x_in  = (const float*)d_in[0];
    const float* y_in  = (const float*)d_in[1];
    const float* Wq    = (const float*)d_in[2];
    const float* Wk    = (const float*)d_in[3];
    const float* Wv    = (const float*)d_in[4];
    const float* Wox   = (const float*)d_in[5];
    const float* box   = (const float*)d_in[6];
    const float* Woy   = (const float*)d_in[7];
    const float* boy   = (const float*)d_in[8];
    const float* l1xg  = (const float*)d_in[9];
    const float* l1xb  = (const float*)d_in[10];
    const float* l1yg  = (const float*)d_in[11];
    const float* l1yb  = (const float*)d_in[12];
    const float* l2xg  = (const float*)d_in[13];
    const float* l2xb  = (const float*)d_in[14];
    const float* l2yg  = (const float*)d_in[15];
    const float* l2yb  = (const float*)d_in[16];
    const float* fxw1  = (const float*)d_in[17];
    const float* fxb1  = (const float*)d_in[18];
    const float* fxw2  = (const float*)d_in[19];
    const float* fxb2  = (const float*)d_in[20];
    const float* fyw1  = (const float*)d_in[21];
    const float* fyb1  = (const float*)d_in[22];
    const float* fyw2  = (const float*)d_in[23];
    const float* fyb2  = (const float*)d_in[24];

    float* X = (float*)d_out;
    float* Y = X + (size_t)NTOK*DD;

    unsigned* xn = symaddr(g_xn); unsigned* yn = symaddr(g_yn);
    unsigned* o1 = symaddr(g_o1); unsigned* o2 = symaddr(g_o2);
    unsigned* qx = symaddr(g_qx); unsigned* kx = symaddr(g_kx); unsigned* vx = symaddr(g_vx);
    unsigned* qy = symaddr(g_qy); unsigned* ky = symaddr(g_ky); unsigned* vy = symaddr(g_vy);
    unsigned* hx = symaddr(g_hx); unsigned* hy = symaddr(g_hy);
    unsigned* cwq = symaddr(g_cwq); unsigned* cwk = symaddr(g_cwk);
    unsigned* cwv = symaddr(g_cwv); unsigned* cwox = symaddr(g_cwox);
    unsigned* cwoy = symaddr(g_cwoy);
    unsigned* cfx1 = symaddr(g_cfx1); unsigned* cfy1 = symaddr(g_cfy1);
    unsigned* cfx2 = symaddr(g_cfx2); unsigned* cfy2 = symaddr(g_cfy2);

    size_t bytes = (size_t)NTOK*DD*sizeof(float);
    cudaMemcpyAsync(X, x_in, bytes, cudaMemcpyDeviceToDevice);
    cudaMemcpyAsync(Y, y_in, bytes, cudaMemcpyDeviceToDevice);

    // weight pre-conversion (all layers at once)
    {
        CvtBatch cb = {};
        cb.src[0]=Wq;   cb.dst[0]=cwq;  cb.n[0]=2*DD*DD;
        cb.src[1]=Wk;   cb.dst[1]=cwk;  cb.n[1]=2*DD*DD;
        cb.src[2]=Wv;   cb.dst[2]=cwv;  cb.n[2]=2*DD*DD;
        cb.src[3]=Wox;  cb.dst[3]=cwox; cb.n[3]=2*DD*DD;
        cb.src[4]=Woy;  cb.dst[4]=cwoy; cb.n[4]=2*DD*DD;
        cb.src[5]=fxw1; cb.dst[5]=cfx1; cb.n[5]=2*DD*FF;
        cb.src[6]=fyw1; cb.dst[6]=cfy1; cb.n[6]=2*DD*FF;
        cb.src[7]=fxw2; cb.dst[7]=cfx2; cb.n[7]=2*FF*DD;
        cb.src[8]=fyw2; cb.dst[8]=cfy2; cb.n[8]=2*FF*DD;
        dim3 grid(64, 9);
        cvt_kernel<<<grid, 256>>>(cb);
    }

    dim3 attnG(BT*HH, TT/128);

    for (int l = 0; l < 2; l++) {
        const unsigned* Wq_l  = cwq  + (size_t)l*DD*DD;
        const unsigned* Wk_l  = cwk  + (size_t)l*DD*DD;
        const unsigned* Wv_l  = cwv  + (size_t)l*DD*DD;
        const unsigned* Wox_l = cwox + (size_t)l*DD*DD;
        const unsigned* Woy_l = cwoy + (size_t)l*DD*DD;
        const float* box_l = box + (size_t)l*DD;
        const float* boy_l = boy + (size_t)l*DD;

        ln_kernel<<<2*NTOK, 128>>>(X, Y, xn, yn,
                                   l1xg + l*DD, l1xb + l*DD,
                                   l1yg + l*DD, l1yb + l*DD);

        {
            GemmBatch gb = {};
            gb.A[0]=xn; gb.B[0]=Wq_l; gb.C[0]=qy; gb.em[0]=4;
            gb.A[1]=xn; gb.B[1]=Wk_l; gb.C[1]=kx; gb.em[1]=3;
            gb.A[2]=xn; gb.B[2]=Wv_l; gb.C[2]=vx; gb.em[2]=3;
            gb.A[3]=yn; gb.B[3]=Wq_l; gb.C[3]=qx; gb.em[3]=4;
            gb.A[4]=yn; gb.B[4]=Wk_l; gb.C[4]=ky; gb.em[4]=3;
            gb.A[5]=yn; gb.B[5]=Wv_l; gb.C[5]=vy; gb.em[5]=3;
            dim3 grid(DD/TBN, NTOK/TBM, 6);
            gemm_tc_kernel<<<grid, 128>>>(gb, NTOK, DD, DD);
        }

        attn_kernel<<<attnG, 256>>>();

        {
            GemmBatch gb = {};
            gb.A[0]=o1; gb.B[0]=Wox_l; gb.bias[0]=box_l; gb.res[0]=X; gb.C[0]=X; gb.em[0]=1;
            gb.A[1]=o2; gb.B[1]=Woy_l; gb.bias[1]=boy_l; gb.res[1]=Y; gb.C[1]=Y; gb.em[1]=1;
            dim3 grid(DD/TBN, NTOK/TBM, 2);
            gemm_tc_kernel<<<grid, 128>>>(gb, NTOK, DD, DD);
        }

        ln_kernel<<<2*NTOK, 128>>>(X, Y, xn, yn,
                                   l2xg + l*DD, l2xb + l*DD,
                                   l2yg + l*DD, l2yb + l*DD);

        {
            GemmBatch gb = {};
            gb.A[0]=xn; gb.B[0]=cfx1 + (size_t)l*DD*FF; gb.bias[0]=fxb1 + l*FF; gb.C[0]=hx; gb.em[0]=2;
            gb.A[1]=yn; gb.B[1]=cfy1 + (size_t)l*DD*FF; gb.bias[1]=fyb1 + l*FF; gb.C[1]=hy; gb.em[1]=2;
            dim3 grid(FF/TBN, NTOK/TBM, 2);
            gemm_tc_kernel<<<grid, 128>>>(gb, NTOK, FF, DD);
        }
        {
            GemmBatch gb = {};
            gb.A[0]=hx; gb.B[0]=cfx2 + (size_t)l*FF*DD; gb.bias[0]=fxb2 + l*DD; gb.res[0]=X; gb.C[0]=X; gb.em[0]=1;
            gb.A[1]=hy; gb.B[1]=cfy2 + (size_t)l*FF*DD; gb.bias[1]=fyb2 + l*DD; gb.res[1]=Y; gb.C[1]=Y; gb.em[1]=1;
            dim3 grid(DD/TBN, NTOK/TBM, 2);
            gemm_tc_kernel<<<grid, 128>>>(gb, NTOK, DD, FF);
        }
    }
}

// round 12
// speedup vs baseline: 3.1474x; 1.0643x over previous
#include <cuda_runtime.h>
#include <math.h>

#define BT   8
#define TT   1024
#define DD   128
#define HH   8
#define DHH  16
#define FF   256
#define NTOK (BT*TT)   /* 8192 rows */

// ---------------- scratch (device globals; no allocation allowed) ----------
__device__ unsigned g_xn[NTOK*DD];     // LN out, tf32 bits
__device__ unsigned g_yn[NTOK*DD];
__device__ unsigned g_qx[NTOK*DD];     // tf32 bits (pre-scaled 0.125)
__device__ unsigned g_kx[NTOK*DD];
__device__ unsigned g_vx[NTOK*DD];
__device__ unsigned g_qy[NTOK*DD];
__device__ unsigned g_ky[NTOK*DD];
__device__ unsigned g_vy[NTOK*DD];
__device__ unsigned g_o1[NTOK*DD];     // attention out, tf32 bits
__device__ unsigned g_o2[NTOK*DD];
__device__ unsigned g_hx[NTOK*FF];     // FFN hidden, tf32 bits
__device__ unsigned g_hy[NTOK*FF];
// converted weights (tf32 bits), both layers
__device__ unsigned g_cwq [2*DD*DD];
__device__ unsigned g_cwk [2*DD*DD];
__device__ unsigned g_cwv [2*DD*DD];
__device__ unsigned g_cwox[2*DD*DD];
__device__ unsigned g_cwoy[2*DD*DD];
__device__ unsigned g_cfx1[2*DD*FF];
__device__ unsigned g_cfy1[2*DD*FF];
__device__ unsigned g_cfx2[2*FF*DD];
__device__ unsigned g_cfy2[2*FF*DD];

// ---------------- helpers ---------------------------------------------------
__device__ __forceinline__ unsigned cvt_tf32(float f) {
    unsigned u;
    asm("cvt.rna.tf32.f32 %0, %1;" : "=r"(u) : "f"(f));
    return u;
}
__device__ __forceinline__ void mma_tf32(float* c,
    unsigned a0, unsigned a1, unsigned a2, unsigned a3,
    unsigned b0, unsigned b1)
{
    asm("mma.sync.aligned.m16n8k8.row.col.f32.tf32.tf32.f32 "
        "{%0,%1,%2,%3}, {%4,%5,%6,%7}, {%8,%9}, {%0,%1,%2,%3};"
        : "+f"(c[0]), "+f"(c[1]), "+f"(c[2]), "+f"(c[3])
        : "r"(a0), "r"(a1), "r"(a2), "r"(a3), "r"(b0), "r"(b1));
}
__device__ __forceinline__ void cp16(unsigned saddr, const void* g) {
    asm volatile("cp.async.cg.shared.global [%0], [%1], 16;" :: "r"(saddr), "l"(g));
}
#define CP_COMMIT() asm volatile("cp.async.commit_group;")
#define CP_WAIT(N)  asm volatile("cp.async.wait_group %0;" :: "n"(N))

// ---------------- weight pre-conversion ------------------------------------
struct CvtBatch {
    const float* src[9];
    unsigned*    dst[9];
    int          n[9];
};
__global__ void cvt_kernel(CvtBatch cb)
{
    int z = blockIdx.y;
    int n = cb.n[z];
    const float4* s = (const float4*)cb.src[z];
    uint4* d = (uint4*)cb.dst[z];
    int i = blockIdx.x * blockDim.x + threadIdx.x;
    if (i*4 < n) {
        float4 v = s[i];
        d[i] = make_uint4(cvt_tf32(v.x), cvt_tf32(v.y), cvt_tf32(v.z), cvt_tf32(v.w));
    }
}

// ---------------- fused layernorm (both streams, tf32-bit output) ----------
__global__ void ln_kernel(const float* __restrict__ xs, const float* __restrict__ ys,
                          unsigned* __restrict__ xd, unsigned* __restrict__ yd,
                          const float* __restrict__ gx, const float* __restrict__ bx,
                          const float* __restrict__ gy, const float* __restrict__ by)
{
    int row = blockIdx.x;
    bool second = row >= NTOK;
    int r = second ? row - NTOK : row;
    const float* src = second ? ys : xs;
    unsigned*    dst = second ? yd : xd;
    const float* g   = second ? gy : gx;
    const float* b   = second ? by : bx;

    int t = threadIdx.x;
    float v = src[(size_t)r*DD + t];
    float s = v, s2 = v*v;
    #pragma unroll
    for (int o = 16; o; o >>= 1) {
        s  += __shfl_xor_sync(0xffffffffu, s , o);
        s2 += __shfl_xor_sync(0xffffffffu, s2, o);
    }
    __shared__ float ss[4], ss2[4];
    int w = t >> 5;
    if ((t & 31) == 0) { ss[w] = s; ss2[w] = s2; }
    __syncthreads();
    s  = ss[0]+ss[1]+ss[2]+ss[3];
    s2 = ss2[0]+ss2[1]+ss2[2]+ss2[3];
    float mean = s * (1.0f/DD);
    float var  = s2 * (1.0f/DD) - mean*mean;
    float inv  = rsqrtf(var + 1e-5f);
    dst[(size_t)r*DD + t] = cvt_tf32((v - mean) * inv * g[t] + b[t]);
}

// ---------------- batched tf32 GEMM, cp.async double-buffered --------------
#define TBM 64
#define TBN 64
#define TBK 32
#define APAD 36
#define BPAD 72

struct GemmBatch {
    const unsigned* A[6];
    const unsigned* B[6];
    const float*    bias[6];
    const float*    res[6];
    void*           C[6];
    int             em[6];
};

__global__ void __launch_bounds__(128)
gemm_tc_kernel(GemmBatch g, int M, int N, int K)
{
    const int z = blockIdx.z;
    const unsigned* __restrict__ A    = g.A[z];
    const unsigned* __restrict__ B    = g.B[z];
    const float*    __restrict__ bias = g.bias[z];
    const float*    __restrict__ res  = g.res[z];
    const int mode = g.em[z];

    __shared__ unsigned As[2][TBM][APAD];
    __shared__ unsigned Bs[2][TBK][BPAD];

    int bn = blockIdx.x * TBN;
    int bm = blockIdx.y * TBM;
    int tid  = threadIdx.x;
    int w    = tid >> 5;
    int lane = tid & 31;
    int gq   = lane >> 2;
    int qq   = lane & 3;
    int wm   = (w & 1) * 32;
    int wn   = (w >> 1) * 32;

    unsigned sA[4], sB[4];
    int ar[4], ac[4], br_[4], bc[4];
    #pragma unroll
    for (int it = 0; it < 4; it++) {
        int e = tid + it*128;
        ar[it] = e >> 3;  ac[it] = (e & 7) * 4;
        br_[it] = e >> 4; bc[it] = (e & 15) * 4;
        sA[it] = (unsigned)__cvta_generic_to_shared(&As[0][ar[it]][ac[it]]);
        sB[it] = (unsigned)__cvta_generic_to_shared(&Bs[0][br_[it]][bc[it]]);
    }
    const unsigned bufA = sizeof(unsigned)*TBM*APAD;
    const unsigned bufB = sizeof(unsigned)*TBK*BPAD;

    float c[2][4][4];
    #pragma unroll
    for (int mi = 0; mi < 2; mi++)
        #pragma unroll
        for (int ni = 0; ni < 4; ni++)
            #pragma unroll
            for (int r = 0; r < 4; r++) c[mi][ni][r] = 0.f;

    int nk = K / TBK;
    #pragma unroll
    for (int it = 0; it < 4; it++) {
        cp16(sA[it], &A[(size_t)(bm + ar[it])*K + ac[it]]);
        cp16(sB[it], &B[(size_t)br_[it]*N + bn + bc[it]]);
    }
    CP_COMMIT();

    for (int kt = 0; kt < nk; kt++) {
        int buf = kt & 1;
        if (kt + 1 < nk) {
            int k0 = (kt + 1) * TBK;
            unsigned off = (buf ^ 1) ? bufA : 0u;
            unsigned offB = (buf ^ 1) ? bufB : 0u;
            #pragma unroll
            for (int it = 0; it < 4; it++) {
                cp16(sA[it] + off,  &A[(size_t)(bm + ar[it])*K + k0 + ac[it]]);
                cp16(sB[it] + offB, &B[(size_t)(k0 + br_[it])*N + bn + bc[it]]);
            }
            CP_COMMIT();
            CP_WAIT(1);
        } else {
            CP_WAIT(0);
        }
        __syncthreads();

        #pragma unroll
        for (int kc = 0; kc < TBK/8; kc++) {
            unsigned a[2][4], bf[4][2];
            #pragma unroll
            for (int mi = 0; mi < 2; mi++) {
                int m0 = wm + mi*16;
                a[mi][0] = As[buf][m0 + gq    ][kc*8 + qq];
                a[mi][1] = As[buf][m0 + gq + 8][kc*8 + qq];
                a[mi][2] = As[buf][m0 + gq    ][kc*8 + qq + 4];
                a[mi][3] = As[buf][m0 + gq + 8][kc*8 + qq + 4];
            }
            #pragma unroll
            for (int ni = 0; ni < 4; ni++) {
                bf[ni][0] = Bs[buf][kc*8 + qq    ][wn + ni*8 + gq];
                bf[ni][1] = Bs[buf][kc*8 + qq + 4][wn + ni*8 + gq];
            }
            #pragma unroll
            for (int mi = 0; mi < 2; mi++)
                #pragma unroll
                for (int ni = 0; ni < 4; ni++)
                    mma_tf32(c[mi][ni], a[mi][0], a[mi][1], a[mi][2], a[mi][3],
                             bf[ni][0], bf[ni][1]);
        }
        __syncthreads();
    }

    #pragma unroll
    for (int mi = 0; mi < 2; mi++) {
        int r0 = bm + wm + mi*16 + gq;
        int r1 = r0 + 8;
        #pragma unroll
        for (int ni = 0; ni < 4; ni++) {
            int n0 = bn + wn + ni*8 + 2*qq;
            float v0 = c[mi][ni][0], v1 = c[mi][ni][1];
            float v2 = c[mi][ni][2], v3 = c[mi][ni][3];
            if (mode == 1) {
                float b0 = bias[n0], b1 = bias[n0+1];
                float* Cf = (float*)g.C[z];
                v0 += b0 + res[(size_t)r0*N + n0];
                v1 += b1 + res[(size_t)r0*N + n0+1];
                v2 += b0 + res[(size_t)r1*N + n0];
                v3 += b1 + res[(size_t)r1*N + n0+1];
                *(float2*)&Cf[(size_t)r0*N + n0] = make_float2(v0, v1);
                *(float2*)&Cf[(size_t)r1*N + n0] = make_float2(v2, v3);
            } else if (mode == 2) {
                float b0 = bias[n0], b1 = bias[n0+1];
                v0 += b0; v1 += b1; v2 += b0; v3 += b1;
                v0 = 0.5f * v0 * (1.0f + erff(v0 * 0.70710678118654752f));
                v1 = 0.5f * v1 * (1.0f + erff(v1 * 0.70710678118654752f));
                v2 = 0.5f * v2 * (1.0f + erff(v2 * 0.70710678118654752f));
                v3 = 0.5f * v3 * (1.0f + erff(v3 * 0.70710678118654752f));
                unsigned* Cu = (unsigned*)g.C[z];
                *(uint2*)&Cu[(size_t)r0*N + n0] = make_uint2(cvt_tf32(v0), cvt_tf32(v1));
                *(uint2*)&Cu[(size_t)r1*N + n0] = make_uint2(cvt_tf32(v2), cvt_tf32(v3));
            } else {
                float sc = (mode == 4) ? 0.125f : 1.0f;
                unsigned* Cu = (unsigned*)g.C[z];
                *(uint2*)&Cu[(size_t)r0*N + n0] = make_uint2(cvt_tf32(v0*sc), cvt_tf32(v1*sc));
                *(uint2*)&Cu[(size_t)r1*N + n0] = make_uint2(cvt_tf32(v2*sc), cvt_tf32(v3*sc));
            }
        }
    }
}

// ---------------- tensor-core dual-branch flash attention (tf32) -----------
// Packed smem layouts:
//  Ks[r][qq*8 + kc*2 + half] = K[r][kc*8+qq+4*half]  -> b-frags via 2x LDS.128
//  Vq2[j*4+qq][d] = (V[8j+qq][d], V[8j+qq+4][d])     -> b-frags via 1x LDS.64
// K/V tiles register-prefetched (LDG next tile during compute, STS at tile top).
#define KPK 36
#define VPK 72    /* words per Vq row (32 uint2 + 4 pad) */
__global__ void __launch_bounds__(256)
attn_kernel()
{
    __shared__ unsigned Ks[64][KPK];
    __shared__ unsigned Vq[32][VPK];

    int bh = blockIdx.x;
    int b  = bh >> 3;
    int h  = bh & 7;
    int tid  = threadIdx.x;
    int w    = tid >> 5;
    int lane = tid & 31;
    int gq   = lane >> 2;
    int qq   = lane & 3;

    int tok0 = b*TT + blockIdx.y*128 + w*16;
    int r0 = tok0 + gq;
    int r1 = r0 + 8;

    // ---- Q fragments (tf32 bits, pre-scaled) ----
    unsigned qa[4][4];
    #pragma unroll
    for (int kc = 0; kc < 4; kc++) {
        const unsigned* src = (kc < 2) ? g_qx : g_qy;
        int d0 = (kc & 1)*8 + qq;
        qa[kc][0] = src[(size_t)r0*DD + h*DHH + d0];
        qa[kc][1] = src[(size_t)r1*DD + h*DHH + d0];
        qa[kc][2] = src[(size_t)r0*DD + h*DHH + d0 + 4];
        qa[kc][3] = src[(size_t)r1*DD + h*DHH + d0 + 4];
    }

    // ---- loader setup ----
    // K: 2 chunks/thread: chunk c = tid + it*256; row = c>>3; kc4 = (c&7)*4
    const unsigned* kptr[2];
    int krow[2], kcol[2];
    #pragma unroll
    for (int it = 0; it < 2; it++) {
        int c = tid + it*256;
        krow[it] = c >> 3;
        int kc4 = (c & 7) * 4;
        kptr[it] = ((kc4 < 16) ? g_kx : g_ky)
                 + (size_t)(b*TT + krow[it])*DD + h*DHH + (kc4 & 15);
        kcol[it] = (kc4 >> 3)*2 + ((kc4 >> 2) & 1);
    }
    // V: 1 chunk/thread: rp = tid>>3 (0..31), vc4 = (tid&7)*4
    int rp  = tid >> 3;
    int vc4 = (tid & 7) * 4;
    int vj = rp >> 2, vqq = rp & 3;
    const unsigned* vptr0 = ((vc4 < 16) ? g_vx : g_vy)
                          + (size_t)(b*TT + vj*8 + vqq)*DD + h*DHH + (vc4 & 15);
    const unsigned* vptr1 = vptr0 + 4*DD;

    float o[4][4];
    #pragma unroll
    for (int j = 0; j < 4; j++)
        #pragma unroll
        for (int cc = 0; cc < 4; cc++) o[j][cc] = 0.f;
    float l0 = 0.f, l1 = 0.f;

    int srcA = 4*gq + (qq >> 1);
    int srcB = srcA + 2;
    bool odd = qq & 1;

    // prefetch tile 0 into registers
    uint4 krg[2], vra, vrb;
    krg[0] = *(const uint4*)kptr[0];
    krg[1] = *(const uint4*)kptr[1];
    vra = *(const uint4*)vptr0;
    vrb = *(const uint4*)vptr1;

    for (int kt = 0; kt < TT/64; kt++) {
        __syncthreads();
        // store registers -> packed smem
        #pragma unroll
        for (int it = 0; it < 2; it++) {
            Ks[krow[it]][ 0 + kcol[it]] = krg[it].x;
            Ks[krow[it]][ 8 + kcol[it]] = krg[it].y;
            Ks[krow[it]][16 + kcol[it]] = krg[it].z;
            Ks[krow[it]][24 + kcol[it]] = krg[it].w;
        }
        *(uint4*)&Vq[rp][vc4*2    ] = make_uint4(vra.x, vrb.x, vra.y, vrb.y);
        *(uint4*)&Vq[rp][vc4*2 + 4] = make_uint4(vra.z, vrb.z, vra.w, vrb.w);
        __syncthreads();

        // prefetch next tile
        if (kt + 1 < TT/64) {
            size_t off = (size_t)(kt + 1)*64*DD;
            krg[0] = *(const uint4*)(kptr[0] + off);
            krg[1] = *(const uint4*)(kptr[1] + off);
            vra = *(const uint4*)(vptr0 + off);
            vrb = *(const uint4*)(vptr1 + off);
        }

        float rs0 = 0.f, rs1 = 0.f;
        #pragma unroll
        for (int j = 0; j < 8; j++) {
            // ---- S chunk: 16 q x 8 keys (K b-frags via 2 LDS.128) ----
            uint4 t0 = *(const uint4*)&Ks[j*8 + gq][qq*8];
            uint4 t1 = *(const uint4*)&Ks[j*8 + gq][qq*8 + 4];
            float sc[4] = {0.f, 0.f, 0.f, 0.f};
            mma_tf32(sc, qa[0][0], qa[0][1], qa[0][2], qa[0][3], t0.x, t0.y);
            mma_tf32(sc, qa[1][0], qa[1][1], qa[1][2], qa[1][3], t0.z, t0.w);
            mma_tf32(sc, qa[2][0], qa[2][1], qa[2][2], qa[2][3], t1.x, t1.y);
            mma_tf32(sc, qa[3][0], qa[3][1], qa[3][2], qa[3][3], t1.z, t1.w);

            float p0 = __expf(sc[0]);
            float p1 = __expf(sc[1]);
            float p2 = __expf(sc[2]);
            float p3 = __expf(sc[3]);
            rs0 += p0 + p1;
            rs1 += p2 + p3;
            unsigned pb0 = cvt_tf32(p0);
            unsigned pb1 = cvt_tf32(p1);
            unsigned pb2 = cvt_tf32(p2);
            unsigned pb3 = cvt_tf32(p3);
            unsigned e0 = __shfl_sync(0xffffffffu, pb0, srcA);
            unsigned e1 = __shfl_sync(0xffffffffu, pb1, srcA);
            unsigned f2 = __shfl_sync(0xffffffffu, pb2, srcA);
            unsigned f3 = __shfl_sync(0xffffffffu, pb3, srcA);
            unsigned g0 = __shfl_sync(0xffffffffu, pb0, srcB);
            unsigned g1 = __shfl_sync(0xffffffffu, pb1, srcB);
            unsigned h2 = __shfl_sync(0xffffffffu, pb2, srcB);
            unsigned h3 = __shfl_sync(0xffffffffu, pb3, srcB);
            unsigned a0 = odd ? e1 : e0;
            unsigned a1 = odd ? f3 : f2;
            unsigned a2 = odd ? g1 : g0;
            unsigned a3 = odd ? h3 : h2;
            // ---- O += P_j @ V_j (V b-frags via 1 LDS.64 each) ----
            #pragma unroll
            for (int jv = 0; jv < 4; jv++) {
                uint2 bb = *(const uint2*)&Vq[j*4 + qq][(8*jv + gq)*2];
                mma_tf32(o[jv], a0, a1, a2, a3, bb.x, bb.y);
            }
        }
        rs0 += __shfl_xor_sync(0xffffffffu, rs0, 1);
        rs0 += __shfl_xor_sync(0xffffffffu, rs0, 2);
        rs1 += __shfl_xor_sync(0xffffffffu, rs1, 1);
        rs1 += __shfl_xor_sync(0xffffffffu, rs1, 2);
        l0 += rs0;
        l1 += rs1;
    }

    float inv0 = 1.f / l0;
    float inv1 = 1.f / l1;
    #pragma unroll
    for (int j = 0; j < 4; j++) {
        unsigned* dst = (j < 2) ? g_o1 : g_o2;
        int dbase = h*DHH + (j & 1)*8 + 2*qq;
        *(uint2*)&dst[(size_t)r0*DD + dbase] =
            make_uint2(cvt_tf32(o[j][0]*inv0), cvt_tf32(o[j][1]*inv0));
        *(uint2*)&dst[(size_t)r1*DD + dbase] =
            make_uint2(cvt_tf32(o[j][2]*inv1), cvt_tf32(o[j][3]*inv1));
    }
}

// ---------------- host launcher --------------------------------------------
template <typename T>
static T* symaddr(const T& s) {
    void* p = nullptr;
    cudaGetSymbolAddress(&p, s);
    return (T*)p;
}
template <typename T, size_t N>
static T* symaddr(const T (&s)[N]) {
    void* p = nullptr;
    cudaGetSymbolAddress(&p, s);
    return (T*)p;
}

extern "C" void kernel_launch(void* const* d_in, const int* in_sizes, int n_in,
                              void* d_out, int out_size)
{
    const float* x_in  = (const float*)d_in[0];
    const float* y_in  = (const float*)d_in[1];
    const float* Wq    = (const float*)d_in[2];
    const float* Wk    = (const float*)d_in[3];
    const float* Wv    = (const float*)d_in[4];
    const float* Wox   = (const float*)d_in[5];
    const float* box   = (const float*)d_in[6];
    const float* Woy   = (const float*)d_in[7];
    const float* boy   = (const float*)d_in[8];
    const float* l1xg  = (const float*)d_in[9];
    const float* l1xb  = (const float*)d_in[10];
    const float* l1yg  = (const float*)d_in[11];
    const float* l1yb  = (const float*)d_in[12];
    const float* l2xg  = (const float*)d_in[13];
    const float* l2xb  = (const float*)d_in[14];
    const float* l2yg  = (const float*)d_in[15];
    const float* l2yb  = (const float*)d_in[16];
    const float* fxw1  = (const float*)d_in[17];
    const float* fxb1  = (const float*)d_in[18];
    const float* fxw2  = (const float*)d_in[19];
    const float* fxb2  = (const float*)d_in[20];
    const float* fyw1  = (const float*)d_in[21];
    const float* fyb1  = (const float*)d_in[22];
    const float* fyw2  = (const float*)d_in[23];
    const float* fyb2  = (const float*)d_in[24];

    float* X = (float*)d_out;
    float* Y = X + (size_t)NTOK*DD;

    unsigned* xn = symaddr(g_xn); unsigned* yn = symaddr(g_yn);
    unsigned* o1 = symaddr(g_o1); unsigned* o2 = symaddr(g_o2);
    unsigned* qx = symaddr(g_qx); unsigned* kx = symaddr(g_kx); unsigned* vx = symaddr(g_vx);
    unsigned* qy = symaddr(g_qy); unsigned* ky = symaddr(g_ky); unsigned* vy = symaddr(g_vy);
    unsigned* hx = symaddr(g_hx); unsigned* hy = symaddr(g_hy);
    unsigned* cwq = symaddr(g_cwq); unsigned* cwk = symaddr(g_cwk);
    unsigned* cwv = symaddr(g_cwv); unsigned* cwox = symaddr(g_cwox);
    unsigned* cwoy = symaddr(g_cwoy);
    unsigned* cfx1 = symaddr(g_cfx1); unsigned* cfy1 = symaddr(g_cfy1);
    unsigned* cfx2 = symaddr(g_cfx2); unsigned* cfy2 = symaddr(g_cfy2);

    size_t bytes = (size_t)NTOK*DD*sizeof(float);
    cudaMemcpyAsync(X, x_in, bytes, cudaMemcpyDeviceToDevice);
    cudaMemcpyAsync(Y, y_in, bytes, cudaMemcpyDeviceToDevice);

    {
        CvtBatch cb = {};
        cb.src[0]=Wq;   cb.dst[0]=cwq;  cb.n[0]=2*DD*DD;
        cb.src[1]=Wk;   cb.dst[1]=cwk;  cb.n[1]=2*DD*DD;
        cb.src[2]=Wv;   cb.dst[2]=cwv;  cb.n[2]=2*DD*DD;
        cb.src[3]=Wox;  cb.dst[3]=cwox; cb.n[3]=2*DD*DD;
        cb.src[4]=Woy;  cb.dst[4]=cwoy; cb.n[4]=2*DD*DD;
        cb.src[5]=fxw1; cb.dst[5]=cfx1; cb.n[5]=2*DD*FF;
        cb.src[6]=fyw1; cb.dst[6]=cfy1; cb.n[6]=2*DD*FF;
        cb.src[7]=fxw2; cb.dst[7]=cfx2; cb.n[7]=2*FF*DD;
        cb.src[8]=fyw2; cb.dst[8]=cfy2; cb.n[8]=2*FF*DD;
        dim3 grid(64, 9);
        cvt_kernel<<<grid, 256>>>(cb);
    }

    dim3 attnG(BT*HH, TT/128);

    for (int l = 0; l < 2; l++) {
        const unsigned* Wq_l  = cwq  + (size_t)l*DD*DD;
        const unsigned* Wk_l  = cwk  + (size_t)l*DD*DD;
        const unsigned* Wv_l  = cwv  + (size_t)l*DD*DD;
        const unsigned* Wox_l = cwox + (size_t)l*DD*DD;
        const unsigned* Woy_l = cwoy + (size_t)l*DD*DD;
        const float* box_l = box + (size_t)l*DD;
        const float* boy_l = boy + (size_t)l*DD;

        ln_kernel<<<2*NTOK, 128>>>(X, Y, xn, yn,
                                   l1xg + l*DD, l1xb + l*DD,
                                   l1yg + l*DD, l1yb + l*DD);

        {
            GemmBatch gb = {};
            gb.A[0]=xn; gb.B[0]=Wq_l; gb.C[0]=qy; gb.em[0]=4;
            gb.A[1]=xn; gb.B[1]=Wk_l; gb.C[1]=kx; gb.em[1]=3;
            gb.A[2]=xn; gb.B[2]=Wv_l; gb.C[2]=vx; gb.em[2]=3;
            gb.A[3]=yn; gb.B[3]=Wq_l; gb.C[3]=qx; gb.em[3]=4;
            gb.A[4]=yn; gb.B[4]=Wk_l; gb.C[4]=ky; gb.em[4]=3;
            gb.A[5]=yn; gb.B[5]=Wv_l; gb.C[5]=vy; gb.em[5]=3;
            dim3 grid(DD/TBN, NTOK/TBM, 6);
            gemm_tc_kernel<<<grid, 128>>>(gb, NTOK, DD, DD);
        }

        attn_kernel<<<attnG, 256>>>();

        {
            GemmBatch gb = {};
            gb.A[0]=o1; gb.B[0]=Wox_l; gb.bias[0]=box_l; gb.res[0]=X; gb.C[0]=X; gb.em[0]=1;
            gb.A[1]=o2; gb.B[1]=Woy_l; gb.bias[1]=boy_l; gb.res[1]=Y; gb.C[1]=Y; gb.em[1]=1;
            dim3 grid(DD/TBN, NTOK/TBM, 2);
            gemm_tc_kernel<<<grid, 128>>>(gb, NTOK, DD, DD);
        }

        ln_kernel<<<2*NTOK, 128>>>(X, Y, xn, yn,
                                   l2xg + l*DD, l2xb + l*DD,
                                   l2yg + l*DD, l2yb + l*DD);

        {
            GemmBatch gb = {};
            gb.A[0]=xn; gb.B[0]=cfx1 + (size_t)l*DD*FF; gb.bias[0]=fxb1 + l*FF; gb.C[0]=hx; gb.em[0]=2;
            gb.A[1]=yn; gb.B[1]=cfy1 + (size_t)l*DD*FF; gb.bias[1]=fyb1 + l*FF; gb.C[1]=hy; gb.em[1]=2;
            dim3 grid(FF/TBN, NTOK/TBM, 2);
            gemm_tc_kernel<<<grid, 128>>>(gb, NTOK, FF, DD);
        }
        {
            GemmBatch gb = {};
            gb.A[0]=hx; gb.B[0]=cfx2 + (size_t)l*FF*DD; gb.bias[0]=fxb2 + l*DD; gb.res[0]=X; gb.C[0]=X; gb.em[0]=1;
            gb.A[1]=hy; gb.B[1]=cfy2 + (size_t)l*FF*DD; gb.bias[1]=fyb2 + l*DD; gb.res[1]=Y; gb.C[1]=Y; gb.em[1]=1;
            dim3 grid(DD/TBN, NTOK/TBM, 2);
            gemm_tc_kernel<<<grid, 128>>>(gb, NTOK, DD, FF);
        }
    }
}

// round 15
// speedup vs baseline: 3.2503x; 1.0327x over previous
#include <cuda_runtime.h>
#include <math.h>

#define BT   8
#define TT   1024
#define DD   128
#define HH   8
#define DHH  16
#define FF   256
#define NTOK (BT*TT)   /* 8192 rows */

// ---------------- scratch (device globals; no allocation allowed) ----------
__device__ unsigned g_xn[NTOK*DD];     // LN out, tf32 bits
__device__ unsigned g_yn[NTOK*DD];
__device__ unsigned g_qx[NTOK*DD];     // tf32 bits (pre-scaled 0.125*log2e)
__device__ unsigned g_kx[NTOK*DD];
__device__ unsigned g_vx[NTOK*DD];
__device__ unsigned g_qy[NTOK*DD];
__device__ unsigned g_ky[NTOK*DD];
__device__ unsigned g_vy[NTOK*DD];
__device__ unsigned g_o1[NTOK*DD];     // attention out, tf32 bits
__device__ unsigned g_o2[NTOK*DD];
__device__ unsigned g_hx[NTOK*FF];     // FFN hidden, tf32 bits
__device__ unsigned g_hy[NTOK*FF];
// converted weights (tf32 bits), both layers
__device__ unsigned g_cwq [2*DD*DD];
__device__ unsigned g_cwk [2*DD*DD];
__device__ unsigned g_cwv [2*DD*DD];
__device__ unsigned g_cwox[2*DD*DD];
__device__ unsigned g_cwoy[2*DD*DD];
__device__ unsigned g_cfx1[2*DD*FF];
__device__ unsigned g_cfy1[2*DD*FF];
__device__ unsigned g_cfx2[2*FF*DD];
__device__ unsigned g_cfy2[2*FF*DD];

// ---------------- helpers ---------------------------------------------------
__device__ __forceinline__ unsigned cvt_tf32(float f) {
    unsigned u;
    asm("cvt.rna.tf32.f32 %0, %1;" : "=r"(u) : "f"(f));
    return u;
}
__device__ __forceinline__ float ex2(float x) {
    float r;
    asm("ex2.approx.f32 %0, %1;" : "=f"(r) : "f"(x));
    return r;
}
__device__ __forceinline__ void mma_tf32(float* c,
    unsigned a0, unsigned a1, unsigned a2, unsigned a3,
    unsigned b0, unsigned b1)
{
    asm("mma.sync.aligned.m16n8k8.row.col.f32.tf32.tf32.f32 "
        "{%0,%1,%2,%3}, {%4,%5,%6,%7}, {%8,%9}, {%0,%1,%2,%3};"
        : "+f"(c[0]), "+f"(c[1]), "+f"(c[2]), "+f"(c[3])
        : "r"(a0), "r"(a1), "r"(a2), "r"(a3), "r"(b0), "r"(b1));
}
__device__ __forceinline__ void cp16(unsigned saddr, const void* g) {
    asm volatile("cp.async.cg.shared.global [%0], [%1], 16;" :: "r"(saddr), "l"(g));
}
#define CP_COMMIT() asm volatile("cp.async.commit_group;")
#define CP_WAIT(N)  asm volatile("cp.async.wait_group %0;" :: "n"(N))

// ---------------- weight pre-conversion ------------------------------------
struct CvtBatch {
    const float* src[9];
    unsigned*    dst[9];
    int          n[9];
};
__global__ void cvt_kernel(CvtBatch cb)
{
    int z = blockIdx.y;
    int n = cb.n[z];
    const float4* s = (const float4*)cb.src[z];
    uint4* d = (uint4*)cb.dst[z];
    int i = blockIdx.x * blockDim.x + threadIdx.x;
    if (i*4 < n) {
        float4 v = s[i];
        d[i] = make_uint4(cvt_tf32(v.x), cvt_tf32(v.y), cvt_tf32(v.z), cvt_tf32(v.w));
    }
}

// ---------------- fused layernorm (both streams, tf32-bit output) ----------
__global__ void ln_kernel(const float* __restrict__ xs, const float* __restrict__ ys,
                          unsigned* __restrict__ xd, unsigned* __restrict__ yd,
                          const float* __restrict__ gx, const float* __restrict__ bx,
                          const float* __restrict__ gy, const float* __restrict__ by)
{
    int row = blockIdx.x;
    bool second = row >= NTOK;
    int r = second ? row - NTOK : row;
    const float* src = second ? ys : xs;
    unsigned*    dst = second ? yd : xd;
    const float* g   = second ? gy : gx;
    const float* b   = second ? by : bx;

    int t = threadIdx.x;
    float v = src[(size_t)r*DD + t];
    float s = v, s2 = v*v;
    #pragma unroll
    for (int o = 16; o; o >>= 1) {
        s  += __shfl_xor_sync(0xffffffffu, s , o);
        s2 += __shfl_xor_sync(0xffffffffu, s2, o);
    }
    __shared__ float ss[4], ss2[4];
    int w = t >> 5;
    if ((t & 31) == 0) { ss[w] = s; ss2[w] = s2; }
    __syncthreads();
    s  = ss[0]+ss[1]+ss[2]+ss[3];
    s2 = ss2[0]+ss2[1]+ss2[2]+ss2[3];
    float mean = s * (1.0f/DD);
    float var  = s2 * (1.0f/DD) - mean*mean;
    float inv  = rsqrtf(var + 1e-5f);
    dst[(size_t)r*DD + t] = cvt_tf32((v - mean) * inv * g[t] + b[t]);
}

// ---------------- batched tf32 GEMM, cp.async double-buffered --------------
#define TBM 64
#define TBN 64
#define TBK 32
#define APAD 36
#define BPAD 72

struct GemmBatch {
    const unsigned* A[6];
    const unsigned* B[6];
    const float*    bias[6];
    const float*    res[6];
    void*           C[6];
    int             em[6];
};

__global__ void __launch_bounds__(128)
gemm_tc_kernel(GemmBatch g, int M, int N, int K)
{
    const int z = blockIdx.z;
    const unsigned* __restrict__ A    = g.A[z];
    const unsigned* __restrict__ B    = g.B[z];
    const float*    __restrict__ bias = g.bias[z];
    const float*    __restrict__ res  = g.res[z];
    const int mode = g.em[z];

    __shared__ unsigned As[2][TBM][APAD];
    __shared__ unsigned Bs[2][TBK][BPAD];

    int bn = blockIdx.x * TBN;
    int bm = blockIdx.y * TBM;
    int tid  = threadIdx.x;
    int w    = tid >> 5;
    int lane = tid & 31;
    int gq   = lane >> 2;
    int qq   = lane & 3;
    int wm   = (w & 1) * 32;
    int wn   = (w >> 1) * 32;

    unsigned sA[4], sB[4];
    int ar[4], ac[4], br_[4], bc[4];
    #pragma unroll
    for (int it = 0; it < 4; it++) {
        int e = tid + it*128;
        ar[it] = e >> 3;  ac[it] = (e & 7) * 4;
        br_[it] = e >> 4; bc[it] = (e & 15) * 4;
        sA[it] = (unsigned)__cvta_generic_to_shared(&As[0][ar[it]][ac[it]]);
        sB[it] = (unsigned)__cvta_generic_to_shared(&Bs[0][br_[it]][bc[it]]);
    }
    const unsigned bufA = sizeof(unsigned)*TBM*APAD;
    const unsigned bufB = sizeof(unsigned)*TBK*BPAD;

    float c[2][4][4];
    #pragma unroll
    for (int mi = 0; mi < 2; mi++)
        #pragma unroll
        for (int ni = 0; ni < 4; ni++)
            #pragma unroll
            for (int r = 0; r < 4; r++) c[mi][ni][r] = 0.f;

    int nk = K / TBK;
    #pragma unroll
    for (int it = 0; it < 4; it++) {
        cp16(sA[it], &A[(size_t)(bm + ar[it])*K + ac[it]]);
        cp16(sB[it], &B[(size_t)br_[it]*N + bn + bc[it]]);
    }
    CP_COMMIT();

    for (int kt = 0; kt < nk; kt++) {
        int buf = kt & 1;
        if (kt + 1 < nk) {
            int k0 = (kt + 1) * TBK;
            unsigned off = (buf ^ 1) ? bufA : 0u;
            unsigned offB = (buf ^ 1) ? bufB : 0u;
            #pragma unroll
            for (int it = 0; it < 4; it++) {
                cp16(sA[it] + off,  &A[(size_t)(bm + ar[it])*K + k0 + ac[it]]);
                cp16(sB[it] + offB, &B[(size_t)(k0 + br_[it])*N + bn + bc[it]]);
            }
            CP_COMMIT();
            CP_WAIT(1);
        } else {
            CP_WAIT(0);
        }
        __syncthreads();

        #pragma unroll
        for (int kc = 0; kc < TBK/8; kc++) {
            unsigned a[2][4], bf[4][2];
            #pragma unroll
            for (int mi = 0; mi < 2; mi++) {
                int m0 = wm + mi*16;
                a[mi][0] = As[buf][m0 + gq    ][kc*8 + qq];
                a[mi][1] = As[buf][m0 + gq + 8][kc*8 + qq];
                a[mi][2] = As[buf][m0 + gq    ][kc*8 + qq + 4];
                a[mi][3] = As[buf][m0 + gq + 8][kc*8 + qq + 4];
            }
            #pragma unroll
            for (int ni = 0; ni < 4; ni++) {
                bf[ni][0] = Bs[buf][kc*8 + qq    ][wn + ni*8 + gq];
                bf[ni][1] = Bs[buf][kc*8 + qq + 4][wn + ni*8 + gq];
            }
            #pragma unroll
            for (int mi = 0; mi < 2; mi++)
                #pragma unroll
                for (int ni = 0; ni < 4; ni++)
                    mma_tf32(c[mi][ni], a[mi][0], a[mi][1], a[mi][2], a[mi][3],
                             bf[ni][0], bf[ni][1]);
        }
        __syncthreads();
    }

    #pragma unroll
    for (int mi = 0; mi < 2; mi++) {
        int r0 = bm + wm + mi*16 + gq;
        int r1 = r0 + 8;
        #pragma unroll
        for (int ni = 0; ni < 4; ni++) {
            int n0 = bn + wn + ni*8 + 2*qq;
            float v0 = c[mi][ni][0], v1 = c[mi][ni][1];
            float v2 = c[mi][ni][2], v3 = c[mi][ni][3];
            if (mode == 1) {
                float b0 = bias[n0], b1 = bias[n0+1];
                float* Cf = (float*)g.C[z];
                v0 += b0 + res[(size_t)r0*N + n0];
                v1 += b1 + res[(size_t)r0*N + n0+1];
                v2 += b0 + res[(size_t)r1*N + n0];
                v3 += b1 + res[(size_t)r1*N + n0+1];
                *(float2*)&Cf[(size_t)r0*N + n0] = make_float2(v0, v1);
                *(float2*)&Cf[(size_t)r1*N + n0] = make_float2(v2, v3);
            } else if (mode == 2) {
                float b0 = bias[n0], b1 = bias[n0+1];
                v0 += b0; v1 += b1; v2 += b0; v3 += b1;
                v0 = 0.5f * v0 * (1.0f + erff(v0 * 0.70710678118654752f));
                v1 = 0.5f * v1 * (1.0f + erff(v1 * 0.70710678118654752f));
                v2 = 0.5f * v2 * (1.0f + erff(v2 * 0.70710678118654752f));
                v3 = 0.5f * v3 * (1.0f + erff(v3 * 0.70710678118654752f));
                unsigned* Cu = (unsigned*)g.C[z];
                *(uint2*)&Cu[(size_t)r0*N + n0] = make_uint2(cvt_tf32(v0), cvt_tf32(v1));
                *(uint2*)&Cu[(size_t)r1*N + n0] = make_uint2(cvt_tf32(v2), cvt_tf32(v3));
            } else {
                // mode 3: tf32 bits ; mode 4: tf32 bits * (0.125*log2e) for Q
                float sc = (mode == 4) ? 0.18033688011112042f : 1.0f;
                unsigned* Cu = (unsigned*)g.C[z];
                *(uint2*)&Cu[(size_t)r0*N + n0] = make_uint2(cvt_tf32(v0*sc), cvt_tf32(v1*sc));
                *(uint2*)&Cu[(size_t)r1*N + n0] = make_uint2(cvt_tf32(v2*sc), cvt_tf32(v3*sc));
            }
        }
    }
}

// ---------------- tensor-core dual-branch flash attention (tf32) -----------
// Shuffle-free P re-layout: PV k-slot k <-> S-column phi(k), phi(qq)=2qq,
// phi(qq+4)=2qq+1  =>  A-frag = (c0, c2, c1, c3) of the S C-frag.
// V pairs packed as ADJACENT rows: Vq[j*4+q][d] = (V[8j+2q][d], V[8j+2q+1][d]).
// exp via raw ex2 (log2e folded into Q pre-scale).
#define KPK 36
#define VPK 72
__global__ void __launch_bounds__(256)
attn_kernel()
{
    __shared__ unsigned Ks[64][KPK];
    __shared__ unsigned Vq[32][VPK];

    int bh = blockIdx.x;
    int b  = bh >> 3;
    int h  = bh & 7;
    int tid  = threadIdx.x;
    int w    = tid >> 5;
    int lane = tid & 31;
    int gq   = lane >> 2;
    int qq   = lane & 3;

    int tok0 = b*TT + blockIdx.y*128 + w*16;
    int r0 = tok0 + gq;
    int r1 = r0 + 8;

    // ---- Q fragments (tf32 bits, pre-scaled by 0.125*log2e) ----
    unsigned qa[4][4];
    #pragma unroll
    for (int kc = 0; kc < 4; kc++) {
        const unsigned* src = (kc < 2) ? g_qx : g_qy;
        int d0 = (kc & 1)*8 + qq;
        qa[kc][0] = src[(size_t)r0*DD + h*DHH + d0];
        qa[kc][1] = src[(size_t)r1*DD + h*DHH + d0];
        qa[kc][2] = src[(size_t)r0*DD + h*DHH + d0 + 4];
        qa[kc][3] = src[(size_t)r1*DD + h*DHH + d0 + 4];
    }

    // ---- loader setup ----
    // K: 2 chunks/thread (packed column layout, unchanged)
    const unsigned* kptr[2];
    int krow[2], kcol[2];
    #pragma unroll
    for (int it = 0; it < 2; it++) {
        int c = tid + it*256;
        krow[it] = c >> 3;
        int kc4 = (c & 7) * 4;
        kptr[it] = ((kc4 < 16) ? g_kx : g_ky)
                 + (size_t)(b*TT + krow[it])*DD + h*DHH + (kc4 & 15);
        kcol[it] = (kc4 >> 3)*2 + ((kc4 >> 2) & 1);
    }
    // V: 1 chunk/thread; pair = adjacent rows (8vj+2vqq, +1)
    int rp  = tid >> 3;
    int vc4 = (tid & 7) * 4;
    int vj = rp >> 2, vqq = rp & 3;
    const unsigned* vptr0 = ((vc4 < 16) ? g_vx : g_vy)
                          + (size_t)(b*TT + vj*8 + 2*vqq)*DD + h*DHH + (vc4 & 15);
    const unsigned* vptr1 = vptr0 + DD;

    float o[4][4];
    #pragma unroll
    for (int j = 0; j < 4; j++)
        #pragma unroll
        for (int cc = 0; cc < 4; cc++) o[j][cc] = 0.f;
    float l0 = 0.f, l1 = 0.f;

    // prefetch tile 0 into registers
    uint4 krg[2], vra, vrb;
    krg[0] = *(const uint4*)kptr[0];
    krg[1] = *(const uint4*)kptr[1];
    vra = *(const uint4*)vptr0;
    vrb = *(const uint4*)vptr1;

    for (int kt = 0; kt < TT/64; kt++) {
        __syncthreads();
        #pragma unroll
        for (int it = 0; it < 2; it++) {
            Ks[krow[it]][ 0 + kcol[it]] = krg[it].x;
            Ks[krow[it]][ 8 + kcol[it]] = krg[it].y;
            Ks[krow[it]][16 + kcol[it]] = krg[it].z;
            Ks[krow[it]][24 + kcol[it]] = krg[it].w;
        }
        *(uint4*)&Vq[rp][vc4*2    ] = make_uint4(vra.x, vrb.x, vra.y, vrb.y);
        *(uint4*)&Vq[rp][vc4*2 + 4] = make_uint4(vra.z, vrb.z, vra.w, vrb.w);
        __syncthreads();

        if (kt + 1 < TT/64) {
            size_t off = (size_t)(kt + 1)*64*DD;
            krg[0] = *(const uint4*)(kptr[0] + off);
            krg[1] = *(const uint4*)(kptr[1] + off);
            vra = *(const uint4*)(vptr0 + off);
            vrb = *(const uint4*)(vptr1 + off);
        }

        float rs0 = 0.f, rs1 = 0.f;
        #pragma unroll
        for (int j = 0; j < 8; j++) {
            // ---- S chunk: 16 q x 8 keys ----
            uint4 t0 = *(const uint4*)&Ks[j*8 + gq][qq*8];
            uint4 t1 = *(const uint4*)&Ks[j*8 + gq][qq*8 + 4];
            float sc[4] = {0.f, 0.f, 0.f, 0.f};
            mma_tf32(sc, qa[0][0], qa[0][1], qa[0][2], qa[0][3], t0.x, t0.y);
            mma_tf32(sc, qa[1][0], qa[1][1], qa[1][2], qa[1][3], t0.z, t0.w);
            mma_tf32(sc, qa[2][0], qa[2][1], qa[2][2], qa[2][3], t1.x, t1.y);
            mma_tf32(sc, qa[3][0], qa[3][1], qa[3][2], qa[3][3], t1.z, t1.w);

            float p0 = ex2(sc[0]);
            float p1 = ex2(sc[1]);
            float p2 = ex2(sc[2]);
            float p3 = ex2(sc[3]);
            rs0 += p0 + p1;
            rs1 += p2 + p3;
            // A-frag = (c0, c2, c1, c3): shuffle-free re-layout
            unsigned a0 = cvt_tf32(p0);
            unsigned a1 = cvt_tf32(p2);
            unsigned a2 = cvt_tf32(p1);
            unsigned a3 = cvt_tf32(p3);
            // ---- O += P_j @ V_j (V pairs are adjacent rows) ----
            #pragma unroll
            for (int jv = 0; jv < 4; jv++) {
                uint2 bb = *(const uint2*)&Vq[j*4 + qq][(8*jv + gq)*2];
                mma_tf32(o[jv], a0, a1, a2, a3, bb.x, bb.y);
            }
        }
        rs0 += __shfl_xor_sync(0xffffffffu, rs0, 1);
        rs0 += __shfl_xor_sync(0xffffffffu, rs0, 2);
        rs1 += __shfl_xor_sync(0xffffffffu, rs1, 1);
        rs1 += __shfl_xor_sync(0xffffffffu, rs1, 2);
        l0 += rs0;
        l1 += rs1;
    }

    float inv0 = 1.f / l0;
    float inv1 = 1.f / l1;
    #pragma unroll
    for (int j = 0; j < 4; j++) {
        unsigned* dst = (j < 2) ? g_o1 : g_o2;
        int dbase = h*DHH + (j & 1)*8 + 2*qq;
        *(uint2*)&dst[(size_t)r0*DD + dbase] =
            make_uint2(cvt_tf32(o[j][0]*inv0), cvt_tf32(o[j][1]*inv0));
        *(uint2*)&dst[(size_t)r1*DD + dbase] =
            make_uint2(cvt_tf32(o[j][2]*inv1), cvt_tf32(o[j][3]*inv1));
    }
}

// ---------------- host launcher --------------------------------------------
template <typename T>
static T* symaddr(const T& s) {
    void* p = nullptr;
    cudaGetSymbolAddress(&p, s);
    return (T*)p;
}
template <typename T, size_t N>
static T* symaddr(const T (&s)[N]) {
    void* p = nullptr;
    cudaGetSymbolAddress(&p, s);
    return (T*)p;
}

extern "C" void kernel_launch(void* const* d_in, const int* in_sizes, int n_in,
                              void* d_out, int out_size)
{
    const float* x_in  = (const float*)d_in[0];
    const float* y_in  = (const float*)d_in[1];
    const float* Wq    = (const float*)d_in[2];
    const float* Wk    = (const float*)d_in[3];
    const float* Wv    = (const float*)d_in[4];
    const float* Wox   = (const float*)d_in[5];
    const float* box   = (const float*)d_in[6];
    const float* Woy   = (const float*)d_in[7];
    const float* boy   = (const float*)d_in[8];
    const float* l1xg  = (const float*)d_in[9];
    const float* l1xb  = (const float*)d_in[10];
    const float* l1yg  = (const float*)d_in[11];
    const float* l1yb  = (const float*)d_in[12];
    const float* l2xg  = (const float*)d_in[13];
    const float* l2xb  = (const float*)d_in[14];
    const float* l2yg  = (const float*)d_in[15];
    const float* l2yb  = (const float*)d_in[16];
    const float* fxw1  = (const float*)d_in[17];
    const float* fxb1  = (const float*)d_in[18];
    const float* fxw2  = (const float*)d_in[19];
    const float* fxb2  = (const float*)d_in[20];
    const float* fyw1  = (const float*)d_in[21];
    const float* fyb1  = (const float*)d_in[22];
    const float* fyw2  = (const float*)d_in[23];
    const float* fyb2  = (const float*)d_in[24];

    float* X = (float*)d_out;
    float* Y = X + (size_t)NTOK*DD;

    unsigned* xn = symaddr(g_xn); unsigned* yn = symaddr(g_yn);
    unsigned* o1 = symaddr(g_o1); unsigned* o2 = symaddr(g_o2);
    unsigned* qx = symaddr(g_qx); unsigned* kx = symaddr(g_kx); unsigned* vx = symaddr(g_vx);
    unsigned* qy = symaddr(g_qy); unsigned* ky = symaddr(g_ky); unsigned* vy = symaddr(g_vy);
    unsigned* hx = symaddr(g_hx); unsigned* hy = symaddr(g_hy);
    unsigned* cwq = symaddr(g_cwq); unsigned* cwk = symaddr(g_cwk);
    unsigned* cwv = symaddr(g_cwv); unsigned* cwox = symaddr(g_cwox);
    unsigned* cwoy = symaddr(g_cwoy);
    unsigned* cfx1 = symaddr(g_cfx1); unsigned* cfy1 = symaddr(g_cfy1);
    unsigned* cfx2 = symaddr(g_cfx2); unsigned* cfy2 = symaddr(g_cfy2);

    size_t bytes = (size_t)NTOK*DD*sizeof(float);
    cudaMemcpyAsync(X, x_in, bytes, cudaMemcpyDeviceToDevice);
    cudaMemcpyAsync(Y, y_in, bytes, cudaMemcpyDeviceToDevice);

    {
        CvtBatch cb = {};
        cb.src[0]=Wq;   cb.dst[0]=cwq;  cb.n[0]=2*DD*DD;
        cb.src[1]=Wk;   cb.dst[1]=cwk;  cb.n[1]=2*DD*DD;
        cb.src[2]=Wv;   cb.dst[2]=cwv;  cb.n[2]=2*DD*DD;
        cb.src[3]=Wox;  cb.dst[3]=cwox; cb.n[3]=2*DD*DD;
        cb.src[4]=Woy;  cb.dst[4]=cwoy; cb.n[4]=2*DD*DD;
        cb.src[5]=fxw1; cb.dst[5]=cfx1; cb.n[5]=2*DD*FF;
        cb.src[6]=fyw1; cb.dst[6]=cfy1; cb.n[6]=2*DD*FF;
        cb.src[7]=fxw2; cb.dst[7]=cfx2; cb.n[7]=2*FF*DD;
        cb.src[8]=fyw2; cb.dst[8]=cfy2; cb.n[8]=2*FF*DD;
        dim3 grid(64, 9);
        cvt_kernel<<<grid, 256>>>(cb);
    }

    dim3 attnG(BT*HH, TT/128);

    for (int l = 0; l < 2; l++) {
        const unsigned* Wq_l  = cwq  + (size_t)l*DD*DD;
        const unsigned* Wk_l  = cwk  + (size_t)l*DD*DD;
        const unsigned* Wv_l  = cwv  + (size_t)l*DD*DD;
        const unsigned* Wox_l = cwox + (size_t)l*DD*DD;
        const unsigned* Woy_l = cwoy + (size_t)l*DD*DD;
        const float* box_l = box + (size_t)l*DD;
        const float* boy_l = boy + (size_t)l*DD;

        ln_kernel<<<2*NTOK, 128>>>(X, Y, xn, yn,
                                   l1xg + l*DD, l1xb + l*DD,
                                   l1yg + l*DD, l1yb + l*DD);

        {
            GemmBatch gb = {};
            gb.A[0]=xn; gb.B[0]=Wq_l; gb.C[0]=qy; gb.em[0]=4;
            gb.A[1]=xn; gb.B[1]=Wk_l; gb.C[1]=kx; gb.em[1]=3;
            gb.A[2]=xn; gb.B[2]=Wv_l; gb.C[2]=vx; gb.em[2]=3;
            gb.A[3]=yn; gb.B[3]=Wq_l; gb.C[3]=qx; gb.em[3]=4;
            gb.A[4]=yn; gb.B[4]=Wk_l; gb.C[4]=ky; gb.em[4]=3;
            gb.A[5]=yn; gb.B[5]=Wv_l; gb.C[5]=vy; gb.em[5]=3;
            dim3 grid(DD/TBN, NTOK/TBM, 6);
            gemm_tc_kernel<<<grid, 128>>>(gb, NTOK, DD, DD);
        }

        attn_kernel<<<attnG, 256>>>();

        {
            GemmBatch gb = {};
            gb.A[0]=o1; gb.B[0]=Wox_l; gb.bias[0]=box_l; gb.res[0]=X; gb.C[0]=X; gb.em[0]=1;
            gb.A[1]=o2; gb.B[1]=Woy_l; gb.bias[1]=boy_l; gb.res[1]=Y; gb.C[1]=Y; gb.em[1]=1;
            dim3 grid(DD/TBN, NTOK/TBM, 2);
            gemm_tc_kernel<<<grid, 128>>>(gb, NTOK, DD, DD);
        }

        ln_kernel<<<2*NTOK, 128>>>(X, Y, xn, yn,
                                   l2xg + l*DD, l2xb + l*DD,
                                   l2yg + l*DD, l2yb + l*DD);

        {
            GemmBatch gb = {};
            gb.A[0]=xn; gb.B[0]=cfx1 + (size_t)l*DD*FF; gb.bias[0]=fxb1 + l*FF; gb.C[0]=hx; gb.em[0]=2;
            gb.A[1]=yn; gb.B[1]=cfy1 + (size_t)l*DD*FF; gb.bias[1]=fyb1 + l*FF; gb.C[1]=hy; gb.em[1]=2;
            dim3 grid(FF/TBN, NTOK/TBM, 2);
            gemm_tc_kernel<<<grid, 128>>>(gb, NTOK, FF, DD);
        }
        {
            GemmBatch gb = {};
            gb.A[0]=hx; gb.B[0]=cfx2 + (size_t)l*FF*DD; gb.bias[0]=fxb2 + l*DD; gb.res[0]=X; gb.C[0]=X; gb.em[0]=1;
            gb.A[1]=hy; gb.B[1]=cfy2 + (size_t)l*FF*DD; gb.bias[1]=fyb2 + l*DD; gb.res[1]=Y; gb.C[1]=Y; gb.em[1]=1;
            dim3 grid(DD/TBN, NTOK/TBM, 2);
            gemm_tc_kernel<<<grid, 128>>>(gb, NTOK, DD, FF);
        }
    }
}

// round 17
// speedup vs baseline: 3.4577x; 1.0638x over previous
#include <cuda_runtime.h>
#include <math.h>

#define BT   8
#define TT   1024
#define DD   128
#define HH   8
#define DHH  16
#define FF   256
#define NTOK (BT*TT)   /* 8192 rows */

// ---------------- scratch (device globals; no allocation allowed) ----------
__device__ unsigned g_xn[NTOK*DD];     // LN out, tf32 bits
__device__ unsigned g_yn[NTOK*DD];
__device__ unsigned g_qx[NTOK*DD];     // tf32 bits (pre-scaled 0.125*log2e)
__device__ unsigned g_kx[NTOK*DD];
__device__ unsigned g_vx[NTOK*DD];
__device__ unsigned g_qy[NTOK*DD];
__device__ unsigned g_ky[NTOK*DD];
__device__ unsigned g_vy[NTOK*DD];
__device__ unsigned g_o1[NTOK*DD];     // attention out, tf32 bits
__device__ unsigned g_o2[NTOK*DD];
__device__ unsigned g_hx[NTOK*FF];     // FFN hidden, tf32 bits
__device__ unsigned g_hy[NTOK*FF];
// converted weights (tf32 bits), both layers
__device__ unsigned g_cwq [2*DD*DD];
__device__ unsigned g_cwk [2*DD*DD];
__device__ unsigned g_cwv [2*DD*DD];
__device__ unsigned g_cwox[2*DD*DD];
__device__ unsigned g_cwoy[2*DD*DD];
__device__ unsigned g_cfx1[2*DD*FF];
__device__ unsigned g_cfy1[2*DD*FF];
__device__ unsigned g_cfx2[2*FF*DD];
__device__ unsigned g_cfy2[2*FF*DD];

// ---------------- helpers ---------------------------------------------------
__device__ __forceinline__ unsigned cvt_tf32(float f) {
    unsigned u;
    asm("cvt.rna.tf32.f32 %0, %1;" : "=r"(u) : "f"(f));
    return u;
}
__device__ __forceinline__ float ex2(float x) {
    float r;
    asm("ex2.approx.f32 %0, %1;" : "=f"(r) : "f"(x));
    return r;
}
__device__ __forceinline__ void mma_tf32(float* c,
    unsigned a0, unsigned a1, unsigned a2, unsigned a3,
    unsigned b0, unsigned b1)
{
    asm("mma.sync.aligned.m16n8k8.row.col.f32.tf32.tf32.f32 "
        "{%0,%1,%2,%3}, {%4,%5,%6,%7}, {%8,%9}, {%0,%1,%2,%3};"
        : "+f"(c[0]), "+f"(c[1]), "+f"(c[2]), "+f"(c[3])
        : "r"(a0), "r"(a1), "r"(a2), "r"(a3), "r"(b0), "r"(b1));
}
__device__ __forceinline__ void cp16(unsigned saddr, const void* g) {
    asm volatile("cp.async.cg.shared.global [%0], [%1], 16;" :: "r"(saddr), "l"(g));
}
#define CP_COMMIT() asm volatile("cp.async.commit_group;")
#define CP_WAIT(N)  asm volatile("cp.async.wait_group %0;" :: "n"(N))

// ---------------- weight pre-conversion ------------------------------------
struct CvtBatch {
    const float* src[9];
    unsigned*    dst[9];
    int          n[9];
};
__global__ void cvt_kernel(CvtBatch cb)
{
    int z = blockIdx.y;
    int n = cb.n[z];
    const float4* s = (const float4*)cb.src[z];
    uint4* d = (uint4*)cb.dst[z];
    int i = blockIdx.x * blockDim.x + threadIdx.x;
    if (i*4 < n) {
        float4 v = s[i];
        d[i] = make_uint4(cvt_tf32(v.x), cvt_tf32(v.y), cvt_tf32(v.z), cvt_tf32(v.w));
    }
}

// ---------------- fused layernorm (both streams, tf32-bit output) ----------
__global__ void ln_kernel(const float* __restrict__ xs, const float* __restrict__ ys,
                          unsigned* __restrict__ xd, unsigned* __restrict__ yd,
                          const float* __restrict__ gx, const float* __restrict__ bx,
                          const float* __restrict__ gy, const float* __restrict__ by)
{
    int row = blockIdx.x;
    bool second = row >= NTOK;
    int r = second ? row - NTOK : row;
    const float* src = second ? ys : xs;
    unsigned*    dst = second ? yd : xd;
    const float* g   = second ? gy : gx;
    const float* b   = second ? by : bx;

    int t = threadIdx.x;
    float v = src[(size_t)r*DD + t];
    float s = v, s2 = v*v;
    #pragma unroll
    for (int o = 16; o; o >>= 1) {
        s  += __shfl_xor_sync(0xffffffffu, s , o);
        s2 += __shfl_xor_sync(0xffffffffu, s2, o);
    }
    __shared__ float ss[4], ss2[4];
    int w = t >> 5;
    if ((t & 31) == 0) { ss[w] = s; ss2[w] = s2; }
    __syncthreads();
    s  = ss[0]+ss[1]+ss[2]+ss[3];
    s2 = ss2[0]+ss2[1]+ss2[2]+ss2[3];
    float mean = s * (1.0f/DD);
    float var  = s2 * (1.0f/DD) - mean*mean;
    float inv  = rsqrtf(var + 1e-5f);
    dst[(size_t)r*DD + t] = cvt_tf32((v - mean) * inv * g[t] + b[t]);
}

// ---------------- batched tf32 GEMM, cp.async double-buffered --------------
#define TBM 64
#define TBN 64
#define TBK 32
#define APAD 36
#define BPAD 72

struct GemmBatch {
    const unsigned* A[6];
    const unsigned* B[6];
    const float*    bias[6];
    const float*    res[6];
    void*           C[6];
    int             em[6];
};

__global__ void __launch_bounds__(128)
gemm_tc_kernel(GemmBatch g, int M, int N, int K)
{
    const int z = blockIdx.z;
    const unsigned* __restrict__ A    = g.A[z];
    const unsigned* __restrict__ B    = g.B[z];
    const float*    __restrict__ bias = g.bias[z];
    const float*    __restrict__ res  = g.res[z];
    const int mode = g.em[z];

    __shared__ unsigned As[2][TBM][APAD];
    __shared__ unsigned Bs[2][TBK][BPAD];

    int bn = blockIdx.x * TBN;
    int bm = blockIdx.y * TBM;
    int tid  = threadIdx.x;
    int w    = tid >> 5;
    int lane = tid & 31;
    int gq   = lane >> 2;
    int qq   = lane & 3;
    int wm   = (w & 1) * 32;
    int wn   = (w >> 1) * 32;

    unsigned sA[4], sB[4];
    int ar[4], ac[4], br_[4], bc[4];
    #pragma unroll
    for (int it = 0; it < 4; it++) {
        int e = tid + it*128;
        ar[it] = e >> 3;  ac[it] = (e & 7) * 4;
        br_[it] = e >> 4; bc[it] = (e & 15) * 4;
        sA[it] = (unsigned)__cvta_generic_to_shared(&As[0][ar[it]][ac[it]]);
        sB[it] = (unsigned)__cvta_generic_to_shared(&Bs[0][br_[it]][bc[it]]);
    }
    const unsigned bufA = sizeof(unsigned)*TBM*APAD;
    const unsigned bufB = sizeof(unsigned)*TBK*BPAD;

    float c[2][4][4];
    #pragma unroll
    for (int mi = 0; mi < 2; mi++)
        #pragma unroll
        for (int ni = 0; ni < 4; ni++)
            #pragma unroll
            for (int r = 0; r < 4; r++) c[mi][ni][r] = 0.f;

    int nk = K / TBK;
    #pragma unroll
    for (int it = 0; it < 4; it++) {
        cp16(sA[it], &A[(size_t)(bm + ar[it])*K + ac[it]]);
        cp16(sB[it], &B[(size_t)br_[it]*N + bn + bc[it]]);
    }
    CP_COMMIT();

    for (int kt = 0; kt < nk; kt++) {
        int buf = kt & 1;
        if (kt + 1 < nk) {
            int k0 = (kt + 1) * TBK;
            unsigned off = (buf ^ 1) ? bufA : 0u;
            unsigned offB = (buf ^ 1) ? bufB : 0u;
            #pragma unroll
            for (int it = 0; it < 4; it++) {
                cp16(sA[it] + off,  &A[(size_t)(bm + ar[it])*K + k0 + ac[it]]);
                cp16(sB[it] + offB, &B[(size_t)(k0 + br_[it])*N + bn + bc[it]]);
            }
            CP_COMMIT();
            CP_WAIT(1);
        } else {
            CP_WAIT(0);
        }
        __syncthreads();

        #pragma unroll
        for (int kc = 0; kc < TBK/8; kc++) {
            unsigned a[2][4], bf[4][2];
            #pragma unroll
            for (int mi = 0; mi < 2; mi++) {
                int m0 = wm + mi*16;
                a[mi][0] = As[buf][m0 + gq    ][kc*8 + qq];
                a[mi][1] = As[buf][m0 + gq + 8][kc*8 + qq];
                a[mi][2] = As[buf][m0 + gq    ][kc*8 + qq + 4];
                a[mi][3] = As[buf][m0 + gq + 8][kc*8 + qq + 4];
            }
            #pragma unroll
            for (int ni = 0; ni < 4; ni++) {
                bf[ni][0] = Bs[buf][kc*8 + qq    ][wn + ni*8 + gq];
                bf[ni][1] = Bs[buf][kc*8 + qq + 4][wn + ni*8 + gq];
            }
            #pragma unroll
            for (int mi = 0; mi < 2; mi++)
                #pragma unroll
                for (int ni = 0; ni < 4; ni++)
                    mma_tf32(c[mi][ni], a[mi][0], a[mi][1], a[mi][2], a[mi][3],
                             bf[ni][0], bf[ni][1]);
        }
        __syncthreads();
    }

    #pragma unroll
    for (int mi = 0; mi < 2; mi++) {
        int r0 = bm + wm + mi*16 + gq;
        int r1 = r0 + 8;
        #pragma unroll
        for (int ni = 0; ni < 4; ni++) {
            int n0 = bn + wn + ni*8 + 2*qq;
            float v0 = c[mi][ni][0], v1 = c[mi][ni][1];
            float v2 = c[mi][ni][2], v3 = c[mi][ni][3];
            if (mode == 1) {
                float b0 = bias[n0], b1 = bias[n0+1];
                float* Cf = (float*)g.C[z];
                v0 += b0 + res[(size_t)r0*N + n0];
                v1 += b1 + res[(size_t)r0*N + n0+1];
                v2 += b0 + res[(size_t)r1*N + n0];
                v3 += b1 + res[(size_t)r1*N + n0+1];
                *(float2*)&Cf[(size_t)r0*N + n0] = make_float2(v0, v1);
                *(float2*)&Cf[(size_t)r1*N + n0] = make_float2(v2, v3);
            } else if (mode == 2) {
                float b0 = bias[n0], b1 = bias[n0+1];
                v0 += b0; v1 += b1; v2 += b0; v3 += b1;
                v0 = 0.5f * v0 * (1.0f + erff(v0 * 0.70710678118654752f));
                v1 = 0.5f * v1 * (1.0f + erff(v1 * 0.70710678118654752f));
                v2 = 0.5f * v2 * (1.0f + erff(v2 * 0.70710678118654752f));
                v3 = 0.5f * v3 * (1.0f + erff(v3 * 0.70710678118654752f));
                unsigned* Cu = (unsigned*)g.C[z];
                *(uint2*)&Cu[(size_t)r0*N + n0] = make_uint2(cvt_tf32(v0), cvt_tf32(v1));
                *(uint2*)&Cu[(size_t)r1*N + n0] = make_uint2(cvt_tf32(v2), cvt_tf32(v3));
            } else {
                float sc = (mode == 4) ? 0.18033688011112042f : 1.0f;
                unsigned* Cu = (unsigned*)g.C[z];
                *(uint2*)&Cu[(size_t)r0*N + n0] = make_uint2(cvt_tf32(v0*sc), cvt_tf32(v1*sc));
                *(uint2*)&Cu[(size_t)r1*N + n0] = make_uint2(cvt_tf32(v2*sc), cvt_tf32(v3*sc));
            }
        }
    }
}

// ---------------- tensor-core dual-branch flash attention (tf32) -----------
// Shuffle-free P re-layout (A-frag = (c0,c2,c1,c3)); V pairs adjacent rows.
// Double-buffered smem (ONE sync per tile); S split into 2 MMA chains;
// row-sum reduce hoisted out of the loop.
#define KPK 36
#define VPK 72
__global__ void __launch_bounds__(256)
attn_kernel()
{
    __shared__ unsigned Ks[2][64][KPK];
    __shared__ unsigned Vq[2][32][VPK];

    int bh = blockIdx.x;
    int b  = bh >> 3;
    int h  = bh & 7;
    int tid  = threadIdx.x;
    int w    = tid >> 5;
    int lane = tid & 31;
    int gq   = lane >> 2;
    int qq   = lane & 3;

    int tok0 = b*TT + blockIdx.y*128 + w*16;
    int r0 = tok0 + gq;
    int r1 = r0 + 8;

    // ---- Q fragments (tf32 bits, pre-scaled by 0.125*log2e) ----
    unsigned qa[4][4];
    #pragma unroll
    for (int kc = 0; kc < 4; kc++) {
        const unsigned* src = (kc < 2) ? g_qx : g_qy;
        int d0 = (kc & 1)*8 + qq;
        qa[kc][0] = src[(size_t)r0*DD + h*DHH + d0];
        qa[kc][1] = src[(size_t)r1*DD + h*DHH + d0];
        qa[kc][2] = src[(size_t)r0*DD + h*DHH + d0 + 4];
        qa[kc][3] = src[(size_t)r1*DD + h*DHH + d0 + 4];
    }

    // ---- loader setup ----
    const unsigned* kptr[2];
    int krow[2], kcol[2];
    #pragma unroll
    for (int it = 0; it < 2; it++) {
        int c = tid + it*256;
        krow[it] = c >> 3;
        int kc4 = (c & 7) * 4;
        kptr[it] = ((kc4 < 16) ? g_kx : g_ky)
                 + (size_t)(b*TT + krow[it])*DD + h*DHH + (kc4 & 15);
        kcol[it] = (kc4 >> 3)*2 + ((kc4 >> 2) & 1);
    }
    int rp  = tid >> 3;
    int vc4 = (tid & 7) * 4;
    int vj = rp >> 2, vqq = rp & 3;
    const unsigned* vptr0 = ((vc4 < 16) ? g_vx : g_vy)
                          + (size_t)(b*TT + vj*8 + 2*vqq)*DD + h*DHH + (vc4 & 15);
    const unsigned* vptr1 = vptr0 + DD;

    float o[4][4];
    #pragma unroll
    for (int j = 0; j < 4; j++)
        #pragma unroll
        for (int cc = 0; cc < 4; cc++) o[j][cc] = 0.f;
    float l0 = 0.f, l1 = 0.f;   // per-lane partials; reduced once at the end

    // prefetch tile 0 into registers
    uint4 krg[2], vra, vrb;
    krg[0] = *(const uint4*)kptr[0];
    krg[1] = *(const uint4*)kptr[1];
    vra = *(const uint4*)vptr0;
    vrb = *(const uint4*)vptr1;

    for (int kt = 0; kt < TT/64; kt++) {
        int buf = kt & 1;
        // store registers -> packed smem (buf); nobody reads buf now
        #pragma unroll
        for (int it = 0; it < 2; it++) {
            Ks[buf][krow[it]][ 0 + kcol[it]] = krg[it].x;
            Ks[buf][krow[it]][ 8 + kcol[it]] = krg[it].y;
            Ks[buf][krow[it]][16 + kcol[it]] = krg[it].z;
            Ks[buf][krow[it]][24 + kcol[it]] = krg[it].w;
        }
        *(uint4*)&Vq[buf][rp][vc4*2    ] = make_uint4(vra.x, vrb.x, vra.y, vrb.y);
        *(uint4*)&Vq[buf][rp][vc4*2 + 4] = make_uint4(vra.z, vrb.z, vra.w, vrb.w);
        __syncthreads();

        // prefetch next tile into registers
        if (kt + 1 < TT/64) {
            size_t off = (size_t)(kt + 1)*64*DD;
            krg[0] = *(const uint4*)(kptr[0] + off);
            krg[1] = *(const uint4*)(kptr[1] + off);
            vra = *(const uint4*)(vptr0 + off);
            vrb = *(const uint4*)(vptr1 + off);
        }

        #pragma unroll
        for (int j = 0; j < 8; j++) {
            // ---- S chunk: two independent MMA chains ----
            uint4 t0 = *(const uint4*)&Ks[buf][j*8 + gq][qq*8];
            uint4 t1 = *(const uint4*)&Ks[buf][j*8 + gq][qq*8 + 4];
            float sa[4] = {0.f, 0.f, 0.f, 0.f};
            float sb[4] = {0.f, 0.f, 0.f, 0.f};
            mma_tf32(sa, qa[0][0], qa[0][1], qa[0][2], qa[0][3], t0.x, t0.y);
            mma_tf32(sb, qa[2][0], qa[2][1], qa[2][2], qa[2][3], t1.x, t1.y);
            mma_tf32(sa, qa[1][0], qa[1][1], qa[1][2], qa[1][3], t0.z, t0.w);
            mma_tf32(sb, qa[3][0], qa[3][1], qa[3][2], qa[3][3], t1.z, t1.w);

            float p0 = ex2(sa[0] + sb[0]);
            float p1 = ex2(sa[1] + sb[1]);
            float p2 = ex2(sa[2] + sb[2]);
            float p3 = ex2(sa[3] + sb[3]);
            l0 += p0 + p1;
            l1 += p2 + p3;
            // A-frag = (c0, c2, c1, c3): shuffle-free re-layout
            unsigned a0 = cvt_tf32(p0);
            unsigned a1 = cvt_tf32(p2);
            unsigned a2 = cvt_tf32(p1);
            unsigned a3 = cvt_tf32(p3);
            #pragma unroll
            for (int jv = 0; jv < 4; jv++) {
                uint2 bb = *(const uint2*)&Vq[buf][j*4 + qq][(8*jv + gq)*2];
                mma_tf32(o[jv], a0, a1, a2, a3, bb.x, bb.y);
            }
        }
        __syncthreads();
    }

    // single row-sum reduce (over the 4 lanes of each quad)
    l0 += __shfl_xor_sync(0xffffffffu, l0, 1);
    l0 += __shfl_xor_sync(0xffffffffu, l0, 2);
    l1 += __shfl_xor_sync(0xffffffffu, l1, 1);
    l1 += __shfl_xor_sync(0xffffffffu, l1, 2);

    float inv0 = 1.f / l0;
    float inv1 = 1.f / l1;
    #pragma unroll
    for (int j = 0; j < 4; j++) {
        unsigned* dst = (j < 2) ? g_o1 : g_o2;
        int dbase = h*DHH + (j & 1)*8 + 2*qq;
        *(uint2*)&dst[(size_t)r0*DD + dbase] =
            make_uint2(cvt_tf32(o[j][0]*inv0), cvt_tf32(o[j][1]*inv0));
        *(uint2*)&dst[(size_t)r1*DD + dbase] =
            make_uint2(cvt_tf32(o[j][2]*inv1), cvt_tf32(o[j][3]*inv1));
    }
}

// ---------------- host launcher --------------------------------------------
template <typename T>
static T* symaddr(const T& s) {
    void* p = nullptr;
    cudaGetSymbolAddress(&p, s);
    return (T*)p;
}
template <typename T, size_t N>
static T* symaddr(const T (&s)[N]) {
    void* p = nullptr;
    cudaGetSymbolAddress(&p, s);
    return (T*)p;
}

extern "C" void kernel_launch(void* const* d_in, const int* in_sizes, int n_in,
                              void* d_out, int out_size)
{
    const float* x_in  = (const float*)d_in[0];
    const float* y_in  = (const float*)d_in[1];
    const float* Wq    = (const float*)d_in[2];
    const float* Wk    = (const float*)d_in[3];
    const float* Wv    = (const float*)d_in[4];
    const float* Wox   = (const float*)d_in[5];
    const float* box   = (const float*)d_in[6];
    const float* Woy   = (const float*)d_in[7];
    const float* boy   = (const float*)d_in[8];
    const float* l1xg  = (const float*)d_in[9];
    const float* l1xb  = (const float*)d_in[10];
    const float* l1yg  = (const float*)d_in[11];
    const float* l1yb  = (const float*)d_in[12];
    const float* l2xg  = (const float*)d_in[13];
    const float* l2xb  = (const float*)d_in[14];
    const float* l2yg  = (const float*)d_in[15];
    const float* l2yb  = (const float*)d_in[16];
    const float* fxw1  = (const float*)d_in[17];
    const float* fxb1  = (const float*)d_in[18];
    const float* fxw2  = (const float*)d_in[19];
    const float* fxb2  = (const float*)d_in[20];
    const float* fyw1  = (const float*)d_in[21];
    const float* fyb1  = (const float*)d_in[22];
    const float* fyw2  = (const float*)d_in[23];
    const float* fyb2  = (const float*)d_in[24];

    float* X = (float*)d_out;
    float* Y = X + (size_t)NTOK*DD;

    unsigned* xn = symaddr(g_xn); unsigned* yn = symaddr(g_yn);
    unsigned* o1 = symaddr(g_o1); unsigned* o2 = symaddr(g_o2);
    unsigned* qx = symaddr(g_qx); unsigned* kx = symaddr(g_kx); unsigned* vx = symaddr(g_vx);
    unsigned* qy = symaddr(g_qy); unsigned* ky = symaddr(g_ky); unsigned* vy = symaddr(g_vy);
    unsigned* hx = symaddr(g_hx); unsigned* hy = symaddr(g_hy);
    unsigned* cwq = symaddr(g_cwq); unsigned* cwk = symaddr(g_cwk);
    unsigned* cwv = symaddr(g_cwv); unsigned* cwox = symaddr(g_cwox);
    unsigned* cwoy = symaddr(g_cwoy);
    unsigned* cfx1 = symaddr(g_cfx1); unsigned* cfy1 = symaddr(g_cfy1);
    unsigned* cfx2 = symaddr(g_cfx2); unsigned* cfy2 = symaddr(g_cfy2);

    size_t bytes = (size_t)NTOK*DD*sizeof(float);
    cudaMemcpyAsync(X, x_in, bytes, cudaMemcpyDeviceToDevice);
    cudaMemcpyAsync(Y, y_in, bytes, cudaMemcpyDeviceToDevice);

    {
        CvtBatch cb = {};
        cb.src[0]=Wq;   cb.dst[0]=cwq;  cb.n[0]=2*DD*DD;
        cb.src[1]=Wk;   cb.dst[1]=cwk;  cb.n[1]=2*DD*DD;
        cb.src[2]=Wv;   cb.dst[2]=cwv;  cb.n[2]=2*DD*DD;
        cb.src[3]=Wox;  cb.dst[3]=cwox; cb.n[3]=2*DD*DD;
        cb.src[4]=Woy;  cb.dst[4]=cwoy; cb.n[4]=2*DD*DD;
        cb.src[5]=fxw1; cb.dst[5]=cfx1; cb.n[5]=2*DD*FF;
        cb.src[6]=fyw1; cb.dst[6]=cfy1; cb.n[6]=2*DD*FF;
        cb.src[7]=fxw2; cb.dst[7]=cfx2; cb.n[7]=2*FF*DD;
        cb.src[8]=fyw2; cb.dst[8]=cfy2; cb.n[8]=2*FF*DD;
        dim3 grid(64, 9);
        cvt_kernel<<<grid, 256>>>(cb);
    }

    dim3 attnG(BT*HH, TT/128);

    for (int l = 0; l < 2; l++) {
        const unsigned* Wq_l  = cwq  + (size_t)l*DD*DD;
        const unsigned* Wk_l  = cwk  + (size_t)l*DD*DD;
        const unsigned* Wv_l  = cwv  + (size_t)l*DD*DD;
        const unsigned* Wox_l = cwox + (size_t)l*DD*DD;
        const unsigned* Woy_l = cwoy + (size_t)l*DD*DD;
        const float* box_l = box + (size_t)l*DD;
        const float* boy_l = boy + (size_t)l*DD;

        ln_kernel<<<2*NTOK, 128>>>(X, Y, xn, yn,
                                   l1xg + l*DD, l1xb + l*DD,
                                   l1yg + l*DD, l1yb + l*DD);

        {
            GemmBatch gb = {};
            gb.A[0]=xn; gb.B[0]=Wq_l; gb.C[0]=qy; gb.em[0]=4;
            gb.A[1]=xn; gb.B[1]=Wk_l; gb.C[1]=kx; gb.em[1]=3;
            gb.A[2]=xn; gb.B[2]=Wv_l; gb.C[2]=vx; gb.em[2]=3;
            gb.A[3]=yn; gb.B[3]=Wq_l; gb.C[3]=qx; gb.em[3]=4;
            gb.A[4]=yn; gb.B[4]=Wk_l; gb.C[4]=ky; gb.em[4]=3;
            gb.A[5]=yn; gb.B[5]=Wv_l; gb.C[5]=vy; gb.em[5]=3;
            dim3 grid(DD/TBN, NTOK/TBM, 6);
            gemm_tc_kernel<<<grid, 128>>>(gb, NTOK, DD, DD);
        }

        attn_kernel<<<attnG, 256>>>();

        {
            GemmBatch gb = {};
            gb.A[0]=o1; gb.B[0]=Wox_l; gb.bias[0]=box_l; gb.res[0]=X; gb.C[0]=X; gb.em[0]=1;
            gb.A[1]=o2; gb.B[1]=Woy_l; gb.bias[1]=boy_l; gb.res[1]=Y; gb.C[1]=Y; gb.em[1]=1;
            dim3 grid(DD/TBN, NTOK/TBM, 2);
            gemm_tc_kernel<<<grid, 128>>>(gb, NTOK, DD, DD);
        }

        ln_kernel<<<2*NTOK, 128>>>(X, Y, xn, yn,
                                   l2xg + l*DD, l2xb + l*DD,
                                   l2yg + l*DD, l2yb + l*DD);

        {
            GemmBatch gb = {};
            gb.A[0]=xn; gb.B[0]=cfx1 + (size_t)l*DD*FF; gb.bias[0]=fxb1 + l*FF; gb.C[0]=hx; gb.em[0]=2;
            gb.A[1]=yn; gb.B[1]=cfy1 + (size_t)l*DD*FF; gb.bias[1]=fyb1 + l*FF; gb.C[1]=hy; gb.em[1]=2;
            dim3 grid(FF/TBN, NTOK/TBM, 2);
            gemm_tc_kernel<<<grid, 128>>>(gb, NTOK, FF, DD);
        }
        {
            GemmBatch gb = {};
            gb.A[0]=hx; gb.B[0]=cfx2 + (size_t)l*FF*DD; gb.bias[0]=fxb2 + l*DD; gb.res[0]=X; gb.C[0]=X; gb.em[0]=1;
            gb.A[1]=hy; gb.B[1]=cfy2 + (size_t)l*FF*DD; gb.bias[1]=fyb2 + l*DD; gb.res[1]=Y; gb.C[1]=Y; gb.em[1]=1;
            dim3 grid(DD/TBN, NTOK/TBM, 2);
            gemm_tc_kernel<<<grid, 128>>>(gb, NTOK, DD, FF);
        }
    }
}